// round 7
// baseline (speedup 1.0000x reference)
#include <cuda_runtime.h>
#include <cuda_bf16.h>
#include <cstdint>

#define BATCH 4
#define SEQ   1024
#define CH    1024
#define HEADS 16
#define DH    64
#define TOKENS (BATCH * SEQ)
#define BH (BATCH * HEADS)
#define OUT_ELEMS (TOKENS * CH)

#define BISECT_ITERS 12
#define SOLVE_ITERS 3
#define SCALE 0.0625f   // (1/sqrt(64)) * (alpha-1)

// bf16 split scratch
__device__ __nv_bfloat16 g_xhi[TOKENS * CH];
__device__ __nv_bfloat16 g_xlo[TOKENS * CH];
__device__ __nv_bfloat16 g_wthi[4 * CH * CH];
__device__ __nv_bfloat16 g_wtlo[4 * CH * CH];
__device__ __nv_bfloat16 g_qhi[BH * SEQ * DH];
__device__ __nv_bfloat16 g_qlo[BH * SEQ * DH];
__device__ __nv_bfloat16 g_khi[BH * SEQ * DH];
__device__ __nv_bfloat16 g_klo[BH * SEQ * DH];
__device__ __nv_bfloat16 g_vthi[BH * DH * SEQ];   // transposed V: [bh][dh][tok]
__device__ __nv_bfloat16 g_vtlo[BH * DH * SEQ];
__device__ __nv_bfloat16 g_phi[(size_t)BH * SEQ * SEQ];  // attn split
__device__ __nv_bfloat16 g_plo[(size_t)BH * SEQ * SEQ];
__device__ __nv_bfloat16 g_chi[TOKENS * CH];
__device__ __nv_bfloat16 g_clo[TOKENS * CH];

// ===================== PTX helpers =========================================
__device__ __forceinline__ uint32_t smem_u32(const void* p) {
    uint32_t a;
    asm("{ .reg .u64 t; cvta.to.shared.u64 t, %1; cvt.u32.u64 %0, t; }" : "=r"(a) : "l"(p));
    return a;
}
#define CP_ASYNC16(sa, g) \
    asm volatile("cp.async.cg.shared.global [%0], [%1], 16;" :: "r"(sa), "l"(g))
#define CP_COMMIT() asm volatile("cp.async.commit_group;" ::: "memory")
#define CP_WAIT0() asm volatile("cp.async.wait_group 0;" ::: "memory")
#define CP_WAIT1() asm volatile("cp.async.wait_group 1;" ::: "memory")
#define LDSM4(r0, r1, r2, r3, addr) \
    asm volatile("ldmatrix.sync.aligned.m8n8.x4.shared.b16 {%0,%1,%2,%3}, [%4];" \
        : "=r"(r0), "=r"(r1), "=r"(r2), "=r"(r3) : "r"(addr))
#define MMA16816(d, a, b0, b1) \
    asm volatile("mma.sync.aligned.m16n8k16.row.col.f32.bf16.bf16.f32 " \
        "{%0,%1,%2,%3}, {%4,%5,%6,%7}, {%8,%9}, {%0,%1,%2,%3};" \
        : "+f"((d)[0]), "+f"((d)[1]), "+f"((d)[2]), "+f"((d)[3]) \
        : "r"((a)[0]), "r"((a)[1]), "r"((a)[2]), "r"((a)[3]), "r"(b0), "r"(b1))

__device__ __forceinline__ void split1(float v, __nv_bfloat16& h, __nv_bfloat16& l) {
    h = __float2bfloat16_rn(v);
    l = __float2bfloat16_rn(v - __bfloat162float(h));
}
__device__ __forceinline__ float sum8(const float* base, int row) {
    float4 a = ((const float4*)base)[row * 2];
    float4 b = ((const float4*)base)[row * 2 + 1];
    return ((a.x + a.y) + (a.z + a.w)) + ((b.x + b.y) + (b.z + b.w));
}
__device__ __forceinline__ float max8(const float* base, int row) {
    float4 a = ((const float4*)base)[row * 2];
    float4 b = ((const float4*)base)[row * 2 + 1];
    return fmaxf(fmaxf(fmaxf(a.x, a.y), fmaxf(a.z, a.w)),
                 fmaxf(fmaxf(b.x, b.y), fmaxf(b.z, b.w)));
}

// ===================== convert kernels =====================================
__global__ __launch_bounds__(256) void split_convert(
    const float* __restrict__ in, __nv_bfloat16* __restrict__ hi,
    __nv_bfloat16* __restrict__ lo, int n4)
{
    int i = blockIdx.x * 256 + threadIdx.x;
    if (i >= n4) return;
    float4 v = ((const float4*)in)[i];
    union { ushort u[4]; uint2 q; } H, L;
    float a[4] = {v.x, v.y, v.z, v.w};
#pragma unroll
    for (int j = 0; j < 4; j++) {
        __nv_bfloat16 h, l; split1(a[j], h, l);
        H.u[j] = __bfloat16_as_ushort(h);
        L.u[j] = __bfloat16_as_ushort(l);
    }
    ((uint2*)hi)[i] = H.q;
    ((uint2*)lo)[i] = L.q;
}

__global__ __launch_bounds__(256) void wtrans_convert(
    const float* __restrict__ W, __nv_bfloat16* __restrict__ hi,
    __nv_bfloat16* __restrict__ lo)
{
    __shared__ float t[32][33];
    int tx = threadIdx.x, ty = threadIdx.y;
    int bx = blockIdx.x, by = blockIdx.y;
#pragma unroll
    for (int i = 0; i < 4; i++)
        t[ty + i * 8][tx] = W[(size_t)(by * 32 + ty + i * 8) * 1024 + bx * 32 + tx];
    __syncthreads();
#pragma unroll
    for (int i = 0; i < 4; i++) {
        float v = t[tx][ty + i * 8];
        __nv_bfloat16 h, l; split1(v, h, l);
        size_t o = (size_t)(bx * 32 + ty + i * 8) * 1024 + by * 32 + tx;
        hi[o] = h;
        lo[o] = l;
    }
}

// ===================== split-bf16 mma.sync GEMM (projections) ==============
#define GSTAGE 32768
#define GSMEM (3 * GSTAGE)

__global__ __launch_bounds__(256) void gemm_mma(
    const __nv_bfloat16* __restrict__ Ah, const __nv_bfloat16* __restrict__ Al,
    const __nv_bfloat16* __restrict__ Bh, const __nv_bfloat16* __restrict__ Bl,
    const float* __restrict__ bias, float* __restrict__ dstf,
    __nv_bfloat16* __restrict__ dhi, __nv_bfloat16* __restrict__ dlo, int mode)
{
    extern __shared__ char sm[];
    uint32_t sb = smem_u32(sm);
    int tid = threadIdx.x, lane = tid & 31, wid = tid >> 5;
    int wm = wid >> 2, wn = wid & 3;
    int n0 = blockIdx.x * 128, m0 = blockIdx.y * 128;

    const __nv_bfloat16* gsrc[4] = {
        Ah + (size_t)m0 * 1024, Al + (size_t)m0 * 1024,
        Bh + (size_t)n0 * 1024, Bl + (size_t)n0 * 1024 };

    int l_row0 = tid >> 2,         l_c0 = tid & 3;
    int l_row1 = (tid + 256) >> 2, l_c1 = (tid + 256) & 3;

    auto load_stage = [&](int kt, int s) {
        uint32_t sbase = sb + s * GSTAGE;
#pragma unroll
        for (int t = 0; t < 4; t++) {
            const char* g0 = (const char*)(gsrc[t] + (size_t)l_row0 * 1024 + kt * 32) + l_c0 * 16;
            const char* g1 = (const char*)(gsrc[t] + (size_t)l_row1 * 1024 + kt * 32) + l_c1 * 16;
            uint32_t s0 = sbase + t * 8192 + l_row0 * 64 + ((l_c0 ^ (l_row0 & 3)) * 16);
            uint32_t s1 = sbase + t * 8192 + l_row1 * 64 + ((l_c1 ^ (l_row1 & 3)) * 16);
            CP_ASYNC16(s0, g0);
            CP_ASYNC16(s1, g1);
        }
        CP_COMMIT();
    };

    float acc[4][4][4];
#pragma unroll
    for (int a = 0; a < 4; a++)
#pragma unroll
        for (int b = 0; b < 4; b++)
#pragma unroll
            for (int c = 0; c < 4; c++) acc[a][b][c] = 0.0f;

    int arow = (lane & 7) | (((lane >> 3) & 1) << 3);
    int asel = lane >> 4;
    int brow = (lane & 7) | ((lane >> 4) << 3);
    int bsel = (lane >> 3) & 1;

    load_stage(0, 0);
    load_stage(1, 1);

#pragma unroll 1
    for (int t = 0; t < 32; t++) {
        if (t >= 30) { CP_WAIT0(); } else { CP_WAIT1(); }
        __syncthreads();
        if (t + 2 < 32) load_stage(t + 2, (t + 2) % 3);

        uint32_t base = sb + (t % 3) * GSTAGE;
        uint32_t Ahb = base, Alb = base + 8192, Bhb = base + 16384, Blb = base + 24576;

#pragma unroll
        for (int ks = 0; ks < 2; ks++) {
            int akc = ks * 2 + asel;
            int bkc = ks * 2 + bsel;
            uint32_t ah[4][4], al[4][4], bhf[2][4], blf[2][4];
#pragma unroll
            for (int mt = 0; mt < 4; mt++) {
                int row = wm * 64 + mt * 16 + arow;
                uint32_t off = row * 64 + ((akc ^ (row & 3)) * 16);
                LDSM4(ah[mt][0], ah[mt][1], ah[mt][2], ah[mt][3], Ahb + off);
            }
#pragma unroll
            for (int nt = 0; nt < 2; nt++) {
                int row = wn * 32 + nt * 16 + brow;
                uint32_t off = row * 64 + ((bkc ^ (row & 3)) * 16);
                LDSM4(bhf[nt][0], bhf[nt][1], bhf[nt][2], bhf[nt][3], Bhb + off);
            }
#pragma unroll
            for (int mt = 0; mt < 4; mt++)
#pragma unroll
                for (int nt = 0; nt < 2; nt++) {
                    MMA16816(acc[mt][nt * 2 + 0], ah[mt], bhf[nt][0], bhf[nt][1]);
                    MMA16816(acc[mt][nt * 2 + 1], ah[mt], bhf[nt][2], bhf[nt][3]);
                }
#pragma unroll
            for (int nt = 0; nt < 2; nt++) {
                int row = wn * 32 + nt * 16 + brow;
                uint32_t off = row * 64 + ((bkc ^ (row & 3)) * 16);
                LDSM4(blf[nt][0], blf[nt][1], blf[nt][2], blf[nt][3], Blb + off);
            }
#pragma unroll
            for (int mt = 0; mt < 4; mt++)
#pragma unroll
                for (int nt = 0; nt < 2; nt++) {
                    MMA16816(acc[mt][nt * 2 + 0], ah[mt], blf[nt][0], blf[nt][1]);
                    MMA16816(acc[mt][nt * 2 + 1], ah[mt], blf[nt][2], blf[nt][3]);
                }
#pragma unroll
            for (int mt = 0; mt < 4; mt++) {
                int row = wm * 64 + mt * 16 + arow;
                uint32_t off = row * 64 + ((akc ^ (row & 3)) * 16);
                LDSM4(al[mt][0], al[mt][1], al[mt][2], al[mt][3], Alb + off);
            }
#pragma unroll
            for (int mt = 0; mt < 4; mt++)
#pragma unroll
                for (int nt = 0; nt < 2; nt++) {
                    MMA16816(acc[mt][nt * 2 + 0], al[mt], bhf[nt][0], bhf[nt][1]);
                    MMA16816(acc[mt][nt * 2 + 1], al[mt], bhf[nt][2], bhf[nt][3]);
                }
        }
        __syncthreads();
    }

    // epilogue
    int r = lane >> 2, c2 = (lane & 3) * 2;
#pragma unroll
    for (int mt = 0; mt < 4; mt++) {
        int mrow = m0 + wm * 64 + mt * 16 + r;
        int bidx = mrow >> 10, ntok = mrow & 1023;
#pragma unroll
        for (int nt8 = 0; nt8 < 4; nt8++) {
            int col = n0 + wn * 32 + nt8 * 8 + c2;
            float b0 = bias[col], b1 = bias[col + 1];
            float v00 = acc[mt][nt8][0] + b0, v01 = acc[mt][nt8][1] + b1;
            float v10 = acc[mt][nt8][2] + b0, v11 = acc[mt][nt8][3] + b1;
            if (mode == 0) {
                int h = col >> 6, dh = col & 63;
                size_t base = ((size_t)(bidx * HEADS + h) * SEQ + ntok) * DH + dh;
                __nv_bfloat16 h0, l0, h1, l1;
                split1(v00, h0, l0); split1(v01, h1, l1);
                *(__nv_bfloat162*)(dhi + base) = {h0, h1};
                *(__nv_bfloat162*)(dlo + base) = {l0, l1};
                split1(v10, h0, l0); split1(v11, h1, l1);
                *(__nv_bfloat162*)(dhi + base + 8 * DH) = {h0, h1};
                *(__nv_bfloat162*)(dlo + base + 8 * DH) = {l0, l1};
            } else if (mode == 1) {
                int h = col >> 6, dh = col & 63;
                size_t vb = ((size_t)(bidx * HEADS + h) * DH + dh) * SEQ + ntok;
                __nv_bfloat16 hh, ll;
                split1(v00, hh, ll); dhi[vb] = hh; dlo[vb] = ll;
                split1(v01, hh, ll); dhi[vb + SEQ] = hh; dlo[vb + SEQ] = ll;
                split1(v10, hh, ll); dhi[vb + 8] = hh; dlo[vb + 8] = ll;
                split1(v11, hh, ll); dhi[vb + SEQ + 8] = hh; dlo[vb + SEQ + 8] = ll;
            } else {
                float* p = dstf + (size_t)mrow * CH + col;
                *(float2*)p = {v00, v01};
                *(float2*)(p + 8 * CH) = {v10, v11};
            }
        }
    }
}

// ===================== fused HMMA scores + entmax ==========================
// RED: 2 parities x 768 floats (3 arrays of [32 rows][8 wcol] for Phase D)
#define EOFF_QH 0
#define EOFF_QL 4096
#define EOFF_K  8192
#define EOFF_RED 73728
#define ESMEM (73728 + 6144)

__global__ __launch_bounds__(512) void attn_entmax_mma(
    float* __restrict__ attn,
    const __nv_bfloat16* __restrict__ qhi, const __nv_bfloat16* __restrict__ qlo,
    const __nv_bfloat16* __restrict__ khi, const __nv_bfloat16* __restrict__ klo,
    __nv_bfloat16* __restrict__ phi, __nv_bfloat16* __restrict__ plo)
{
    extern __shared__ char sm[];
    uint32_t sb = smem_u32(sm);
    float* RED = (float*)(sm + EOFF_RED);   // [2][768]

    int tid = threadIdx.x, lane = tid & 31, wid = tid >> 5;
    int wrow = wid >> 3, wcol = wid & 7;
    int bh = blockIdx.y;
    int R0 = blockIdx.x * 32;

    {   // Q: 512 chunks, 1/thread (joins group 0 commit below)
        int hl = tid >> 8;
        int row = (tid >> 3) & 31;
        int u = tid & 7;
        const __nv_bfloat16* src = (hl ? qlo : qhi) + ((size_t)bh * SEQ + R0 + row) * DH + u * 8;
        uint32_t d = sb + EOFF_QH + hl * 4096 + row * 128 + ((u ^ (row & 7)) * 16);
        CP_ASYNC16(d, src);
    }
    auto loadK = [&](int c, int s) {
        uint32_t base = sb + EOFF_K + s * 32768;
#pragma unroll
        for (int i = 0; i < 4; i++) {
            int idx = tid + i * 512;
            int hl = idx >> 10;
            int row = (idx >> 3) & 127;
            int u = idx & 7;
            const __nv_bfloat16* src = (hl ? klo : khi) + ((size_t)bh * SEQ + c * 128 + row) * DH + u * 8;
            uint32_t d = base + hl * 16384 + row * 128 + ((u ^ (row & 7)) * 16);
            CP_ASYNC16(d, src);
        }
        CP_COMMIT();
    };
    loadK(0, 0);
    loadK(1, 1);

    float acc[16][4];
#pragma unroll
    for (int t = 0; t < 16; t++)
#pragma unroll
        for (int e = 0; e < 4; e++) acc[t][e] = 0.0f;

    int arow_ = wrow * 16 + ((lane & 7) | (((lane >> 3) & 1) << 3));
    int asel = lane >> 4;
    int brow_ = (lane & 7) | ((lane >> 4) << 3);
    int bsel = (lane >> 3) & 1;

#pragma unroll 1
    for (int c = 0; c < 8; c++) {
        if (c >= 7) { CP_WAIT0(); } else { CP_WAIT1(); }
        __syncthreads();
        if (wcol == c) {
            uint32_t KHb = sb + EOFF_K + (c & 1) * 32768;
            uint32_t KLb = KHb + 16384;
            uint32_t QHb = sb + EOFF_QH, QLb = sb + EOFF_QL;
#pragma unroll
            for (int kc = 0; kc < 4; kc++) {
                uint32_t au = (uint32_t)(kc * 2 + asel);
                uint32_t aoff = arow_ * 128 + ((au ^ (arow_ & 7)) * 16);
                uint32_t ah[4], al[4];
                LDSM4(ah[0], ah[1], ah[2], ah[3], QHb + aoff);
                LDSM4(al[0], al[1], al[2], al[3], QLb + aoff);
#pragma unroll
                for (int nt = 0; nt < 8; nt++) {
                    int krow = nt * 16 + brow_;
                    uint32_t bu = (uint32_t)(kc * 2 + bsel);
                    uint32_t boff = krow * 128 + ((bu ^ (krow & 7)) * 16);
                    uint32_t bh4[4], bl4[4];
                    LDSM4(bh4[0], bh4[1], bh4[2], bh4[3], KHb + boff);
                    LDSM4(bl4[0], bl4[1], bl4[2], bl4[3], KLb + boff);
                    MMA16816(acc[nt * 2 + 0], ah, bh4[0], bh4[1]);
                    MMA16816(acc[nt * 2 + 1], ah, bh4[2], bh4[3]);
                    MMA16816(acc[nt * 2 + 0], ah, bl4[0], bl4[1]);
                    MMA16816(acc[nt * 2 + 1], ah, bl4[2], bl4[3]);
                    MMA16816(acc[nt * 2 + 0], al, bh4[0], bh4[1]);
                    MMA16816(acc[nt * 2 + 1], al, bh4[2], bh4[3]);
                    MMA16816(acc[nt * 2 + 0], al, bl4[0], bl4[1]);
                    MMA16816(acc[nt * 2 + 1], al, bl4[2], bl4[3]);
                }
            }
        }
        __syncthreads();
        if (c + 2 < 8) loadK(c + 2, c & 1);
    }

    // --- entmax in HMMA layout, redundant all-thread reductions ---
    int r0 = wrow * 16 + (lane >> 2);
    int r1 = r0 + 8;
    bool qlead = (lane & 3) == 0;
    int par = 0;

#pragma unroll
    for (int t = 0; t < 16; t++)
#pragma unroll
        for (int e = 0; e < 4; e++) acc[t][e] *= SCALE;

    // Phase A: row max
    float tloA, tloB;
    {
        float mA = -1e30f, mB = -1e30f;
#pragma unroll
        for (int t = 0; t < 16; t++) {
            mA = fmaxf(mA, fmaxf(acc[t][0], acc[t][1]));
            mB = fmaxf(mB, fmaxf(acc[t][2], acc[t][3]));
        }
        mA = fmaxf(mA, __shfl_xor_sync(0xffffffffu, mA, 1));
        mA = fmaxf(mA, __shfl_xor_sync(0xffffffffu, mA, 2));
        mB = fmaxf(mB, __shfl_xor_sync(0xffffffffu, mB, 1));
        mB = fmaxf(mB, __shfl_xor_sync(0xffffffffu, mB, 2));
        float* RP = RED + par * 768;
        if (qlead) { RP[r0 * 8 + wcol] = mA; RP[r1 * 8 + wcol] = mB; }
        __syncthreads();
        tloA = max8(RP, r0) - 1.0f;
        tloB = max8(RP, r1) - 1.0f;
        par ^= 1;
    }

    // Phase B: f_lo
    float flA, flB;
    {
        float c0 = 0.f, c1 = 0.f, c2 = 0.f, c3 = 0.f;
#pragma unroll
        for (int t = 0; t < 16; t++) {
            float u;
            u = fmaxf(acc[t][0] - tloA, 0.f); c0 = fmaf(u, u, c0);
            u = fmaxf(acc[t][1] - tloA, 0.f); c1 = fmaf(u, u, c1);
            u = fmaxf(acc[t][2] - tloB, 0.f); c2 = fmaf(u, u, c2);
            u = fmaxf(acc[t][3] - tloB, 0.f); c3 = fmaf(u, u, c3);
        }
        float vA = c0 + c1, vB = c2 + c3;
        vA += __shfl_xor_sync(0xffffffffu, vA, 1);
        vA += __shfl_xor_sync(0xffffffffu, vA, 2);
        vB += __shfl_xor_sync(0xffffffffu, vB, 1);
        vB += __shfl_xor_sync(0xffffffffu, vB, 2);
        float* RP = RED + par * 768;
        if (qlead) { RP[r0 * 8 + wcol] = vA; RP[r1 * 8 + wcol] = vB; }
        __syncthreads();
        flA = sum8(RP, r0) - 1.0f;
        flB = sum8(RP, r1) - 1.0f;
        par ^= 1;
    }

    float dm = 0.484375f;          // (1 - (1/1024)^0.5) / 2
    float tmA = tloA + dm, tmB = tloB + dm;

    // Phase C: bisection (1 barrier/iter, double-buffered partials)
#pragma unroll 1
    for (int it = 0; it < BISECT_ITERS; it++) {
        float c0 = 0.f, c1 = 0.f, c2 = 0.f, c3 = 0.f;
#pragma unroll
        for (int t = 0; t < 16; t++) {
            float u;
            u = fmaxf(acc[t][0] - tmA, 0.f); c0 = fmaf(u, u, c0);
            u = fmaxf(acc[t][1] - tmA, 0.f); c1 = fmaf(u, u, c1);
            u = fmaxf(acc[t][2] - tmB, 0.f); c2 = fmaf(u, u, c2);
            u = fmaxf(acc[t][3] - tmB, 0.f); c3 = fmaf(u, u, c3);
        }
        float vA = c0 + c1, vB = c2 + c3;
        vA += __shfl_xor_sync(0xffffffffu, vA, 1);
        vA += __shfl_xor_sync(0xffffffffu, vA, 2);
        vB += __shfl_xor_sync(0xffffffffu, vB, 1);
        vB += __shfl_xor_sync(0xffffffffu, vB, 2);
        float* RP = RED + par * 768;
        if (qlead) { RP[r0 * 8 + wcol] = vA; RP[r1 * 8 + wcol] = vB; }
        __syncthreads();
        float fmA = sum8(RP, r0) - 1.0f;
        float fmB = sum8(RP, r1) - 1.0f;
        if (fmA * flA >= 0.f) tloA = tmA;
        if (fmB * flB >= 0.f) tloB = tmB;
        if (it < BISECT_ITERS - 1) {
            dm *= 0.5f;
            tmA = tloA + dm;
            tmB = tloB + dm;
        }
        par ^= 1;
    }

    // Phase D: analytic support-fixpoint solves
#pragma unroll 1
    for (int ps = 0; ps < SOLVE_ITERS; ps++) {
        float nA = 0.f, s1A = 0.f, s2A = 0.f;
        float nB = 0.f, s1B = 0.f, s2B = 0.f;
#pragma unroll
        for (int t = 0; t < 16; t++) {
#pragma unroll
            for (int e = 0; e < 2; e++) {
                float a = acc[t][e];
                if (a > tmA) { nA += 1.f; s1A += a; s2A = fmaf(a, a, s2A); }
                float b = acc[t][e + 2];
                if (b > tmB) { nB += 1.f; s1B += b; s2B = fmaf(b, b, s2B); }
            }
        }
#pragma unroll
        for (int o = 1; o <= 2; o <<= 1) {
            nA += __shfl_xor_sync(0xffffffffu, nA, o);
            s1A += __shfl_xor_sync(0xffffffffu, s1A, o);
            s2A += __shfl_xor_sync(0xffffffffu, s2A, o);
            nB += __shfl_xor_sync(0xffffffffu, nB, o);
            s1B += __shfl_xor_sync(0xffffffffu, s1B, o);
            s2B += __shfl_xor_sync(0xffffffffu, s2B, o);
        }
        float* RP = RED + par * 768;
        if (qlead) {
            RP[r0 * 8 + wcol] = nA;        RP[r1 * 8 + wcol] = nB;
            RP[256 + r0 * 8 + wcol] = s1A; RP[256 + r1 * 8 + wcol] = s1B;
            RP[512 + r0 * 8 + wcol] = s2A; RP[512 + r1 * 8 + wcol] = s2B;
        }
        __syncthreads();
        {
            float n = sum8(RP, r0), s1 = sum8(RP + 256, r0), s2 = sum8(RP + 512, r0);
            float D = fmaxf(fmaf(s1, s1, -n * (s2 - 1.0f)), 0.f);
            tmA = (s1 - sqrtf(D)) / n;
            n = sum8(RP, r1); s1 = sum8(RP + 256, r1); s2 = sum8(RP + 512, r1);
            D = fmaxf(fmaf(s1, s1, -n * (s2 - 1.0f)), 0.f);
            tmB = (s1 - sqrtf(D)) / n;
        }
        par ^= 1;
    }

    // Phase E: final p + normalize + write
    float ivA, ivB;
    {
        float c0 = 0.f, c1 = 0.f, c2 = 0.f, c3 = 0.f;
#pragma unroll
        for (int t = 0; t < 16; t++) {
            float u;
            u = fmaxf(acc[t][0] - tmA, 0.f); acc[t][0] = u * u; c0 += acc[t][0];
            u = fmaxf(acc[t][1] - tmA, 0.f); acc[t][1] = u * u; c1 += acc[t][1];
            u = fmaxf(acc[t][2] - tmB, 0.f); acc[t][2] = u * u; c2 += acc[t][2];
            u = fmaxf(acc[t][3] - tmB, 0.f); acc[t][3] = u * u; c3 += acc[t][3];
        }
        float vA = c0 + c1, vB = c2 + c3;
        vA += __shfl_xor_sync(0xffffffffu, vA, 1);
        vA += __shfl_xor_sync(0xffffffffu, vA, 2);
        vB += __shfl_xor_sync(0xffffffffu, vB, 1);
        vB += __shfl_xor_sync(0xffffffffu, vB, 2);
        float* RP = RED + par * 768;
        if (qlead) { RP[r0 * 8 + wcol] = vA; RP[r1 * 8 + wcol] = vB; }
        __syncthreads();
        ivA = 1.0f / sum8(RP, r0);
        ivB = 1.0f / sum8(RP, r1);
    }
    {
        size_t rb0 = ((size_t)bh * SEQ + R0 + r0) * SEQ + wcol * 128 + (lane & 3) * 2;
        size_t rb1 = ((size_t)bh * SEQ + R0 + r1) * SEQ + wcol * 128 + (lane & 3) * 2;
#pragma unroll
        for (int t = 0; t < 16; t++) {
            float p0 = acc[t][0] * ivA, p1 = acc[t][1] * ivA;
            float p2 = acc[t][2] * ivB, p3 = acc[t][3] * ivB;
            *(float2*)(attn + rb0 + t * 8) = {p0, p1};
            *(float2*)(attn + rb1 + t * 8) = {p2, p3};
            __nv_bfloat16 h0, l0, h1, l1;
            split1(p0, h0, l0); split1(p1, h1, l1);
            *(__nv_bfloat162*)(phi + rb0 + t * 8) = {h0, h1};
            *(__nv_bfloat162*)(plo + rb0 + t * 8) = {l0, l1};
            split1(p2, h0, l0); split1(p3, h1, l1);
            *(__nv_bfloat162*)(phi + rb1 + t * 8) = {h0, h1};
            *(__nv_bfloat162*)(plo + rb1 + t * 8) = {l0, l1};
        }
    }
}

// ===================== attn @ V via HMMA (split-bf16) ======================
#define VSTAGE 24576
#define VSMEM (3 * VSTAGE)

__global__ __launch_bounds__(256) void gemm_av_mma(
    const __nv_bfloat16* __restrict__ Ph, const __nv_bfloat16* __restrict__ Pl,
    const __nv_bfloat16* __restrict__ Vh, const __nv_bfloat16* __restrict__ Vl,
    __nv_bfloat16* __restrict__ chi, __nv_bfloat16* __restrict__ clo)
{
    extern __shared__ char sm[];
    uint32_t sb = smem_u32(sm);
    int tid = threadIdx.x, lane = tid & 31, wid = tid >> 5;
    int wm = wid >> 1, wn = wid & 1;
    int m0 = blockIdx.x * 128;
    int bh = blockIdx.y;

    const __nv_bfloat16* pa[2] = { Ph + ((size_t)bh * SEQ + m0) * SEQ,
                                   Pl + ((size_t)bh * SEQ + m0) * SEQ };
    const __nv_bfloat16* pb[2] = { Vh + (size_t)bh * DH * SEQ,
                                   Vl + (size_t)bh * DH * SEQ };

    auto load_stage = [&](int kt, int s) {
        uint32_t base = sb + s * VSTAGE;
#pragma unroll
        for (int i = 0; i < 4; i++) {
            int idx = tid + i * 256;
            int hl = idx >> 9;
            int row = (idx >> 2) & 127;
            int u = idx & 3;
            const __nv_bfloat16* g = pa[hl] + (size_t)row * SEQ + kt * 32 + u * 8;
            uint32_t d = base + hl * 8192 + row * 64 + ((u ^ (row & 3)) * 16);
            CP_ASYNC16(d, g);
        }
#pragma unroll
        for (int i = 0; i < 2; i++) {
            int idx = tid + i * 256;
            int hl = idx >> 8;
            int row = (idx >> 2) & 63;
            int u = idx & 3;
            const __nv_bfloat16* g = pb[hl] + (size_t)row * SEQ + kt * 32 + u * 8;
            uint32_t d = base + 16384 + hl * 4096 + row * 64 + ((u ^ (row & 3)) * 16);
            CP_ASYNC16(d, g);
        }
        CP_COMMIT();
    };

    float acc[2][4][4];
#pragma unroll
    for (int a = 0; a < 2; a++)
#pragma unroll
        for (int b = 0; b < 4; b++)
#pragma unroll
            for (int c = 0; c < 4; c++) acc[a][b][c] = 0.0f;

    int arow = (lane & 7) | (((lane >> 3) & 1) << 3);
    int asel = lane >> 4;
    int brow = (lane & 7) | ((lane >> 4) << 3);
    int bsel = (lane >> 3) & 1;

    load_stage(0, 0);
    load_stage(1, 1);

#pragma unroll 1
    for (int t = 0; t < 32; t++) {
        if (t >= 30) { CP_WAIT0(); } else { CP_WAIT1(); }
        __syncthreads();
        if (t + 2 < 32) load_stage(t + 2, (t + 2) % 3);

        uint32_t base = sb + (t % 3) * VSTAGE;
        uint32_t Ahb = base, Alb = base + 8192, Bhb = base + 16384, Blb = base + 20480;

#pragma unroll
        for (int ks = 0; ks < 2; ks++) {
            int akc = ks * 2 + asel;
            int bkc = ks * 2 + bsel;
            uint32_t ah[2][4], al[2][4], bh4[2][4], bl4[2][4];
#pragma unroll
            for (int mt = 0; mt < 2; mt++) {
                int row = wm * 32 + mt * 16 + arow;
                uint32_t off = row * 64 + ((akc ^ (row & 3)) * 16);
                LDSM4(ah[mt][0], ah[mt][1], ah[mt][2], ah[mt][3], Ahb + off);
                LDSM4(al[mt][0], al[mt][1], al[mt][2], al[mt][3], Alb + off);
            }
#pragma unroll
            for (int nt = 0; nt < 2; nt++) {
                int row = wn * 32 + nt * 16 + brow;
                uint32_t off = row * 64 + ((bkc ^ (row & 3)) * 16);
                LDSM4(bh4[nt][0], bh4[nt][1], bh4[nt][2], bh4[nt][3], Bhb + off);
                LDSM4(bl4[nt][0], bl4[nt][1], bl4[nt][2], bl4[nt][3], Blb + off);
            }
#pragma unroll
            for (int mt = 0; mt < 2; mt++)
#pragma unroll
                for (int nt = 0; nt < 2; nt++) {
                    MMA16816(acc[mt][nt * 2 + 0], ah[mt], bh4[nt][0], bh4[nt][1]);
                    MMA16816(acc[mt][nt * 2 + 1], ah[mt], bh4[nt][2], bh4[nt][3]);
                    MMA16816(acc[mt][nt * 2 + 0], ah[mt], bl4[nt][0], bl4[nt][1]);
                    MMA16816(acc[mt][nt * 2 + 1], ah[mt], bl4[nt][2], bl4[nt][3]);
                    MMA16816(acc[mt][nt * 2 + 0], al[mt], bh4[nt][0], bh4[nt][1]);
                    MMA16816(acc[mt][nt * 2 + 1], al[mt], bh4[nt][2], bh4[nt][3]);
                }
        }
        __syncthreads();
    }

    // epilogue: write ctx split [tok][1024]
    int r = lane >> 2, c2 = (lane & 3) * 2;
    int bidx = bh >> 4, h = bh & 15;
#pragma unroll
    for (int mt = 0; mt < 2; mt++) {
        int mrow = m0 + wm * 32 + mt * 16 + r;
        size_t tok0 = (size_t)(bidx * SEQ + mrow) * CH;
        size_t tok1 = (size_t)(bidx * SEQ + mrow + 8) * CH;
#pragma unroll
        for (int nt8 = 0; nt8 < 4; nt8++) {
            int col = h * DH + wn * 32 + nt8 * 8 + c2;
            __nv_bfloat16 h0, l0, h1, l1;
            split1(acc[mt][nt8][0], h0, l0); split1(acc[mt][nt8][1], h1, l1);
            *(__nv_bfloat162*)(chi + tok0 + col) = {h0, h1};
            *(__nv_bfloat162*)(clo + tok0 + col) = {l0, l1};
            split1(acc[mt][nt8][2], h0, l0); split1(acc[mt][nt8][3], h1, l1);
            *(__nv_bfloat162*)(chi + tok1 + col) = {h0, h1};
            *(__nv_bfloat162*)(clo + tok1 + col) = {l0, l1};
        }
    }
}

// ---------------------------------------------------------------------------
extern "C" void kernel_launch(void* const* d_in, const int* in_sizes, int n_in,
                              void* d_out, int out_size)
{
    const float* x  = (const float*)d_in[0];
    const float* Wq = (const float*)d_in[1];
    const float* bq = (const float*)d_in[2];
    const float* Wk = (const float*)d_in[3];
    const float* bk = (const float*)d_in[4];
    const float* Wv = (const float*)d_in[5];
    const float* bv = (const float*)d_in[6];
    const float* Wo = (const float*)d_in[7];
    const float* bo = (const float*)d_in[8];

    float* out_ptr  = (float*)d_out;
    float* attn_ptr = out_ptr + OUT_ELEMS;

    __nv_bfloat16 *p_xhi, *p_xlo, *p_wthi, *p_wtlo;
    __nv_bfloat16 *p_qhi, *p_qlo, *p_khi, *p_klo, *p_vthi, *p_vtlo;
    __nv_bfloat16 *p_phi, *p_plo, *p_chi, *p_clo;
    cudaGetSymbolAddress((void**)&p_xhi, g_xhi);
    cudaGetSymbolAddress((void**)&p_xlo, g_xlo);
    cudaGetSymbolAddress((void**)&p_wthi, g_wthi);
    cudaGetSymbolAddress((void**)&p_wtlo, g_wtlo);
    cudaGetSymbolAddress((void**)&p_qhi, g_qhi);
    cudaGetSymbolAddress((void**)&p_qlo, g_qlo);
    cudaGetSymbolAddress((void**)&p_khi, g_khi);
    cudaGetSymbolAddress((void**)&p_klo, g_klo);
    cudaGetSymbolAddress((void**)&p_vthi, g_vthi);
    cudaGetSymbolAddress((void**)&p_vtlo, g_vtlo);
    cudaGetSymbolAddress((void**)&p_phi, g_phi);
    cudaGetSymbolAddress((void**)&p_plo, g_plo);
    cudaGetSymbolAddress((void**)&p_chi, g_chi);
    cudaGetSymbolAddress((void**)&p_clo, g_clo);

    cudaFuncSetAttribute(gemm_mma, cudaFuncAttributeMaxDynamicSharedMemorySize, GSMEM);
    cudaFuncSetAttribute(attn_entmax_mma, cudaFuncAttributeMaxDynamicSharedMemorySize, ESMEM);
    cudaFuncSetAttribute(gemm_av_mma, cudaFuncAttributeMaxDynamicSharedMemorySize, VSMEM);

    // Fork-join side streams (created once; work per call is identical)
    static cudaStream_t s1 = nullptr, s2 = nullptr;
    static cudaEvent_t eFork = nullptr, eX = nullptr, eJ1 = nullptr, eJ2 = nullptr;
    if (s1 == nullptr) {
        cudaStreamCreateWithFlags(&s1, cudaStreamNonBlocking);
        cudaStreamCreateWithFlags(&s2, cudaStreamNonBlocking);
        cudaEventCreateWithFlags(&eFork, cudaEventDisableTiming);
        cudaEventCreateWithFlags(&eX, cudaEventDisableTiming);
        cudaEventCreateWithFlags(&eJ1, cudaEventDisableTiming);
        cudaEventCreateWithFlags(&eJ2, cudaEventDisableTiming);
    }

    dim3 wt(32, 32), wb(32, 8);
    dim3 gg(8, 32);

    // Fork
    cudaEventRecord(eFork, 0);
    cudaStreamWaitEvent(s1, eFork, 0);
    cudaStreamWaitEvent(s2, eFork, 0);

    // stream 0: x split (needed by all three QKV), then V path
    split_convert<<<OUT_ELEMS / 4 / 256, 256>>>(x, p_xhi, p_xlo, OUT_ELEMS / 4);
    cudaEventRecord(eX, 0);
    wtrans_convert<<<wt, wb>>>(Wv, p_wthi + 2 * 1048576, p_wtlo + 2 * 1048576);
    wtrans_convert<<<wt, wb>>>(Wo, p_wthi + 3 * 1048576, p_wtlo + 3 * 1048576);
    gemm_mma<<<gg, 256, GSMEM>>>(p_xhi, p_xlo, p_wthi + 2 * 1048576, p_wtlo + 2 * 1048576,
                                 bv, nullptr, p_vthi, p_vtlo, 1);

    // s1: Q path
    wtrans_convert<<<wt, wb, 0, s1>>>(Wq, p_wthi + 0 * 1048576, p_wtlo + 0 * 1048576);
    cudaStreamWaitEvent(s1, eX, 0);
    gemm_mma<<<gg, 256, GSMEM, s1>>>(p_xhi, p_xlo, p_wthi + 0 * 1048576, p_wtlo + 0 * 1048576,
                                     bq, nullptr, p_qhi, p_qlo, 0);
    cudaEventRecord(eJ1, s1);

    // s2: K path
    wtrans_convert<<<wt, wb, 0, s2>>>(Wk, p_wthi + 1 * 1048576, p_wtlo + 1 * 1048576);
    cudaStreamWaitEvent(s2, eX, 0);
    gemm_mma<<<gg, 256, GSMEM, s2>>>(p_xhi, p_xlo, p_wthi + 1 * 1048576, p_wtlo + 1 * 1048576,
                                     bk, nullptr, p_khi, p_klo, 0);
    cudaEventRecord(eJ2, s2);

    // Join
    cudaStreamWaitEvent(0, eJ1, 0);
    cudaStreamWaitEvent(0, eJ2, 0);

    dim3 ge(32, BH);
    attn_entmax_mma<<<ge, 512, ESMEM>>>(attn_ptr, p_qhi, p_qlo, p_khi, p_klo, p_phi, p_plo);

    dim3 ga(8, BH);
    gemm_av_mma<<<ga, 256, VSMEM>>>(p_phi, p_plo, p_vthi, p_vtlo, p_chi, p_clo);

    gemm_mma<<<gg, 256, GSMEM>>>(p_chi, p_clo, p_wthi + 3 * 1048576, p_wtlo + 3 * 1048576,
                                 bo, out_ptr, nullptr, nullptr, 2);
}

// round 8
// speedup vs baseline: 1.0238x; 1.0238x over previous
#include <cuda_runtime.h>
#include <cuda_bf16.h>
#include <cstdint>

#define BATCH 4
#define SEQ   1024
#define CH    1024
#define HEADS 16
#define DH    64
#define TOKENS (BATCH * SEQ)
#define BH (BATCH * HEADS)
#define OUT_ELEMS (TOKENS * CH)

#define BISECT_ITERS 12
#define SOLVE_ITERS 3
#define SCALE 0.0625f   // (1/sqrt(64)) * (alpha-1)

// bf16 split scratch
__device__ __nv_bfloat16 g_xhi[TOKENS * CH];
__device__ __nv_bfloat16 g_xlo[TOKENS * CH];
__device__ __nv_bfloat16 g_wthi[4 * CH * CH];
__device__ __nv_bfloat16 g_wtlo[4 * CH * CH];
__device__ __nv_bfloat16 g_qhi[BH * SEQ * DH];
__device__ __nv_bfloat16 g_qlo[BH * SEQ * DH];
__device__ __nv_bfloat16 g_khi[BH * SEQ * DH];
__device__ __nv_bfloat16 g_klo[BH * SEQ * DH];
__device__ __nv_bfloat16 g_vthi[BH * DH * SEQ];   // transposed V: [bh][dh][tok]
__device__ __nv_bfloat16 g_vtlo[BH * DH * SEQ];
__device__ __nv_bfloat16 g_phi[(size_t)BH * SEQ * SEQ];  // attn split
__device__ __nv_bfloat16 g_plo[(size_t)BH * SEQ * SEQ];
__device__ __nv_bfloat16 g_chi[TOKENS * CH];
__device__ __nv_bfloat16 g_clo[TOKENS * CH];

// ===================== PTX helpers =========================================
__device__ __forceinline__ uint32_t smem_u32(const void* p) {
    uint32_t a;
    asm("{ .reg .u64 t; cvta.to.shared.u64 t, %1; cvt.u32.u64 %0, t; }" : "=r"(a) : "l"(p));
    return a;
}
#define CP_ASYNC16(sa, g) \
    asm volatile("cp.async.cg.shared.global [%0], [%1], 16;" :: "r"(sa), "l"(g))
#define CP_COMMIT() asm volatile("cp.async.commit_group;" ::: "memory")
#define CP_WAIT0() asm volatile("cp.async.wait_group 0;" ::: "memory")
#define CP_WAIT1() asm volatile("cp.async.wait_group 1;" ::: "memory")
#define LDSM4(r0, r1, r2, r3, addr) \
    asm volatile("ldmatrix.sync.aligned.m8n8.x4.shared.b16 {%0,%1,%2,%3}, [%4];" \
        : "=r"(r0), "=r"(r1), "=r"(r2), "=r"(r3) : "r"(addr))
#define MMA16816(d, a, b0, b1) \
    asm volatile("mma.sync.aligned.m16n8k16.row.col.f32.bf16.bf16.f32 " \
        "{%0,%1,%2,%3}, {%4,%5,%6,%7}, {%8,%9}, {%0,%1,%2,%3};" \
        : "+f"((d)[0]), "+f"((d)[1]), "+f"((d)[2]), "+f"((d)[3]) \
        : "r"((a)[0]), "r"((a)[1]), "r"((a)[2]), "r"((a)[3]), "r"(b0), "r"(b1))

__device__ __forceinline__ void split1(float v, __nv_bfloat16& h, __nv_bfloat16& l) {
    h = __float2bfloat16_rn(v);
    l = __float2bfloat16_rn(v - __bfloat162float(h));
}
__device__ __forceinline__ float sum8(const float* base, int row) {
    float4 a = ((const float4*)base)[row * 2];
    float4 b = ((const float4*)base)[row * 2 + 1];
    return ((a.x + a.y) + (a.z + a.w)) + ((b.x + b.y) + (b.z + b.w));
}
__device__ __forceinline__ float max8(const float* base, int row) {
    float4 a = ((const float4*)base)[row * 2];
    float4 b = ((const float4*)base)[row * 2 + 1];
    return fmaxf(fmaxf(fmaxf(a.x, a.y), fmaxf(a.z, a.w)),
                 fmaxf(fmaxf(b.x, b.y), fmaxf(b.z, b.w)));
}

// ===================== convert kernels =====================================
__global__ __launch_bounds__(256) void split_convert(
    const float* __restrict__ in, __nv_bfloat16* __restrict__ hi,
    __nv_bfloat16* __restrict__ lo, int n4)
{
    int i = blockIdx.x * 256 + threadIdx.x;
    if (i >= n4) return;
    float4 v = ((const float4*)in)[i];
    union { ushort u[4]; uint2 q; } H, L;
    float a[4] = {v.x, v.y, v.z, v.w};
#pragma unroll
    for (int j = 0; j < 4; j++) {
        __nv_bfloat16 h, l; split1(a[j], h, l);
        H.u[j] = __bfloat16_as_ushort(h);
        L.u[j] = __bfloat16_as_ushort(l);
    }
    ((uint2*)hi)[i] = H.q;
    ((uint2*)lo)[i] = L.q;
}

__global__ __launch_bounds__(256) void wtrans_convert(
    const float* __restrict__ W, __nv_bfloat16* __restrict__ hi,
    __nv_bfloat16* __restrict__ lo)
{
    __shared__ float t[32][33];
    int tx = threadIdx.x, ty = threadIdx.y;
    int bx = blockIdx.x, by = blockIdx.y;
#pragma unroll
    for (int i = 0; i < 4; i++)
        t[ty + i * 8][tx] = W[(size_t)(by * 32 + ty + i * 8) * 1024 + bx * 32 + tx];
    __syncthreads();
#pragma unroll
    for (int i = 0; i < 4; i++) {
        float v = t[tx][ty + i * 8];
        __nv_bfloat16 h, l; split1(v, h, l);
        size_t o = (size_t)(bx * 32 + ty + i * 8) * 1024 + by * 32 + tx;
        hi[o] = h;
        lo[o] = l;
    }
}

// ===================== split-bf16 mma.sync GEMM (projections) ==============
// 2-stage smem (64KB), 2 CTAs/SM for latency hiding.
#define GSTAGE 32768
#define GSMEM (2 * GSTAGE)

__global__ __launch_bounds__(256, 2) void gemm_mma(
    const __nv_bfloat16* __restrict__ Ah, const __nv_bfloat16* __restrict__ Al,
    const __nv_bfloat16* __restrict__ Bh, const __nv_bfloat16* __restrict__ Bl,
    const float* __restrict__ bias, float* __restrict__ dstf,
    __nv_bfloat16* __restrict__ dhi, __nv_bfloat16* __restrict__ dlo, int mode)
{
    extern __shared__ char sm[];
    uint32_t sb = smem_u32(sm);
    int tid = threadIdx.x, lane = tid & 31, wid = tid >> 5;
    int wm = wid >> 2, wn = wid & 3;
    int n0 = blockIdx.x * 128, m0 = blockIdx.y * 128;

    const __nv_bfloat16* gsrc[4] = {
        Ah + (size_t)m0 * 1024, Al + (size_t)m0 * 1024,
        Bh + (size_t)n0 * 1024, Bl + (size_t)n0 * 1024 };

    int l_row0 = tid >> 2,         l_c0 = tid & 3;
    int l_row1 = (tid + 256) >> 2, l_c1 = (tid + 256) & 3;

    auto load_stage = [&](int kt, int s) {
        uint32_t sbase = sb + s * GSTAGE;
#pragma unroll
        for (int t = 0; t < 4; t++) {
            const char* g0 = (const char*)(gsrc[t] + (size_t)l_row0 * 1024 + kt * 32) + l_c0 * 16;
            const char* g1 = (const char*)(gsrc[t] + (size_t)l_row1 * 1024 + kt * 32) + l_c1 * 16;
            uint32_t s0 = sbase + t * 8192 + l_row0 * 64 + ((l_c0 ^ (l_row0 & 3)) * 16);
            uint32_t s1 = sbase + t * 8192 + l_row1 * 64 + ((l_c1 ^ (l_row1 & 3)) * 16);
            CP_ASYNC16(s0, g0);
            CP_ASYNC16(s1, g1);
        }
        CP_COMMIT();
    };

    float acc[4][4][4];
#pragma unroll
    for (int a = 0; a < 4; a++)
#pragma unroll
        for (int b = 0; b < 4; b++)
#pragma unroll
            for (int c = 0; c < 4; c++) acc[a][b][c] = 0.0f;

    int arow = (lane & 7) | (((lane >> 3) & 1) << 3);
    int asel = lane >> 4;
    int brow = (lane & 7) | ((lane >> 4) << 3);
    int bsel = (lane >> 3) & 1;

    load_stage(0, 0);
    load_stage(1, 1);

#pragma unroll 1
    for (int t = 0; t < 32; t++) {
        if (t >= 31) { CP_WAIT0(); } else { CP_WAIT1(); }
        __syncthreads();

        uint32_t base = sb + (t & 1) * GSTAGE;
        uint32_t Ahb = base, Alb = base + 8192, Bhb = base + 16384, Blb = base + 24576;

#pragma unroll
        for (int ks = 0; ks < 2; ks++) {
            int akc = ks * 2 + asel;
            int bkc = ks * 2 + bsel;
            uint32_t ah[4][4], al[4][4], bhf[2][4], blf[2][4];
#pragma unroll
            for (int mt = 0; mt < 4; mt++) {
                int row = wm * 64 + mt * 16 + arow;
                uint32_t off = row * 64 + ((akc ^ (row & 3)) * 16);
                LDSM4(ah[mt][0], ah[mt][1], ah[mt][2], ah[mt][3], Ahb + off);
            }
#pragma unroll
            for (int nt = 0; nt < 2; nt++) {
                int row = wn * 32 + nt * 16 + brow;
                uint32_t off = row * 64 + ((bkc ^ (row & 3)) * 16);
                LDSM4(bhf[nt][0], bhf[nt][1], bhf[nt][2], bhf[nt][3], Bhb + off);
            }
#pragma unroll
            for (int mt = 0; mt < 4; mt++)
#pragma unroll
                for (int nt = 0; nt < 2; nt++) {
                    MMA16816(acc[mt][nt * 2 + 0], ah[mt], bhf[nt][0], bhf[nt][1]);
                    MMA16816(acc[mt][nt * 2 + 1], ah[mt], bhf[nt][2], bhf[nt][3]);
                }
#pragma unroll
            for (int nt = 0; nt < 2; nt++) {
                int row = wn * 32 + nt * 16 + brow;
                uint32_t off = row * 64 + ((bkc ^ (row & 3)) * 16);
                LDSM4(blf[nt][0], blf[nt][1], blf[nt][2], blf[nt][3], Blb + off);
            }
#pragma unroll
            for (int mt = 0; mt < 4; mt++)
#pragma unroll
                for (int nt = 0; nt < 2; nt++) {
                    MMA16816(acc[mt][nt * 2 + 0], ah[mt], blf[nt][0], blf[nt][1]);
                    MMA16816(acc[mt][nt * 2 + 1], ah[mt], blf[nt][2], blf[nt][3]);
                }
#pragma unroll
            for (int mt = 0; mt < 4; mt++) {
                int row = wm * 64 + mt * 16 + arow;
                uint32_t off = row * 64 + ((akc ^ (row & 3)) * 16);
                LDSM4(al[mt][0], al[mt][1], al[mt][2], al[mt][3], Alb + off);
            }
#pragma unroll
            for (int mt = 0; mt < 4; mt++)
#pragma unroll
                for (int nt = 0; nt < 2; nt++) {
                    MMA16816(acc[mt][nt * 2 + 0], al[mt], bhf[nt][0], bhf[nt][1]);
                    MMA16816(acc[mt][nt * 2 + 1], al[mt], bhf[nt][2], bhf[nt][3]);
                }
        }
        __syncthreads();
        if (t + 2 < 32) load_stage(t + 2, t & 1);
    }

    // epilogue
    int r = lane >> 2, c2 = (lane & 3) * 2;
#pragma unroll
    for (int mt = 0; mt < 4; mt++) {
        int mrow = m0 + wm * 64 + mt * 16 + r;
        int bidx = mrow >> 10, ntok = mrow & 1023;
#pragma unroll
        for (int nt8 = 0; nt8 < 4; nt8++) {
            int col = n0 + wn * 32 + nt8 * 8 + c2;
            float b0 = bias[col], b1 = bias[col + 1];
            float v00 = acc[mt][nt8][0] + b0, v01 = acc[mt][nt8][1] + b1;
            float v10 = acc[mt][nt8][2] + b0, v11 = acc[mt][nt8][3] + b1;
            if (mode == 0) {
                int h = col >> 6, dh = col & 63;
                size_t base = ((size_t)(bidx * HEADS + h) * SEQ + ntok) * DH + dh;
                __nv_bfloat16 h0, l0, h1, l1;
                split1(v00, h0, l0); split1(v01, h1, l1);
                *(__nv_bfloat162*)(dhi + base) = {h0, h1};
                *(__nv_bfloat162*)(dlo + base) = {l0, l1};
                split1(v10, h0, l0); split1(v11, h1, l1);
                *(__nv_bfloat162*)(dhi + base + 8 * DH) = {h0, h1};
                *(__nv_bfloat162*)(dlo + base + 8 * DH) = {l0, l1};
            } else if (mode == 1) {
                int h = col >> 6, dh = col & 63;
                size_t vb = ((size_t)(bidx * HEADS + h) * DH + dh) * SEQ + ntok;
                __nv_bfloat16 hh, ll;
                split1(v00, hh, ll); dhi[vb] = hh; dlo[vb] = ll;
                split1(v01, hh, ll); dhi[vb + SEQ] = hh; dlo[vb + SEQ] = ll;
                split1(v10, hh, ll); dhi[vb + 8] = hh; dlo[vb + 8] = ll;
                split1(v11, hh, ll); dhi[vb + SEQ + 8] = hh; dlo[vb + SEQ + 8] = ll;
            } else {
                float* p = dstf + (size_t)mrow * CH + col;
                *(float2*)p = {v00, v01};
                *(float2*)(p + 8 * CH) = {v10, v11};
            }
        }
    }
}

// ===================== fused HMMA scores + entmax ==========================
// RED: 2 parities x 768 floats
#define EOFF_QH 0
#define EOFF_QL 4096
#define EOFF_K  8192
#define EOFF_RED 73728
#define ESMEM (73728 + 6144)

__global__ __launch_bounds__(512) void attn_entmax_mma(
    float* __restrict__ attn,
    const __nv_bfloat16* __restrict__ qhi, const __nv_bfloat16* __restrict__ qlo,
    const __nv_bfloat16* __restrict__ khi, const __nv_bfloat16* __restrict__ klo,
    __nv_bfloat16* __restrict__ phi, __nv_bfloat16* __restrict__ plo)
{
    extern __shared__ char sm[];
    uint32_t sb = smem_u32(sm);
    float* RED = (float*)(sm + EOFF_RED);   // [2][768]

    int tid = threadIdx.x, lane = tid & 31, wid = tid >> 5;
    int wrow = wid >> 3, wcol = wid & 7;
    int bh = blockIdx.y;
    int R0 = blockIdx.x * 32;

    {   // Q: 512 chunks, 1/thread (joins group 0 commit below)
        int hl = tid >> 8;
        int row = (tid >> 3) & 31;
        int u = tid & 7;
        const __nv_bfloat16* src = (hl ? qlo : qhi) + ((size_t)bh * SEQ + R0 + row) * DH + u * 8;
        uint32_t d = sb + EOFF_QH + hl * 4096 + row * 128 + ((u ^ (row & 7)) * 16);
        CP_ASYNC16(d, src);
    }
    auto loadK = [&](int c, int s) {
        uint32_t base = sb + EOFF_K + s * 32768;
#pragma unroll
        for (int i = 0; i < 4; i++) {
            int idx = tid + i * 512;
            int hl = idx >> 10;
            int row = (idx >> 3) & 127;
            int u = idx & 7;
            const __nv_bfloat16* src = (hl ? klo : khi) + ((size_t)bh * SEQ + c * 128 + row) * DH + u * 8;
            uint32_t d = base + hl * 16384 + row * 128 + ((u ^ (row & 7)) * 16);
            CP_ASYNC16(d, src);
        }
        CP_COMMIT();
    };
    loadK(0, 0);
    loadK(1, 1);

    float acc[16][4];
#pragma unroll
    for (int t = 0; t < 16; t++)
#pragma unroll
        for (int e = 0; e < 4; e++) acc[t][e] = 0.0f;

    int arow_ = wrow * 16 + ((lane & 7) | (((lane >> 3) & 1) << 3));
    int asel = lane >> 4;
    int brow_ = (lane & 7) | ((lane >> 4) << 3);
    int bsel = (lane >> 3) & 1;

#pragma unroll 1
    for (int c = 0; c < 8; c++) {
        if (c >= 7) { CP_WAIT0(); } else { CP_WAIT1(); }
        __syncthreads();
        if (wcol == c) {
            uint32_t KHb = sb + EOFF_K + (c & 1) * 32768;
            uint32_t KLb = KHb + 16384;
            uint32_t QHb = sb + EOFF_QH, QLb = sb + EOFF_QL;
#pragma unroll
            for (int kc = 0; kc < 4; kc++) {
                uint32_t au = (uint32_t)(kc * 2 + asel);
                uint32_t aoff = arow_ * 128 + ((au ^ (arow_ & 7)) * 16);
                uint32_t ah[4], al[4];
                LDSM4(ah[0], ah[1], ah[2], ah[3], QHb + aoff);
                LDSM4(al[0], al[1], al[2], al[3], QLb + aoff);
#pragma unroll
                for (int nt = 0; nt < 8; nt++) {
                    int krow = nt * 16 + brow_;
                    uint32_t bu = (uint32_t)(kc * 2 + bsel);
                    uint32_t boff = krow * 128 + ((bu ^ (krow & 7)) * 16);
                    uint32_t bh4[4], bl4[4];
                    LDSM4(bh4[0], bh4[1], bh4[2], bh4[3], KHb + boff);
                    LDSM4(bl4[0], bl4[1], bl4[2], bl4[3], KLb + boff);
                    MMA16816(acc[nt * 2 + 0], ah, bh4[0], bh4[1]);
                    MMA16816(acc[nt * 2 + 1], ah, bh4[2], bh4[3]);
                    MMA16816(acc[nt * 2 + 0], ah, bl4[0], bl4[1]);
                    MMA16816(acc[nt * 2 + 1], ah, bl4[2], bl4[3]);
                    MMA16816(acc[nt * 2 + 0], al, bh4[0], bh4[1]);
                    MMA16816(acc[nt * 2 + 1], al, bh4[2], bh4[3]);
                    MMA16816(acc[nt * 2 + 0], al, bl4[0], bl4[1]);
                    MMA16816(acc[nt * 2 + 1], al, bl4[2], bl4[3]);
                }
            }
        }
        __syncthreads();
        if (c + 2 < 8) loadK(c + 2, c & 1);
    }

    // --- entmax in HMMA layout, redundant all-thread reductions ---
    int r0 = wrow * 16 + (lane >> 2);
    int r1 = r0 + 8;
    bool qlead = (lane & 3) == 0;
    int par = 0;

#pragma unroll
    for (int t = 0; t < 16; t++)
#pragma unroll
        for (int e = 0; e < 4; e++) acc[t][e] *= SCALE;

    // Phase A: row max
    float tloA, tloB;
    {
        float mA = -1e30f, mB = -1e30f;
#pragma unroll
        for (int t = 0; t < 16; t++) {
            mA = fmaxf(mA, fmaxf(acc[t][0], acc[t][1]));
            mB = fmaxf(mB, fmaxf(acc[t][2], acc[t][3]));
        }
        mA = fmaxf(mA, __shfl_xor_sync(0xffffffffu, mA, 1));
        mA = fmaxf(mA, __shfl_xor_sync(0xffffffffu, mA, 2));
        mB = fmaxf(mB, __shfl_xor_sync(0xffffffffu, mB, 1));
        mB = fmaxf(mB, __shfl_xor_sync(0xffffffffu, mB, 2));
        float* RP = RED + par * 768;
        if (qlead) { RP[r0 * 8 + wcol] = mA; RP[r1 * 8 + wcol] = mB; }
        __syncthreads();
        tloA = max8(RP, r0) - 1.0f;
        tloB = max8(RP, r1) - 1.0f;
        par ^= 1;
    }

    // Phase B: f_lo
    float flA, flB;
    {
        float c0 = 0.f, c1 = 0.f, c2 = 0.f, c3 = 0.f;
#pragma unroll
        for (int t = 0; t < 16; t++) {
            float u;
            u = fmaxf(acc[t][0] - tloA, 0.f); c0 = fmaf(u, u, c0);
            u = fmaxf(acc[t][1] - tloA, 0.f); c1 = fmaf(u, u, c1);
            u = fmaxf(acc[t][2] - tloB, 0.f); c2 = fmaf(u, u, c2);
            u = fmaxf(acc[t][3] - tloB, 0.f); c3 = fmaf(u, u, c3);
        }
        float vA = c0 + c1, vB = c2 + c3;
        vA += __shfl_xor_sync(0xffffffffu, vA, 1);
        vA += __shfl_xor_sync(0xffffffffu, vA, 2);
        vB += __shfl_xor_sync(0xffffffffu, vB, 1);
        vB += __shfl_xor_sync(0xffffffffu, vB, 2);
        float* RP = RED + par * 768;
        if (qlead) { RP[r0 * 8 + wcol] = vA; RP[r1 * 8 + wcol] = vB; }
        __syncthreads();
        flA = sum8(RP, r0) - 1.0f;
        flB = sum8(RP, r1) - 1.0f;
        par ^= 1;
    }

    float dm = 0.484375f;          // (1 - (1/1024)^0.5) / 2
    float tmA = tloA + dm, tmB = tloB + dm;

    // Phase C: bisection (1 barrier/iter, double-buffered partials)
#pragma unroll 1
    for (int it = 0; it < BISECT_ITERS; it++) {
        float c0 = 0.f, c1 = 0.f, c2 = 0.f, c3 = 0.f;
#pragma unroll
        for (int t = 0; t < 16; t++) {
            float u;
            u = fmaxf(acc[t][0] - tmA, 0.f); c0 = fmaf(u, u, c0);
            u = fmaxf(acc[t][1] - tmA, 0.f); c1 = fmaf(u, u, c1);
            u = fmaxf(acc[t][2] - tmB, 0.f); c2 = fmaf(u, u, c2);
            u = fmaxf(acc[t][3] - tmB, 0.f); c3 = fmaf(u, u, c3);
        }
        float vA = c0 + c1, vB = c2 + c3;
        vA += __shfl_xor_sync(0xffffffffu, vA, 1);
        vA += __shfl_xor_sync(0xffffffffu, vA, 2);
        vB += __shfl_xor_sync(0xffffffffu, vB, 1);
        vB += __shfl_xor_sync(0xffffffffu, vB, 2);
        float* RP = RED + par * 768;
        if (qlead) { RP[r0 * 8 + wcol] = vA; RP[r1 * 8 + wcol] = vB; }
        __syncthreads();
        float fmA = sum8(RP, r0) - 1.0f;
        float fmB = sum8(RP, r1) - 1.0f;
        if (fmA * flA >= 0.f) tloA = tmA;
        if (fmB * flB >= 0.f) tloB = tmB;
        if (it < BISECT_ITERS - 1) {
            dm *= 0.5f;
            tmA = tloA + dm;
            tmB = tloB + dm;
        }
        par ^= 1;
    }

    // Phase D: analytic support-fixpoint solves
#pragma unroll 1
    for (int ps = 0; ps < SOLVE_ITERS; ps++) {
        float nA = 0.f, s1A = 0.f, s2A = 0.f;
        float nB = 0.f, s1B = 0.f, s2B = 0.f;
#pragma unroll
        for (int t = 0; t < 16; t++) {
#pragma unroll
            for (int e = 0; e < 2; e++) {
                float a = acc[t][e];
                if (a > tmA) { nA += 1.f; s1A += a; s2A = fmaf(a, a, s2A); }
                float b = acc[t][e + 2];
                if (b > tmB) { nB += 1.f; s1B += b; s2B = fmaf(b, b, s2B); }
            }
        }
#pragma unroll
        for (int o = 1; o <= 2; o <<= 1) {
            nA += __shfl_xor_sync(0xffffffffu, nA, o);
            s1A += __shfl_xor_sync(0xffffffffu, s1A, o);
            s2A += __shfl_xor_sync(0xffffffffu, s2A, o);
            nB += __shfl_xor_sync(0xffffffffu, nB, o);
            s1B += __shfl_xor_sync(0xffffffffu, s1B, o);
            s2B += __shfl_xor_sync(0xffffffffu, s2B, o);
        }
        float* RP = RED + par * 768;
        if (qlead) {
            RP[r0 * 8 + wcol] = nA;        RP[r1 * 8 + wcol] = nB;
            RP[256 + r0 * 8 + wcol] = s1A; RP[256 + r1 * 8 + wcol] = s1B;
            RP[512 + r0 * 8 + wcol] = s2A; RP[512 + r1 * 8 + wcol] = s2B;
        }
        __syncthreads();
        {
            float n = sum8(RP, r0), s1 = sum8(RP + 256, r0), s2 = sum8(RP + 512, r0);
            float D = fmaxf(fmaf(s1, s1, -n * (s2 - 1.0f)), 0.f);
            tmA = (s1 - sqrtf(D)) / n;
            n = sum8(RP, r1); s1 = sum8(RP + 256, r1); s2 = sum8(RP + 512, r1);
            D = fmaxf(fmaf(s1, s1, -n * (s2 - 1.0f)), 0.f);
            tmB = (s1 - sqrtf(D)) / n;
        }
        par ^= 1;
    }

    // Phase E: final p + normalize + write
    float ivA, ivB;
    {
        float c0 = 0.f, c1 = 0.f, c2 = 0.f, c3 = 0.f;
#pragma unroll
        for (int t = 0; t < 16; t++) {
            float u;
            u = fmaxf(acc[t][0] - tmA, 0.f); acc[t][0] = u * u; c0 += acc[t][0];
            u = fmaxf(acc[t][1] - tmA, 0.f); acc[t][1] = u * u; c1 += acc[t][1];
            u = fmaxf(acc[t][2] - tmB, 0.f); acc[t][2] = u * u; c2 += acc[t][2];
            u = fmaxf(acc[t][3] - tmB, 0.f); acc[t][3] = u * u; c3 += acc[t][3];
        }
        float vA = c0 + c1, vB = c2 + c3;
        vA += __shfl_xor_sync(0xffffffffu, vA, 1);
        vA += __shfl_xor_sync(0xffffffffu, vA, 2);
        vB += __shfl_xor_sync(0xffffffffu, vB, 1);
        vB += __shfl_xor_sync(0xffffffffu, vB, 2);
        float* RP = RED + par * 768;
        if (qlead) { RP[r0 * 8 + wcol] = vA; RP[r1 * 8 + wcol] = vB; }
        __syncthreads();
        ivA = 1.0f / sum8(RP, r0);
        ivB = 1.0f / sum8(RP, r1);
    }
    {
        size_t rb0 = ((size_t)bh * SEQ + R0 + r0) * SEQ + wcol * 128 + (lane & 3) * 2;
        size_t rb1 = ((size_t)bh * SEQ + R0 + r1) * SEQ + wcol * 128 + (lane & 3) * 2;
#pragma unroll
        for (int t = 0; t < 16; t++) {
            float p0 = acc[t][0] * ivA, p1 = acc[t][1] * ivA;
            float p2 = acc[t][2] * ivB, p3 = acc[t][3] * ivB;
            *(float2*)(attn + rb0 + t * 8) = {p0, p1};
            *(float2*)(attn + rb1 + t * 8) = {p2, p3};
            __nv_bfloat16 h0, l0, h1, l1;
            split1(p0, h0, l0); split1(p1, h1, l1);
            *(__nv_bfloat162*)(phi + rb0 + t * 8) = {h0, h1};
            *(__nv_bfloat162*)(plo + rb0 + t * 8) = {l0, l1};
            split1(p2, h0, l0); split1(p3, h1, l1);
            *(__nv_bfloat162*)(phi + rb1 + t * 8) = {h0, h1};
            *(__nv_bfloat162*)(plo + rb1 + t * 8) = {l0, l1};
        }
    }
}

// ===================== attn @ V via HMMA (split-bf16) ======================
// 2-stage (48KB), 2 CTAs/SM.
#define VSTAGE 24576
#define VSMEM (2 * VSTAGE)

__global__ __launch_bounds__(256, 2) void gemm_av_mma(
    const __nv_bfloat16* __restrict__ Ph, const __nv_bfloat16* __restrict__ Pl,
    const __nv_bfloat16* __restrict__ Vh, const __nv_bfloat16* __restrict__ Vl,
    __nv_bfloat16* __restrict__ chi, __nv_bfloat16* __restrict__ clo)
{
    extern __shared__ char sm[];
    uint32_t sb = smem_u32(sm);
    int tid = threadIdx.x, lane = tid & 31, wid = tid >> 5;
    int wm = wid >> 1, wn = wid & 1;
    int m0 = blockIdx.x * 128;
    int bh = blockIdx.y;

    const __nv_bfloat16* pa[2] = { Ph + ((size_t)bh * SEQ + m0) * SEQ,
                                   Pl + ((size_t)bh * SEQ + m0) * SEQ };
    const __nv_bfloat16* pb[2] = { Vh + (size_t)bh * DH * SEQ,
                                   Vl + (size_t)bh * DH * SEQ };

    auto load_stage = [&](int kt, int s) {
        uint32_t base = sb + s * VSTAGE;
#pragma unroll
        for (int i = 0; i < 4; i++) {
            int idx = tid + i * 256;
            int hl = idx >> 9;
            int row = (idx >> 2) & 127;
            int u = idx & 3;
            const __nv_bfloat16* g = pa[hl] + (size_t)row * SEQ + kt * 32 + u * 8;
            uint32_t d = base + hl * 8192 + row * 64 + ((u ^ (row & 3)) * 16);
            CP_ASYNC16(d, g);
        }
#pragma unroll
        for (int i = 0; i < 2; i++) {
            int idx = tid + i * 256;
            int hl = idx >> 8;
            int row = (idx >> 2) & 63;
            int u = idx & 3;
            const __nv_bfloat16* g = pb[hl] + (size_t)row * SEQ + kt * 32 + u * 8;
            uint32_t d = base + 16384 + hl * 4096 + row * 64 + ((u ^ (row & 3)) * 16);
            CP_ASYNC16(d, g);
        }
        CP_COMMIT();
    };

    float acc[2][4][4];
#pragma unroll
    for (int a = 0; a < 2; a++)
#pragma unroll
        for (int b = 0; b < 4; b++)
#pragma unroll
            for (int c = 0; c < 4; c++) acc[a][b][c] = 0.0f;

    int arow = (lane & 7) | (((lane >> 3) & 1) << 3);
    int asel = lane >> 4;
    int brow = (lane & 7) | ((lane >> 4) << 3);
    int bsel = (lane >> 3) & 1;

    load_stage(0, 0);
    load_stage(1, 1);

#pragma unroll 1
    for (int t = 0; t < 32; t++) {
        if (t >= 31) { CP_WAIT0(); } else { CP_WAIT1(); }
        __syncthreads();

        uint32_t base = sb + (t & 1) * VSTAGE;
        uint32_t Ahb = base, Alb = base + 8192, Bhb = base + 16384, Blb = base + 20480;

#pragma unroll
        for (int ks = 0; ks < 2; ks++) {
            int akc = ks * 2 + asel;
            int bkc = ks * 2 + bsel;
            uint32_t ah[2][4], al[2][4], bh4[2][4], bl4[2][4];
#pragma unroll
            for (int mt = 0; mt < 2; mt++) {
                int row = wm * 32 + mt * 16 + arow;
                uint32_t off = row * 64 + ((akc ^ (row & 3)) * 16);
                LDSM4(ah[mt][0], ah[mt][1], ah[mt][2], ah[mt][3], Ahb + off);
                LDSM4(al[mt][0], al[mt][1], al[mt][2], al[mt][3], Alb + off);
            }
#pragma unroll
            for (int nt = 0; nt < 2; nt++) {
                int row = wn * 32 + nt * 16 + brow;
                uint32_t off = row * 64 + ((bkc ^ (row & 3)) * 16);
                LDSM4(bh4[nt][0], bh4[nt][1], bh4[nt][2], bh4[nt][3], Bhb + off);
                LDSM4(bl4[nt][0], bl4[nt][1], bl4[nt][2], bl4[nt][3], Blb + off);
            }
#pragma unroll
            for (int mt = 0; mt < 2; mt++)
#pragma unroll
                for (int nt = 0; nt < 2; nt++) {
                    MMA16816(acc[mt][nt * 2 + 0], ah[mt], bh4[nt][0], bh4[nt][1]);
                    MMA16816(acc[mt][nt * 2 + 1], ah[mt], bh4[nt][2], bh4[nt][3]);
                    MMA16816(acc[mt][nt * 2 + 0], ah[mt], bl4[nt][0], bl4[nt][1]);
                    MMA16816(acc[mt][nt * 2 + 1], ah[mt], bl4[nt][2], bl4[nt][3]);
                    MMA16816(acc[mt][nt * 2 + 0], al[mt], bh4[nt][0], bh4[nt][1]);
                    MMA16816(acc[mt][nt * 2 + 1], al[mt], bh4[nt][2], bh4[nt][3]);
                }
        }
        __syncthreads();
        if (t + 2 < 32) load_stage(t + 2, t & 1);
    }

    // epilogue: write ctx split [tok][1024]
    int r = lane >> 2, c2 = (lane & 3) * 2;
    int bidx = bh >> 4, h = bh & 15;
#pragma unroll
    for (int mt = 0; mt < 2; mt++) {
        int mrow = m0 + wm * 32 + mt * 16 + r;
        size_t tok0 = (size_t)(bidx * SEQ + mrow) * CH;
        size_t tok1 = (size_t)(bidx * SEQ + mrow + 8) * CH;
#pragma unroll
        for (int nt8 = 0; nt8 < 4; nt8++) {
            int col = h * DH + wn * 32 + nt8 * 8 + c2;
            __nv_bfloat16 h0, l0, h1, l1;
            split1(acc[mt][nt8][0], h0, l0); split1(acc[mt][nt8][1], h1, l1);
            *(__nv_bfloat162*)(chi + tok0 + col) = {h0, h1};
            *(__nv_bfloat162*)(clo + tok0 + col) = {l0, l1};
            split1(acc[mt][nt8][2], h0, l0); split1(acc[mt][nt8][3], h1, l1);
            *(__nv_bfloat162*)(chi + tok1 + col) = {h0, h1};
            *(__nv_bfloat162*)(clo + tok1 + col) = {l0, l1};
        }
    }
}

// ---------------------------------------------------------------------------
extern "C" void kernel_launch(void* const* d_in, const int* in_sizes, int n_in,
                              void* d_out, int out_size)
{
    const float* x  = (const float*)d_in[0];
    const float* Wq = (const float*)d_in[1];
    const float* bq = (const float*)d_in[2];
    const float* Wk = (const float*)d_in[3];
    const float* bk = (const float*)d_in[4];
    const float* Wv = (const float*)d_in[5];
    const float* bv = (const float*)d_in[6];
    const float* Wo = (const float*)d_in[7];
    const float* bo = (const float*)d_in[8];

    float* out_ptr  = (float*)d_out;
    float* attn_ptr = out_ptr + OUT_ELEMS;

    __nv_bfloat16 *p_xhi, *p_xlo, *p_wthi, *p_wtlo;
    __nv_bfloat16 *p_qhi, *p_qlo, *p_khi, *p_klo, *p_vthi, *p_vtlo;
    __nv_bfloat16 *p_phi, *p_plo, *p_chi, *p_clo;
    cudaGetSymbolAddress((void**)&p_xhi, g_xhi);
    cudaGetSymbolAddress((void**)&p_xlo, g_xlo);
    cudaGetSymbolAddress((void**)&p_wthi, g_wthi);
    cudaGetSymbolAddress((void**)&p_wtlo, g_wtlo);
    cudaGetSymbolAddress((void**)&p_qhi, g_qhi);
    cudaGetSymbolAddress((void**)&p_qlo, g_qlo);
    cudaGetSymbolAddress((void**)&p_khi, g_khi);
    cudaGetSymbolAddress((void**)&p_klo, g_klo);
    cudaGetSymbolAddress((void**)&p_vthi, g_vthi);
    cudaGetSymbolAddress((void**)&p_vtlo, g_vtlo);
    cudaGetSymbolAddress((void**)&p_phi, g_phi);
    cudaGetSymbolAddress((void**)&p_plo, g_plo);
    cudaGetSymbolAddress((void**)&p_chi, g_chi);
    cudaGetSymbolAddress((void**)&p_clo, g_clo);

    cudaFuncSetAttribute(gemm_mma, cudaFuncAttributeMaxDynamicSharedMemorySize, GSMEM);
    cudaFuncSetAttribute(attn_entmax_mma, cudaFuncAttributeMaxDynamicSharedMemorySize, ESMEM);
    cudaFuncSetAttribute(gemm_av_mma, cudaFuncAttributeMaxDynamicSharedMemorySize, VSMEM);

    // converts
    split_convert<<<OUT_ELEMS / 4 / 256, 256>>>(x, p_xhi, p_xlo, OUT_ELEMS / 4);
    dim3 wt(32, 32), wb(32, 8);
    wtrans_convert<<<wt, wb>>>(Wq, p_wthi + 0 * 1048576, p_wtlo + 0 * 1048576);
    wtrans_convert<<<wt, wb>>>(Wk, p_wthi + 1 * 1048576, p_wtlo + 1 * 1048576);
    wtrans_convert<<<wt, wb>>>(Wv, p_wthi + 2 * 1048576, p_wtlo + 2 * 1048576);
    wtrans_convert<<<wt, wb>>>(Wo, p_wthi + 3 * 1048576, p_wtlo + 3 * 1048576);

    // QKV projections on tensor cores
    dim3 gg(8, 32);
    gemm_mma<<<gg, 256, GSMEM>>>(p_xhi, p_xlo, p_wthi + 0 * 1048576, p_wtlo + 0 * 1048576,
                                 bq, nullptr, p_qhi, p_qlo, 0);
    gemm_mma<<<gg, 256, GSMEM>>>(p_xhi, p_xlo, p_wthi + 1 * 1048576, p_wtlo + 1 * 1048576,
                                 bk, nullptr, p_khi, p_klo, 0);
    gemm_mma<<<gg, 256, GSMEM>>>(p_xhi, p_xlo, p_wthi + 2 * 1048576, p_wtlo + 2 * 1048576,
                                 bv, nullptr, p_vthi, p_vtlo, 1);

    // scores + entmax
    dim3 ge(32, BH);
    attn_entmax_mma<<<ge, 512, ESMEM>>>(attn_ptr, p_qhi, p_qlo, p_khi, p_klo, p_phi, p_plo);

    // attn @ V
    dim3 ga(8, BH);
    gemm_av_mma<<<ga, 256, VSMEM>>>(p_phi, p_plo, p_vthi, p_vtlo, p_chi, p_clo);

    // output projection
    gemm_mma<<<gg, 256, GSMEM>>>(p_chi, p_clo, p_wthi + 3 * 1048576, p_wtlo + 3 * 1048576,
                                 bo, out_ptr, nullptr, nullptr, 2);
}

// round 11
// speedup vs baseline: 1.0410x; 1.0168x over previous
#include <cuda_runtime.h>
#include <cuda_bf16.h>
#include <cstdint>

#define BATCH 4
#define SEQ   1024
#define CH    1024
#define HEADS 16
#define DH    64
#define TOKENS (BATCH * SEQ)
#define BH (BATCH * HEADS)
#define OUT_ELEMS (TOKENS * CH)

#define BISECT_ITERS 12
#define SOLVE_ITERS 3
#define SCALE 0.0625f   // (1/sqrt(64)) * (alpha-1)

// bf16 split scratch
__device__ __nv_bfloat16 g_xhi[TOKENS * CH];
__device__ __nv_bfloat16 g_xlo[TOKENS * CH];
__device__ __nv_bfloat16 g_wthi[4 * CH * CH];
__device__ __nv_bfloat16 g_wtlo[4 * CH * CH];
__device__ __nv_bfloat16 g_qhi[BH * SEQ * DH];
__device__ __nv_bfloat16 g_qlo[BH * SEQ * DH];
__device__ __nv_bfloat16 g_khi[BH * SEQ * DH];
__device__ __nv_bfloat16 g_klo[BH * SEQ * DH];
__device__ __nv_bfloat16 g_vthi[BH * DH * SEQ];   // transposed V: [bh][dh][tok]
__device__ __nv_bfloat16 g_vtlo[BH * DH * SEQ];
__device__ __nv_bfloat16 g_phi[(size_t)BH * SEQ * SEQ];  // attn split
__device__ __nv_bfloat16 g_plo[(size_t)BH * SEQ * SEQ];
__device__ __nv_bfloat16 g_chi[TOKENS * CH];
__device__ __nv_bfloat16 g_clo[TOKENS * CH];

// ===================== PTX helpers =========================================
__device__ __forceinline__ uint32_t smem_u32(const void* p) {
    uint32_t a;
    asm("{ .reg .u64 t; cvta.to.shared.u64 t, %1; cvt.u32.u64 %0, t; }" : "=r"(a) : "l"(p));
    return a;
}
#define CP_ASYNC16(sa, g) \
    asm volatile("cp.async.cg.shared.global [%0], [%1], 16;" :: "r"(sa), "l"(g))
#define CP_COMMIT() asm volatile("cp.async.commit_group;" ::: "memory")
#define CP_WAIT0() asm volatile("cp.async.wait_group 0;" ::: "memory")
#define CP_WAIT1() asm volatile("cp.async.wait_group 1;" ::: "memory")
#define LDSM4(r0, r1, r2, r3, addr) \
    asm volatile("ldmatrix.sync.aligned.m8n8.x4.shared.b16 {%0,%1,%2,%3}, [%4];" \
        : "=r"(r0), "=r"(r1), "=r"(r2), "=r"(r3) : "r"(addr))
#define MMA16816(d, a, b0, b1) \
    asm volatile("mma.sync.aligned.m16n8k16.row.col.f32.bf16.bf16.f32 " \
        "{%0,%1,%2,%3}, {%4,%5,%6,%7}, {%8,%9}, {%0,%1,%2,%3};" \
        : "+f"((d)[0]), "+f"((d)[1]), "+f"((d)[2]), "+f"((d)[3]) \
        : "r"((a)[0]), "r"((a)[1]), "r"((a)[2]), "r"((a)[3]), "r"(b0), "r"(b1))

__device__ __forceinline__ void split1(float v, __nv_bfloat16& h, __nv_bfloat16& l) {
    h = __float2bfloat16_rn(v);
    l = __float2bfloat16_rn(v - __bfloat162float(h));
}
__device__ __forceinline__ float sum8(const float* base, int row) {
    float4 a = ((const float4*)base)[row * 2];
    float4 b = ((const float4*)base)[row * 2 + 1];
    return ((a.x + a.y) + (a.z + a.w)) + ((b.x + b.y) + (b.z + b.w));
}
__device__ __forceinline__ float max8(const float* base, int row) {
    float4 a = ((const float4*)base)[row * 2];
    float4 b = ((const float4*)base)[row * 2 + 1];
    return fmaxf(fmaxf(fmaxf(a.x, a.y), fmaxf(a.z, a.w)),
                 fmaxf(fmaxf(b.x, b.y), fmaxf(b.z, b.w)));
}

// ===================== convert kernels =====================================
__global__ __launch_bounds__(256) void split_convert(
    const float* __restrict__ in, __nv_bfloat16* __restrict__ hi,
    __nv_bfloat16* __restrict__ lo, int n4)
{
    int i = blockIdx.x * 256 + threadIdx.x;
    if (i >= n4) return;
    float4 v = ((const float4*)in)[i];
    union { ushort u[4]; uint2 q; } H, L;
    float a[4] = {v.x, v.y, v.z, v.w};
#pragma unroll
    for (int j = 0; j < 4; j++) {
        __nv_bfloat16 h, l; split1(a[j], h, l);
        H.u[j] = __bfloat16_as_ushort(h);
        L.u[j] = __bfloat16_as_ushort(l);
    }
    ((uint2*)hi)[i] = H.q;
    ((uint2*)lo)[i] = L.q;
}

// all 4 weights in one launch: blockIdx.z selects the matrix
__global__ __launch_bounds__(256) void wtrans_convert4(
    const float* __restrict__ W0, const float* __restrict__ W1,
    const float* __restrict__ W2, const float* __restrict__ W3)
{
    __shared__ float t[32][33];
    int tx = threadIdx.x, ty = threadIdx.y;
    int bx = blockIdx.x, by = blockIdx.y, bz = blockIdx.z;
    const float* W = (bz == 0) ? W0 : (bz == 1) ? W1 : (bz == 2) ? W2 : W3;
    __nv_bfloat16* hi = g_wthi + (size_t)bz * 1048576;
    __nv_bfloat16* lo = g_wtlo + (size_t)bz * 1048576;
#pragma unroll
    for (int i = 0; i < 4; i++)
        t[ty + i * 8][tx] = W[(size_t)(by * 32 + ty + i * 8) * 1024 + bx * 32 + tx];
    __syncthreads();
#pragma unroll
    for (int i = 0; i < 4; i++) {
        float v = t[tx][ty + i * 8];
        __nv_bfloat16 h, l; split1(v, h, l);
        size_t o = (size_t)(bx * 32 + ty + i * 8) * 1024 + by * 32 + tx;
        hi[o] = h;
        lo[o] = l;
    }
}

// ===================== GEMM core (shared by QKV-fused and plain) ===========
#define GSTAGE 32768
#define GSMEM (2 * GSTAGE)

// inner mainloop shared via inline function
__device__ __forceinline__ void gemm_mainloop(
    uint32_t sb, int tid, int wm, int wn,
    const __nv_bfloat16* Ah, const __nv_bfloat16* Al,
    const __nv_bfloat16* Bh, const __nv_bfloat16* Bl,
    float acc[4][4][4])
{
    int lane = tid & 31;
    const __nv_bfloat16* gsrc[4] = { Ah, Al, Bh, Bl };
    int l_row0 = tid >> 2,         l_c0 = tid & 3;
    int l_row1 = (tid + 256) >> 2, l_c1 = (tid + 256) & 3;

    auto load_stage = [&](int kt, int s) {
        uint32_t sbase = sb + s * GSTAGE;
#pragma unroll
        for (int t = 0; t < 4; t++) {
            const char* g0 = (const char*)(gsrc[t] + (size_t)l_row0 * 1024 + kt * 32) + l_c0 * 16;
            const char* g1 = (const char*)(gsrc[t] + (size_t)l_row1 * 1024 + kt * 32) + l_c1 * 16;
            uint32_t s0 = sbase + t * 8192 + l_row0 * 64 + ((l_c0 ^ (l_row0 & 3)) * 16);
            uint32_t s1 = sbase + t * 8192 + l_row1 * 64 + ((l_c1 ^ (l_row1 & 3)) * 16);
            CP_ASYNC16(s0, g0);
            CP_ASYNC16(s1, g1);
        }
        CP_COMMIT();
    };

    int arow = (lane & 7) | (((lane >> 3) & 1) << 3);
    int asel = lane >> 4;
    int brow = (lane & 7) | ((lane >> 4) << 3);
    int bsel = (lane >> 3) & 1;

    load_stage(0, 0);
    load_stage(1, 1);

#pragma unroll 1
    for (int t = 0; t < 32; t++) {
        if (t >= 31) { CP_WAIT0(); } else { CP_WAIT1(); }
        __syncthreads();

        uint32_t base = sb + (t & 1) * GSTAGE;
        uint32_t Ahb = base, Alb = base + 8192, Bhb = base + 16384, Blb = base + 24576;

#pragma unroll
        for (int ks = 0; ks < 2; ks++) {
            int akc = ks * 2 + asel;
            int bkc = ks * 2 + bsel;
            uint32_t ah[4][4], al[4][4], bhf[2][4], blf[2][4];
#pragma unroll
            for (int mt = 0; mt < 4; mt++) {
                int row = wm * 64 + mt * 16 + arow;
                uint32_t off = row * 64 + ((akc ^ (row & 3)) * 16);
                LDSM4(ah[mt][0], ah[mt][1], ah[mt][2], ah[mt][3], Ahb + off);
            }
#pragma unroll
            for (int nt = 0; nt < 2; nt++) {
                int row = wn * 32 + nt * 16 + brow;
                uint32_t off = row * 64 + ((bkc ^ (row & 3)) * 16);
                LDSM4(bhf[nt][0], bhf[nt][1], bhf[nt][2], bhf[nt][3], Bhb + off);
            }
#pragma unroll
            for (int mt = 0; mt < 4; mt++)
#pragma unroll
                for (int nt = 0; nt < 2; nt++) {
                    MMA16816(acc[mt][nt * 2 + 0], ah[mt], bhf[nt][0], bhf[nt][1]);
                    MMA16816(acc[mt][nt * 2 + 1], ah[mt], bhf[nt][2], bhf[nt][3]);
                }
#pragma unroll
            for (int nt = 0; nt < 2; nt++) {
                int row = wn * 32 + nt * 16 + brow;
                uint32_t off = row * 64 + ((bkc ^ (row & 3)) * 16);
                LDSM4(blf[nt][0], blf[nt][1], blf[nt][2], blf[nt][3], Blb + off);
            }
#pragma unroll
            for (int mt = 0; mt < 4; mt++)
#pragma unroll
                for (int nt = 0; nt < 2; nt++) {
                    MMA16816(acc[mt][nt * 2 + 0], ah[mt], blf[nt][0], blf[nt][1]);
                    MMA16816(acc[mt][nt * 2 + 1], ah[mt], blf[nt][2], blf[nt][3]);
                }
#pragma unroll
            for (int mt = 0; mt < 4; mt++) {
                int row = wm * 64 + mt * 16 + arow;
                uint32_t off = row * 64 + ((akc ^ (row & 3)) * 16);
                LDSM4(al[mt][0], al[mt][1], al[mt][2], al[mt][3], Alb + off);
            }
#pragma unroll
            for (int mt = 0; mt < 4; mt++)
#pragma unroll
                for (int nt = 0; nt < 2; nt++) {
                    MMA16816(acc[mt][nt * 2 + 0], al[mt], bhf[nt][0], bhf[nt][1]);
                    MMA16816(acc[mt][nt * 2 + 1], al[mt], bhf[nt][2], bhf[nt][3]);
                }
        }
        __syncthreads();
        if (t + 2 < 32) load_stage(t + 2, t & 1);
    }
}

// Fused QKV projection: grid (24, 32). bx 0-7 -> Q, 8-15 -> K, 16-23 -> V.
__global__ __launch_bounds__(256, 2) void gemm_qkv(
    const float* __restrict__ bq, const float* __restrict__ bk,
    const float* __restrict__ bv)
{
    extern __shared__ char sm[];
    uint32_t sb = smem_u32(sm);
    int tid = threadIdx.x, lane = tid & 31, wid = tid >> 5;
    int wm = wid >> 2, wn = wid & 3;
    int widx = blockIdx.x >> 3;
    int n0 = (blockIdx.x & 7) * 128;
    int m0 = blockIdx.y * 128;

    const float* bias = (widx == 0) ? bq : (widx == 1) ? bk : bv;
    const __nv_bfloat16* Bh = g_wthi + (size_t)widx * 1048576 + (size_t)n0 * 1024;
    const __nv_bfloat16* Bl = g_wtlo + (size_t)widx * 1048576 + (size_t)n0 * 1024;

    float acc[4][4][4];
#pragma unroll
    for (int a = 0; a < 4; a++)
#pragma unroll
        for (int b = 0; b < 4; b++)
#pragma unroll
            for (int c = 0; c < 4; c++) acc[a][b][c] = 0.0f;

    gemm_mainloop(sb, tid, wm, wn,
                  g_xhi + (size_t)m0 * 1024, g_xlo + (size_t)m0 * 1024, Bh, Bl, acc);

    // epilogue
    int r = lane >> 2, c2 = (lane & 3) * 2;
    __nv_bfloat16* dhi = (widx == 0) ? g_qhi : (widx == 1) ? g_khi : g_vthi;
    __nv_bfloat16* dlo = (widx == 0) ? g_qlo : (widx == 1) ? g_klo : g_vtlo;
#pragma unroll
    for (int mt = 0; mt < 4; mt++) {
        int mrow = m0 + wm * 64 + mt * 16 + r;
        int bidx = mrow >> 10, ntok = mrow & 1023;
#pragma unroll
        for (int nt8 = 0; nt8 < 4; nt8++) {
            int col = n0 + wn * 32 + nt8 * 8 + c2;
            float b0 = bias[col], b1 = bias[col + 1];
            float v00 = acc[mt][nt8][0] + b0, v01 = acc[mt][nt8][1] + b1;
            float v10 = acc[mt][nt8][2] + b0, v11 = acc[mt][nt8][3] + b1;
            int h = col >> 6, dh = col & 63;
            if (widx < 2) {
                size_t base = ((size_t)(bidx * HEADS + h) * SEQ + ntok) * DH + dh;
                __nv_bfloat16 h0, l0, h1, l1;
                split1(v00, h0, l0); split1(v01, h1, l1);
                *(__nv_bfloat162*)(dhi + base) = {h0, h1};
                *(__nv_bfloat162*)(dlo + base) = {l0, l1};
                split1(v10, h0, l0); split1(v11, h1, l1);
                *(__nv_bfloat162*)(dhi + base + 8 * DH) = {h0, h1};
                *(__nv_bfloat162*)(dlo + base + 8 * DH) = {l0, l1};
            } else {
                size_t vb = ((size_t)(bidx * HEADS + h) * DH + dh) * SEQ + ntok;
                __nv_bfloat16 hh, ll;
                split1(v00, hh, ll); dhi[vb] = hh; dlo[vb] = ll;
                split1(v01, hh, ll); dhi[vb + SEQ] = hh; dlo[vb + SEQ] = ll;
                split1(v10, hh, ll); dhi[vb + 8] = hh; dlo[vb + 8] = ll;
                split1(v11, hh, ll); dhi[vb + SEQ + 8] = hh; dlo[vb + SEQ + 8] = ll;
            }
        }
    }
}

// Output projection: ctx_split @ Wo^T + bo -> fp32 out
__global__ __launch_bounds__(256, 2) void gemm_out(
    const float* __restrict__ bias, float* __restrict__ dstf)
{
    extern __shared__ char sm[];
    uint32_t sb = smem_u32(sm);
    int tid = threadIdx.x, lane = tid & 31, wid = tid >> 5;
    int wm = wid >> 2, wn = wid & 3;
    int n0 = blockIdx.x * 128, m0 = blockIdx.y * 128;

    float acc[4][4][4];
#pragma unroll
    for (int a = 0; a < 4; a++)
#pragma unroll
        for (int b = 0; b < 4; b++)
#pragma unroll
            for (int c = 0; c < 4; c++) acc[a][b][c] = 0.0f;

    gemm_mainloop(sb, tid, wm, wn,
                  g_chi + (size_t)m0 * 1024, g_clo + (size_t)m0 * 1024,
                  g_wthi + 3u * 1048576 + (size_t)n0 * 1024,
                  g_wtlo + 3u * 1048576 + (size_t)n0 * 1024, acc);

    int r = lane >> 2, c2 = (lane & 3) * 2;
#pragma unroll
    for (int mt = 0; mt < 4; mt++) {
        int mrow = m0 + wm * 64 + mt * 16 + r;
#pragma unroll
        for (int nt8 = 0; nt8 < 4; nt8++) {
            int col = n0 + wn * 32 + nt8 * 8 + c2;
            float b0 = bias[col], b1 = bias[col + 1];
            float* p = dstf + (size_t)mrow * CH + col;
            *(float2*)p = {acc[mt][nt8][0] + b0, acc[mt][nt8][1] + b1};
            *(float2*)(p + 8 * CH) = {acc[mt][nt8][2] + b0, acc[mt][nt8][3] + b1};
        }
    }
}

// ===================== fused HMMA scores + entmax ==========================
#define EOFF_QH 0
#define EOFF_QL 4096
#define EOFF_K  8192
#define EOFF_RED 73728
#define ESMEM (73728 + 6144)

__global__ __launch_bounds__(512) void attn_entmax_mma(
    float* __restrict__ attn,
    __nv_bfloat16* __restrict__ phi, __nv_bfloat16* __restrict__ plo)
{
    extern __shared__ char sm[];
    uint32_t sb = smem_u32(sm);
    float* RED = (float*)(sm + EOFF_RED);   // [2][768]

    int tid = threadIdx.x, lane = tid & 31, wid = tid >> 5;
    int wrow = wid >> 3, wcol = wid & 7;
    int bh = blockIdx.y;
    int R0 = blockIdx.x * 32;

    {   // Q: 512 chunks, 1/thread
        int hl = tid >> 8;
        int row = (tid >> 3) & 31;
        int u = tid & 7;
        const __nv_bfloat16* src = (hl ? g_qlo : g_qhi) + ((size_t)bh * SEQ + R0 + row) * DH + u * 8;
        uint32_t d = sb + EOFF_QH + hl * 4096 + row * 128 + ((u ^ (row & 7)) * 16);
        CP_ASYNC16(d, src);
    }
    auto loadK = [&](int c, int s) {
        uint32_t base = sb + EOFF_K + s * 32768;
#pragma unroll
        for (int i = 0; i < 4; i++) {
            int idx = tid + i * 512;
            int hl = idx >> 10;
            int row = (idx >> 3) & 127;
            int u = idx & 7;
            const __nv_bfloat16* src = (hl ? g_klo : g_khi) + ((size_t)bh * SEQ + c * 128 + row) * DH + u * 8;
            uint32_t d = base + hl * 16384 + row * 128 + ((u ^ (row & 7)) * 16);
            CP_ASYNC16(d, src);
        }
        CP_COMMIT();
    };
    loadK(0, 0);
    loadK(1, 1);

    float acc[16][4];
#pragma unroll
    for (int t = 0; t < 16; t++)
#pragma unroll
        for (int e = 0; e < 4; e++) acc[t][e] = 0.0f;

    int arow_ = wrow * 16 + ((lane & 7) | (((lane >> 3) & 1) << 3));
    int asel = lane >> 4;
    int brow_ = (lane & 7) | ((lane >> 4) << 3);
    int bsel = (lane >> 3) & 1;

#pragma unroll 1
    for (int c = 0; c < 8; c++) {
        if (c >= 7) { CP_WAIT0(); } else { CP_WAIT1(); }
        __syncthreads();
        if (wcol == c) {
            uint32_t KHb = sb + EOFF_K + (c & 1) * 32768;
            uint32_t KLb = KHb + 16384;
            uint32_t QHb = sb + EOFF_QH, QLb = sb + EOFF_QL;
#pragma unroll
            for (int kc = 0; kc < 4; kc++) {
                uint32_t au = (uint32_t)(kc * 2 + asel);
                uint32_t aoff = arow_ * 128 + ((au ^ (arow_ & 7)) * 16);
                uint32_t ah[4], al[4];
                LDSM4(ah[0], ah[1], ah[2], ah[3], QHb + aoff);
                LDSM4(al[0], al[1], al[2], al[3], QLb + aoff);
#pragma unroll
                for (int nt = 0; nt < 8; nt++) {
                    int krow = nt * 16 + brow_;
                    uint32_t bu = (uint32_t)(kc * 2 + bsel);
                    uint32_t boff = krow * 128 + ((bu ^ (krow & 7)) * 16);
                    uint32_t bh4[4], bl4[4];
                    LDSM4(bh4[0], bh4[1], bh4[2], bh4[3], KHb + boff);
                    LDSM4(bl4[0], bl4[1], bl4[2], bl4[3], KLb + boff);
                    MMA16816(acc[nt * 2 + 0], ah, bh4[0], bh4[1]);
                    MMA16816(acc[nt * 2 + 1], ah, bh4[2], bh4[3]);
                    MMA16816(acc[nt * 2 + 0], ah, bl4[0], bl4[1]);
                    MMA16816(acc[nt * 2 + 1], ah, bl4[2], bl4[3]);
                    MMA16816(acc[nt * 2 + 0], al, bh4[0], bh4[1]);
                    MMA16816(acc[nt * 2 + 1], al, bh4[2], bh4[3]);
                    MMA16816(acc[nt * 2 + 0], al, bl4[0], bl4[1]);
                    MMA16816(acc[nt * 2 + 1], al, bl4[2], bl4[3]);
                }
            }
        }
        __syncthreads();
        if (c + 2 < 8) loadK(c + 2, c & 1);
    }

    // --- entmax in HMMA layout, redundant all-thread reductions ---
    int r0 = wrow * 16 + (lane >> 2);
    int r1 = r0 + 8;
    bool qlead = (lane & 3) == 0;
    int par = 0;

#pragma unroll
    for (int t = 0; t < 16; t++)
#pragma unroll
        for (int e = 0; e < 4; e++) acc[t][e] *= SCALE;

    // Phase A: row max
    float tloA, tloB;
    {
        float mA = -1e30f, mB = -1e30f;
#pragma unroll
        for (int t = 0; t < 16; t++) {
            mA = fmaxf(mA, fmaxf(acc[t][0], acc[t][1]));
            mB = fmaxf(mB, fmaxf(acc[t][2], acc[t][3]));
        }
        mA = fmaxf(mA, __shfl_xor_sync(0xffffffffu, mA, 1));
        mA = fmaxf(mA, __shfl_xor_sync(0xffffffffu, mA, 2));
        mB = fmaxf(mB, __shfl_xor_sync(0xffffffffu, mB, 1));
        mB = fmaxf(mB, __shfl_xor_sync(0xffffffffu, mB, 2));
        float* RP = RED + par * 768;
        if (qlead) { RP[r0 * 8 + wcol] = mA; RP[r1 * 8 + wcol] = mB; }
        __syncthreads();
        tloA = max8(RP, r0) - 1.0f;
        tloB = max8(RP, r1) - 1.0f;
        par ^= 1;
    }

    // Phase B: f_lo
    float flA, flB;
    {
        float c0 = 0.f, c1 = 0.f, c2 = 0.f, c3 = 0.f;
#pragma unroll
        for (int t = 0; t < 16; t++) {
            float u;
            u = fmaxf(acc[t][0] - tloA, 0.f); c0 = fmaf(u, u, c0);
            u = fmaxf(acc[t][1] - tloA, 0.f); c1 = fmaf(u, u, c1);
            u = fmaxf(acc[t][2] - tloB, 0.f); c2 = fmaf(u, u, c2);
            u = fmaxf(acc[t][3] - tloB, 0.f); c3 = fmaf(u, u, c3);
        }
        float vA = c0 + c1, vB = c2 + c3;
        vA += __shfl_xor_sync(0xffffffffu, vA, 1);
        vA += __shfl_xor_sync(0xffffffffu, vA, 2);
        vB += __shfl_xor_sync(0xffffffffu, vB, 1);
        vB += __shfl_xor_sync(0xffffffffu, vB, 2);
        float* RP = RED + par * 768;
        if (qlead) { RP[r0 * 8 + wcol] = vA; RP[r1 * 8 + wcol] = vB; }
        __syncthreads();
        flA = sum8(RP, r0) - 1.0f;
        flB = sum8(RP, r1) - 1.0f;
        par ^= 1;
    }

    float dm = 0.484375f;
    float tmA = tloA + dm, tmB = tloB + dm;

    // Phase C: bisection
#pragma unroll 1
    for (int it = 0; it < BISECT_ITERS; it++) {
        float c0 = 0.f, c1 = 0.f, c2 = 0.f, c3 = 0.f;
#pragma unroll
        for (int t = 0; t < 16; t++) {
            float u;
            u = fmaxf(acc[t][0] - tmA, 0.f); c0 = fmaf(u, u, c0);
            u = fmaxf(acc[t][1] - tmA, 0.f); c1 = fmaf(u, u, c1);
            u = fmaxf(acc[t][2] - tmB, 0.f); c2 = fmaf(u, u, c2);
            u = fmaxf(acc[t][3] - tmB, 0.f); c3 = fmaf(u, u, c3);
        }
        float vA = c0 + c1, vB = c2 + c3;
        vA += __shfl_xor_sync(0xffffffffu, vA, 1);
        vA += __shfl_xor_sync(0xffffffffu, vA, 2);
        vB += __shfl_xor_sync(0xffffffffu, vB, 1);
        vB += __shfl_xor_sync(0xffffffffu, vB, 2);
        float* RP = RED + par * 768;
        if (qlead) { RP[r0 * 8 + wcol] = vA; RP[r1 * 8 + wcol] = vB; }
        __syncthreads();
        float fmA = sum8(RP, r0) - 1.0f;
        float fmB = sum8(RP, r1) - 1.0f;
        if (fmA * flA >= 0.f) tloA = tmA;
        if (fmB * flB >= 0.f) tloB = tmB;
        if (it < BISECT_ITERS - 1) {
            dm *= 0.5f;
            tmA = tloA + dm;
            tmB = tloB + dm;
        }
        par ^= 1;
    }

    // Phase D: analytic support-fixpoint solves
#pragma unroll 1
    for (int ps = 0; ps < SOLVE_ITERS; ps++) {
        float nA = 0.f, s1A = 0.f, s2A = 0.f;
        float nB = 0.f, s1B = 0.f, s2B = 0.f;
#pragma unroll
        for (int t = 0; t < 16; t++) {
#pragma unroll
            for (int e = 0; e < 2; e++) {
                float a = acc[t][e];
                if (a > tmA) { nA += 1.f; s1A += a; s2A = fmaf(a, a, s2A); }
                float b = acc[t][e + 2];
                if (b > tmB) { nB += 1.f; s1B += b; s2B = fmaf(b, b, s2B); }
            }
        }
#pragma unroll
        for (int o = 1; o <= 2; o <<= 1) {
            nA += __shfl_xor_sync(0xffffffffu, nA, o);
            s1A += __shfl_xor_sync(0xffffffffu, s1A, o);
            s2A += __shfl_xor_sync(0xffffffffu, s2A, o);
            nB += __shfl_xor_sync(0xffffffffu, nB, o);
            s1B += __shfl_xor_sync(0xffffffffu, s1B, o);
            s2B += __shfl_xor_sync(0xffffffffu, s2B, o);
        }
        float* RP = RED + par * 768;
        if (qlead) {
            RP[r0 * 8 + wcol] = nA;        RP[r1 * 8 + wcol] = nB;
            RP[256 + r0 * 8 + wcol] = s1A; RP[256 + r1 * 8 + wcol] = s1B;
            RP[512 + r0 * 8 + wcol] = s2A; RP[512 + r1 * 8 + wcol] = s2B;
        }
        __syncthreads();
        {
            float n = sum8(RP, r0), s1 = sum8(RP + 256, r0), s2 = sum8(RP + 512, r0);
            float D = fmaxf(fmaf(s1, s1, -n * (s2 - 1.0f)), 0.f);
            tmA = (s1 - sqrtf(D)) / n;
            n = sum8(RP, r1); s1 = sum8(RP + 256, r1); s2 = sum8(RP + 512, r1);
            D = fmaxf(fmaf(s1, s1, -n * (s2 - 1.0f)), 0.f);
            tmB = (s1 - sqrtf(D)) / n;
        }
        par ^= 1;
    }

    // Phase E: final p + normalize + write
    float ivA, ivB;
    {
        float c0 = 0.f, c1 = 0.f, c2 = 0.f, c3 = 0.f;
#pragma unroll
        for (int t = 0; t < 16; t++) {
            float u;
            u = fmaxf(acc[t][0] - tmA, 0.f); acc[t][0] = u * u; c0 += acc[t][0];
            u = fmaxf(acc[t][1] - tmA, 0.f); acc[t][1] = u * u; c1 += acc[t][1];
            u = fmaxf(acc[t][2] - tmB, 0.f); acc[t][2] = u * u; c2 += acc[t][2];
            u = fmaxf(acc[t][3] - tmB, 0.f); acc[t][3] = u * u; c3 += acc[t][3];
        }
        float vA = c0 + c1, vB = c2 + c3;
        vA += __shfl_xor_sync(0xffffffffu, vA, 1);
        vA += __shfl_xor_sync(0xffffffffu, vA, 2);
        vB += __shfl_xor_sync(0xffffffffu, vB, 1);
        vB += __shfl_xor_sync(0xffffffffu, vB, 2);
        float* RP = RED + par * 768;
        if (qlead) { RP[r0 * 8 + wcol] = vA; RP[r1 * 8 + wcol] = vB; }
        __syncthreads();
        ivA = 1.0f / sum8(RP, r0);
        ivB = 1.0f / sum8(RP, r1);
    }
    {
        size_t rb0 = ((size_t)bh * SEQ + R0 + r0) * SEQ + wcol * 128 + (lane & 3) * 2;
        size_t rb1 = ((size_t)bh * SEQ + R0 + r1) * SEQ + wcol * 128 + (lane & 3) * 2;
#pragma unroll
        for (int t = 0; t < 16; t++) {
            float p0 = acc[t][0] * ivA, p1 = acc[t][1] * ivA;
            float p2 = acc[t][2] * ivB, p3 = acc[t][3] * ivB;
            *(float2*)(attn + rb0 + t * 8) = {p0, p1};
            *(float2*)(attn + rb1 + t * 8) = {p2, p3};
            __nv_bfloat16 h0, l0, h1, l1;
            split1(p0, h0, l0); split1(p1, h1, l1);
            *(__nv_bfloat162*)(phi + rb0 + t * 8) = {h0, h1};
            *(__nv_bfloat162*)(plo + rb0 + t * 8) = {l0, l1};
            split1(p2, h0, l0); split1(p3, h1, l1);
            *(__nv_bfloat162*)(phi + rb1 + t * 8) = {h0, h1};
            *(__nv_bfloat162*)(plo + rb1 + t * 8) = {l0, l1};
        }
    }
}

// ===================== attn @ V via HMMA (split-bf16) ======================
#define VSTAGE 24576
#define VSMEM (2 * VSTAGE)

__global__ __launch_bounds__(256, 2) void gemm_av_mma(
    const __nv_bfloat16* __restrict__ Ph, const __nv_bfloat16* __restrict__ Pl)
{
    extern __shared__ char sm[];
    uint32_t sb = smem_u32(sm);
    int tid = threadIdx.x, lane = tid & 31, wid = tid >> 5;
    int wm = wid >> 1, wn = wid & 1;
    int m0 = blockIdx.x * 128;
    int bh = blockIdx.y;

    const __nv_bfloat16* pa[2] = { Ph + ((size_t)bh * SEQ + m0) * SEQ,
                                   Pl + ((size_t)bh * SEQ + m0) * SEQ };
    const __nv_bfloat16* pb[2] = { g_vthi + (size_t)bh * DH * SEQ,
                                   g_vtlo + (size_t)bh * DH * SEQ };

    auto load_stage = [&](int kt, int s) {
        uint32_t base = sb + s * VSTAGE;
#pragma unroll
        for (int i = 0; i < 4; i++) {
            int idx = tid + i * 256;
            int hl = idx >> 9;
            int row = (idx >> 2) & 127;
            int u = idx & 3;
            const __nv_bfloat16* g = pa[hl] + (size_t)row * SEQ + kt * 32 + u * 8;
            uint32_t d = base + hl * 8192 + row * 64 + ((u ^ (row & 3)) * 16);
            CP_ASYNC16(d, g);
        }
#pragma unroll
        for (int i = 0; i < 2; i++) {
            int idx = tid + i * 256;
            int hl = idx >> 8;
            int row = (idx >> 2) & 63;
            int u = idx & 3;
            const __nv_bfloat16* g = pb[hl] + (size_t)row * SEQ + kt * 32 + u * 8;
            uint32_t d = base + 16384 + hl * 4096 + row * 64 + ((u ^ (row & 3)) * 16);
            CP_ASYNC16(d, g);
        }
        CP_COMMIT();
    };

    float acc[2][4][4];
#pragma unroll
    for (int a = 0; a < 2; a++)
#pragma unroll
        for (int b = 0; b < 4; b++)
#pragma unroll
            for (int c = 0; c < 4; c++) acc[a][b][c] = 0.0f;

    int arow = (lane & 7) | (((lane >> 3) & 1) << 3);
    int asel = lane >> 4;
    int brow = (lane & 7) | ((lane >> 4) << 3);
    int bsel = (lane >> 3) & 1;

    load_stage(0, 0);
    load_stage(1, 1);

#pragma unroll 1
    for (int t = 0; t < 32; t++) {
        if (t >= 31) { CP_WAIT0(); } else { CP_WAIT1(); }
        __syncthreads();

        uint32_t base = sb + (t & 1) * VSTAGE;
        uint32_t Ahb = base, Alb = base + 8192, Bhb = base + 16384, Blb = base + 20480;

#pragma unroll
        for (int ks = 0; ks < 2; ks++) {
            int akc = ks * 2 + asel;
            int bkc = ks * 2 + bsel;
            uint32_t ah[2][4], al[2][4], bh4[2][4], bl4[2][4];
#pragma unroll
            for (int mt = 0; mt < 2; mt++) {
                int row = wm * 32 + mt * 16 + arow;
                uint32_t off = row * 64 + ((akc ^ (row & 3)) * 16);
                LDSM4(ah[mt][0], ah[mt][1], ah[mt][2], ah[mt][3], Ahb + off);
                LDSM4(al[mt][0], al[mt][1], al[mt][2], al[mt][3], Alb + off);
            }
#pragma unroll
            for (int nt = 0; nt < 2; nt++) {
                int row = wn * 32 + nt * 16 + brow;
                uint32_t off = row * 64 + ((bkc ^ (row & 3)) * 16);
                LDSM4(bh4[nt][0], bh4[nt][1], bh4[nt][2], bh4[nt][3], Bhb + off);
                LDSM4(bl4[nt][0], bl4[nt][1], bl4[nt][2], bl4[nt][3], Blb + off);
            }
#pragma unroll
            for (int mt = 0; mt < 2; mt++)
#pragma unroll
                for (int nt = 0; nt < 2; nt++) {
                    MMA16816(acc[mt][nt * 2 + 0], ah[mt], bh4[nt][0], bh4[nt][1]);
                    MMA16816(acc[mt][nt * 2 + 1], ah[mt], bh4[nt][2], bh4[nt][3]);
                    MMA16816(acc[mt][nt * 2 + 0], ah[mt], bl4[nt][0], bl4[nt][1]);
                    MMA16816(acc[mt][nt * 2 + 1], ah[mt], bl4[nt][2], bl4[nt][3]);
                    MMA16816(acc[mt][nt * 2 + 0], al[mt], bh4[nt][0], bh4[nt][1]);
                    MMA16816(acc[mt][nt * 2 + 1], al[mt], bh4[nt][2], bh4[nt][3]);
                }
        }
        __syncthreads();
        if (t + 2 < 32) load_stage(t + 2, t & 1);
    }

    // epilogue: write ctx split [tok][1024]
    int r = lane >> 2, c2 = (lane & 3) * 2;
    int bidx = bh >> 4, h = bh & 15;
#pragma unroll
    for (int mt = 0; mt < 2; mt++) {
        int mrow = m0 + wm * 32 + mt * 16 + r;
        size_t tok0 = (size_t)(bidx * SEQ + mrow) * CH;
        size_t tok1 = (size_t)(bidx * SEQ + mrow + 8) * CH;
#pragma unroll
        for (int nt8 = 0; nt8 < 4; nt8++) {
            int col = h * DH + wn * 32 + nt8 * 8 + c2;
            __nv_bfloat16 h0, l0, h1, l1;
            split1(acc[mt][nt8][0], h0, l0); split1(acc[mt][nt8][1], h1, l1);
            *(__nv_bfloat162*)(g_chi + tok0 + col) = {h0, h1};
            *(__nv_bfloat162*)(g_clo + tok0 + col) = {l0, l1};
            split1(acc[mt][nt8][2], h0, l0); split1(acc[mt][nt8][3], h1, l1);
            *(__nv_bfloat162*)(g_chi + tok1 + col) = {h0, h1};
            *(__nv_bfloat162*)(g_clo + tok1 + col) = {l0, l1};
        }
    }
}

// ---------------------------------------------------------------------------
extern "C" void kernel_launch(void* const* d_in, const int* in_sizes, int n_in,
                              void* d_out, int out_size)
{
    const float* x  = (const float*)d_in[0];
    const float* Wq = (const float*)d_in[1];
    const float* bq = (const float*)d_in[2];
    const float* Wk = (const float*)d_in[3];
    const float* bk = (const float*)d_in[4];
    const float* Wv = (const float*)d_in[5];
    const float* bv = (const float*)d_in[6];
    const float* Wo = (const float*)d_in[7];
    const float* bo = (const float*)d_in[8];

    float* out_ptr  = (float*)d_out;
    float* attn_ptr = out_ptr + OUT_ELEMS;

    __nv_bfloat16 *p_xhi, *p_xlo, *p_phi, *p_plo;
    cudaGetSymbolAddress((void**)&p_xhi, g_xhi);
    cudaGetSymbolAddress((void**)&p_xlo, g_xlo);
    cudaGetSymbolAddress((void**)&p_phi, g_phi);
    cudaGetSymbolAddress((void**)&p_plo, g_plo);

    cudaFuncSetAttribute(gemm_qkv, cudaFuncAttributeMaxDynamicSharedMemorySize, GSMEM);
    cudaFuncSetAttribute(gemm_out, cudaFuncAttributeMaxDynamicSharedMemorySize, GSMEM);
    cudaFuncSetAttribute(attn_entmax_mma, cudaFuncAttributeMaxDynamicSharedMemorySize, ESMEM);
    cudaFuncSetAttribute(gemm_av_mma, cudaFuncAttributeMaxDynamicSharedMemorySize, VSMEM);

    // converts (x split + all 4 weight transposes in one launch each)
    split_convert<<<OUT_ELEMS / 4 / 256, 256>>>(x, p_xhi, p_xlo, OUT_ELEMS / 4);
    dim3 wt4(32, 32, 4), wb(32, 8);
    wtrans_convert4<<<wt4, wb>>>(Wq, Wk, Wv, Wo);

    // fused QKV projection (one launch, 768 CTAs)
    dim3 gq(24, 32);
    gemm_qkv<<<gq, 256, GSMEM>>>(bq, bk, bv);

    // scores + entmax
    dim3 ge(32, BH);
    attn_entmax_mma<<<ge, 512, ESMEM>>>(attn_ptr, p_phi, p_plo);

    // attn @ V
    dim3 ga(8, BH);
    gemm_av_mma<<<ga, 256, VSMEM>>>(p_phi, p_plo);

    // output projection
    dim3 gg(8, 32);
    gemm_out<<<gg, 256, GSMEM>>>(bo, out_ptr);
}

// round 12
// speedup vs baseline: 1.3663x; 1.3125x over previous
#include <cuda_runtime.h>
#include <cuda_bf16.h>
#include <cstdint>

#define BATCH 4
#define SEQ   1024
#define CH    1024
#define HEADS 16
#define DH    64
#define TOKENS (BATCH * SEQ)
#define BH (BATCH * HEADS)
#define OUT_ELEMS (TOKENS * CH)

#define BISECT_ITERS 12
#define SOLVE_ITERS 3
#define SCALE 0.0625f   // (1/sqrt(64)) * (alpha-1)

// bf16 split scratch
__device__ __nv_bfloat16 g_xhi[TOKENS * CH];
__device__ __nv_bfloat16 g_xlo[TOKENS * CH];
__device__ __nv_bfloat16 g_wthi[4 * CH * CH];
__device__ __nv_bfloat16 g_wtlo[4 * CH * CH];
__device__ __nv_bfloat16 g_qhi[BH * SEQ * DH];
__device__ __nv_bfloat16 g_qlo[BH * SEQ * DH];
__device__ __nv_bfloat16 g_khi[BH * SEQ * DH];
__device__ __nv_bfloat16 g_klo[BH * SEQ * DH];
__device__ __nv_bfloat16 g_vthi[BH * DH * SEQ];   // transposed V: [bh][dh][tok]
__device__ __nv_bfloat16 g_vtlo[BH * DH * SEQ];
__device__ __nv_bfloat16 g_phi[(size_t)BH * SEQ * SEQ];  // attn split
__device__ __nv_bfloat16 g_plo[(size_t)BH * SEQ * SEQ];
__device__ __nv_bfloat16 g_chi[TOKENS * CH];
__device__ __nv_bfloat16 g_clo[TOKENS * CH];

// ===================== PTX helpers =========================================
__device__ __forceinline__ uint32_t smem_u32(const void* p) {
    uint32_t a;
    asm("{ .reg .u64 t; cvta.to.shared.u64 t, %1; cvt.u32.u64 %0, t; }" : "=r"(a) : "l"(p));
    return a;
}
#define CP_ASYNC16(sa, g) \
    asm volatile("cp.async.cg.shared.global [%0], [%1], 16;" :: "r"(sa), "l"(g))
#define CP_COMMIT() asm volatile("cp.async.commit_group;" ::: "memory")
#define CP_WAIT0() asm volatile("cp.async.wait_group 0;" ::: "memory")
#define CP_WAIT1() asm volatile("cp.async.wait_group 1;" ::: "memory")
#define LDSM4(r0, r1, r2, r3, addr) \
    asm volatile("ldmatrix.sync.aligned.m8n8.x4.shared.b16 {%0,%1,%2,%3}, [%4];" \
        : "=r"(r0), "=r"(r1), "=r"(r2), "=r"(r3) : "r"(addr))
#define MMA16816(d, a, b0, b1) \
    asm volatile("mma.sync.aligned.m16n8k16.row.col.f32.bf16.bf16.f32 " \
        "{%0,%1,%2,%3}, {%4,%5,%6,%7}, {%8,%9}, {%0,%1,%2,%3};" \
        : "+f"((d)[0]), "+f"((d)[1]), "+f"((d)[2]), "+f"((d)[3]) \
        : "r"((a)[0]), "r"((a)[1]), "r"((a)[2]), "r"((a)[3]), "r"(b0), "r"(b1))

__device__ __forceinline__ void split1(float v, __nv_bfloat16& h, __nv_bfloat16& l) {
    h = __float2bfloat16_rn(v);
    l = __float2bfloat16_rn(v - __bfloat162float(h));
}
__device__ __forceinline__ float sum8(const float* base, int row) {
    float4 a = ((const float4*)base)[row * 2];
    float4 b = ((const float4*)base)[row * 2 + 1];
    return ((a.x + a.y) + (a.z + a.w)) + ((b.x + b.y) + (b.z + b.w));
}
__device__ __forceinline__ float max8(const float* base, int row) {
    float4 a = ((const float4*)base)[row * 2];
    float4 b = ((const float4*)base)[row * 2 + 1];
    return fmaxf(fmaxf(fmaxf(a.x, a.y), fmaxf(a.z, a.w)),
                 fmaxf(fmaxf(b.x, b.y), fmaxf(b.z, b.w)));
}

// ===================== convert kernels =====================================
__global__ __launch_bounds__(256) void split_convert(
    const float* __restrict__ in, __nv_bfloat16* __restrict__ hi,
    __nv_bfloat16* __restrict__ lo, int n4)
{
    int i = blockIdx.x * 256 + threadIdx.x;
    if (i >= n4) return;
    float4 v = ((const float4*)in)[i];
    union { ushort u[4]; uint2 q; } H, L;
    float a[4] = {v.x, v.y, v.z, v.w};
#pragma unroll
    for (int j = 0; j < 4; j++) {
        __nv_bfloat16 h, l; split1(a[j], h, l);
        H.u[j] = __bfloat16_as_ushort(h);
        L.u[j] = __bfloat16_as_ushort(l);
    }
    ((uint2*)hi)[i] = H.q;
    ((uint2*)lo)[i] = L.q;
}

// all 4 weights in one launch: blockIdx.z selects the matrix
__global__ __launch_bounds__(256) void wtrans_convert4(
    const float* __restrict__ W0, const float* __restrict__ W1,
    const float* __restrict__ W2, const float* __restrict__ W3)
{
    __shared__ float t[32][33];
    int tx = threadIdx.x, ty = threadIdx.y;
    int bx = blockIdx.x, by = blockIdx.y, bz = blockIdx.z;
    const float* W = (bz == 0) ? W0 : (bz == 1) ? W1 : (bz == 2) ? W2 : W3;
    __nv_bfloat16* hi = g_wthi + (size_t)bz * 1048576;
    __nv_bfloat16* lo = g_wtlo + (size_t)bz * 1048576;
#pragma unroll
    for (int i = 0; i < 4; i++)
        t[ty + i * 8][tx] = W[(size_t)(by * 32 + ty + i * 8) * 1024 + bx * 32 + tx];
    __syncthreads();
#pragma unroll
    for (int i = 0; i < 4; i++) {
        float v = t[tx][ty + i * 8];
        __nv_bfloat16 h, l; split1(v, h, l);
        size_t o = (size_t)(bx * 32 + ty + i * 8) * 1024 + by * 32 + tx;
        hi[o] = h;
        lo[o] = l;
    }
}

// ===================== GEMM core (shared by QKV-fused and plain) ===========
#define GSTAGE 32768
#define GSMEM (2 * GSTAGE)

__device__ __forceinline__ void gemm_mainloop(
    uint32_t sb, int tid, int wm, int wn,
    const __nv_bfloat16* Ah, const __nv_bfloat16* Al,
    const __nv_bfloat16* Bh, const __nv_bfloat16* Bl,
    float acc[4][4][4])
{
    int lane = tid & 31;
    const __nv_bfloat16* gsrc[4] = { Ah, Al, Bh, Bl };
    int l_row0 = tid >> 2,         l_c0 = tid & 3;
    int l_row1 = (tid + 256) >> 2, l_c1 = (tid + 256) & 3;

    auto load_stage = [&](int kt, int s) {
        uint32_t sbase = sb + s * GSTAGE;
#pragma unroll
        for (int t = 0; t < 4; t++) {
            const char* g0 = (const char*)(gsrc[t] + (size_t)l_row0 * 1024 + kt * 32) + l_c0 * 16;
            const char* g1 = (const char*)(gsrc[t] + (size_t)l_row1 * 1024 + kt * 32) + l_c1 * 16;
            uint32_t s0 = sbase + t * 8192 + l_row0 * 64 + ((l_c0 ^ (l_row0 & 3)) * 16);
            uint32_t s1 = sbase + t * 8192 + l_row1 * 64 + ((l_c1 ^ (l_row1 & 3)) * 16);
            CP_ASYNC16(s0, g0);
            CP_ASYNC16(s1, g1);
        }
        CP_COMMIT();
    };

    int arow = (lane & 7) | (((lane >> 3) & 1) << 3);
    int asel = lane >> 4;
    int brow = (lane & 7) | ((lane >> 4) << 3);
    int bsel = (lane >> 3) & 1;

    load_stage(0, 0);
    load_stage(1, 1);

#pragma unroll 1
    for (int t = 0; t < 32; t++) {
        if (t >= 31) { CP_WAIT0(); } else { CP_WAIT1(); }
        __syncthreads();

        uint32_t base = sb + (t & 1) * GSTAGE;
        uint32_t Ahb = base, Alb = base + 8192, Bhb = base + 16384, Blb = base + 24576;

#pragma unroll
        for (int ks = 0; ks < 2; ks++) {
            int akc = ks * 2 + asel;
            int bkc = ks * 2 + bsel;
            uint32_t ah[4][4], al[4][4], bhf[2][4], blf[2][4];
#pragma unroll
            for (int mt = 0; mt < 4; mt++) {
                int row = wm * 64 + mt * 16 + arow;
                uint32_t off = row * 64 + ((akc ^ (row & 3)) * 16);
                LDSM4(ah[mt][0], ah[mt][1], ah[mt][2], ah[mt][3], Ahb + off);
            }
#pragma unroll
            for (int nt = 0; nt < 2; nt++) {
                int row = wn * 32 + nt * 16 + brow;
                uint32_t off = row * 64 + ((bkc ^ (row & 3)) * 16);
                LDSM4(bhf[nt][0], bhf[nt][1], bhf[nt][2], bhf[nt][3], Bhb + off);
            }
#pragma unroll
            for (int mt = 0; mt < 4; mt++)
#pragma unroll
                for (int nt = 0; nt < 2; nt++) {
                    MMA16816(acc[mt][nt * 2 + 0], ah[mt], bhf[nt][0], bhf[nt][1]);
                    MMA16816(acc[mt][nt * 2 + 1], ah[mt], bhf[nt][2], bhf[nt][3]);
                }
#pragma unroll
            for (int nt = 0; nt < 2; nt++) {
                int row = wn * 32 + nt * 16 + brow;
                uint32_t off = row * 64 + ((bkc ^ (row & 3)) * 16);
                LDSM4(blf[nt][0], blf[nt][1], blf[nt][2], blf[nt][3], Blb + off);
            }
#pragma unroll
            for (int mt = 0; mt < 4; mt++)
#pragma unroll
                for (int nt = 0; nt < 2; nt++) {
                    MMA16816(acc[mt][nt * 2 + 0], ah[mt], blf[nt][0], blf[nt][1]);
                    MMA16816(acc[mt][nt * 2 + 1], ah[mt], blf[nt][2], blf[nt][3]);
                }
#pragma unroll
            for (int mt = 0; mt < 4; mt++) {
                int row = wm * 64 + mt * 16 + arow;
                uint32_t off = row * 64 + ((akc ^ (row & 3)) * 16);
                LDSM4(al[mt][0], al[mt][1], al[mt][2], al[mt][3], Alb + off);
            }
#pragma unroll
            for (int mt = 0; mt < 4; mt++)
#pragma unroll
                for (int nt = 0; nt < 2; nt++) {
                    MMA16816(acc[mt][nt * 2 + 0], al[mt], bhf[nt][0], bhf[nt][1]);
                    MMA16816(acc[mt][nt * 2 + 1], al[mt], bhf[nt][2], bhf[nt][3]);
                }
        }
        __syncthreads();
        if (t + 2 < 32) load_stage(t + 2, t & 1);
    }
}

// Fused QKV projection: grid (24, 32). bx 0-7 -> Q, 8-15 -> K, 16-23 -> V.
__global__ __launch_bounds__(256, 2) void gemm_qkv(
    const float* __restrict__ bq, const float* __restrict__ bk,
    const float* __restrict__ bv)
{
    extern __shared__ char sm[];
    uint32_t sb = smem_u32(sm);
    int tid = threadIdx.x, lane = tid & 31, wid = tid >> 5;
    int wm = wid >> 2, wn = wid & 3;
    int widx = blockIdx.x >> 3;
    int n0 = (blockIdx.x & 7) * 128;
    int m0 = blockIdx.y * 128;

    const float* bias = (widx == 0) ? bq : (widx == 1) ? bk : bv;
    const __nv_bfloat16* Bh = g_wthi + (size_t)widx * 1048576 + (size_t)n0 * 1024;
    const __nv_bfloat16* Bl = g_wtlo + (size_t)widx * 1048576 + (size_t)n0 * 1024;

    float acc[4][4][4];
#pragma unroll
    for (int a = 0; a < 4; a++)
#pragma unroll
        for (int b = 0; b < 4; b++)
#pragma unroll
            for (int c = 0; c < 4; c++) acc[a][b][c] = 0.0f;

    gemm_mainloop(sb, tid, wm, wn,
                  g_xhi + (size_t)m0 * 1024, g_xlo + (size_t)m0 * 1024, Bh, Bl, acc);

    int r = lane >> 2, c2 = (lane & 3) * 2;
    __nv_bfloat16* dhi = (widx == 0) ? g_qhi : (widx == 1) ? g_khi : g_vthi;
    __nv_bfloat16* dlo = (widx == 0) ? g_qlo : (widx == 1) ? g_klo : g_vtlo;
#pragma unroll
    for (int mt = 0; mt < 4; mt++) {
        int mrow = m0 + wm * 64 + mt * 16 + r;
        int bidx = mrow >> 10, ntok = mrow & 1023;
#pragma unroll
        for (int nt8 = 0; nt8 < 4; nt8++) {
            int col = n0 + wn * 32 + nt8 * 8 + c2;
            float b0 = bias[col], b1 = bias[col + 1];
            float v00 = acc[mt][nt8][0] + b0, v01 = acc[mt][nt8][1] + b1;
            float v10 = acc[mt][nt8][2] + b0, v11 = acc[mt][nt8][3] + b1;
            int h = col >> 6, dh = col & 63;
            if (widx < 2) {
                size_t base = ((size_t)(bidx * HEADS + h) * SEQ + ntok) * DH + dh;
                __nv_bfloat16 h0, l0, h1, l1;
                split1(v00, h0, l0); split1(v01, h1, l1);
                *(__nv_bfloat162*)(dhi + base) = {h0, h1};
                *(__nv_bfloat162*)(dlo + base) = {l0, l1};
                split1(v10, h0, l0); split1(v11, h1, l1);
                *(__nv_bfloat162*)(dhi + base + 8 * DH) = {h0, h1};
                *(__nv_bfloat162*)(dlo + base + 8 * DH) = {l0, l1};
            } else {
                size_t vb = ((size_t)(bidx * HEADS + h) * DH + dh) * SEQ + ntok;
                __nv_bfloat16 hh, ll;
                split1(v00, hh, ll); dhi[vb] = hh; dlo[vb] = ll;
                split1(v01, hh, ll); dhi[vb + SEQ] = hh; dlo[vb + SEQ] = ll;
                split1(v10, hh, ll); dhi[vb + 8] = hh; dlo[vb + 8] = ll;
                split1(v11, hh, ll); dhi[vb + SEQ + 8] = hh; dlo[vb + SEQ + 8] = ll;
            }
        }
    }
}

// Output projection: ctx_split @ Wo^T + bo -> fp32 out
__global__ __launch_bounds__(256, 2) void gemm_out(
    const float* __restrict__ bias, float* __restrict__ dstf)
{
    extern __shared__ char sm[];
    uint32_t sb = smem_u32(sm);
    int tid = threadIdx.x, lane = tid & 31, wid = tid >> 5;
    int wm = wid >> 2, wn = wid & 3;
    int n0 = blockIdx.x * 128, m0 = blockIdx.y * 128;

    float acc[4][4][4];
#pragma unroll
    for (int a = 0; a < 4; a++)
#pragma unroll
        for (int b = 0; b < 4; b++)
#pragma unroll
            for (int c = 0; c < 4; c++) acc[a][b][c] = 0.0f;

    gemm_mainloop(sb, tid, wm, wn,
                  g_chi + (size_t)m0 * 1024, g_clo + (size_t)m0 * 1024,
                  g_wthi + 3u * 1048576 + (size_t)n0 * 1024,
                  g_wtlo + 3u * 1048576 + (size_t)n0 * 1024, acc);

    int r = lane >> 2, c2 = (lane & 3) * 2;
#pragma unroll
    for (int mt = 0; mt < 4; mt++) {
        int mrow = m0 + wm * 64 + mt * 16 + r;
#pragma unroll
        for (int nt8 = 0; nt8 < 4; nt8++) {
            int col = n0 + wn * 32 + nt8 * 8 + c2;
            float b0 = bias[col], b1 = bias[col + 1];
            float* p = dstf + (size_t)mrow * CH + col;
            *(float2*)p = {acc[mt][nt8][0] + b0, acc[mt][nt8][1] + b1};
            *(float2*)(p + 8 * CH) = {acc[mt][nt8][2] + b0, acc[mt][nt8][3] + b1};
        }
    }
}

// ===================== fused HMMA scores + entmax ==========================
// 256 thr = 8 warps, 16 q-rows/CTA, 2 CTAs/SM. Warp w computes within-chunk
// col-tile w (16 cols) for ALL 8 chunks; acc[2c+half] = chunk c.
#define EOFF_QH 0
#define EOFF_QL 2048
#define EOFF_K  4096
#define EOFF_RED (4096 + 2 * 32768)
#define ESMEM (EOFF_RED + 2 * 384 * 4)

__global__ __launch_bounds__(256, 2) void attn_entmax_mma(
    float* __restrict__ attn,
    __nv_bfloat16* __restrict__ phi, __nv_bfloat16* __restrict__ plo)
{
    extern __shared__ char sm[];
    uint32_t sb = smem_u32(sm);
    float* RED = (float*)(sm + EOFF_RED);   // [2][384]

    int tid = threadIdx.x, lane = tid & 31, wid = tid >> 5;   // wid 0..7
    int bh = blockIdx.y;
    int R0 = blockIdx.x * 16;

    {   // Q: 16 rows x 8 u x {hi,lo} = 256 chunks, 1/thread
        int hl = tid >> 7;
        int row = (tid >> 3) & 15;
        int u = tid & 7;
        const __nv_bfloat16* src = (hl ? g_qlo : g_qhi) + ((size_t)bh * SEQ + R0 + row) * DH + u * 8;
        uint32_t d = sb + EOFF_QH + hl * 2048 + row * 128 + ((u ^ (row & 7)) * 16);
        CP_ASYNC16(d, src);
    }
    auto loadK = [&](int c, int s) {
        uint32_t base = sb + EOFF_K + s * 32768;
#pragma unroll
        for (int i = 0; i < 8; i++) {
            int idx = tid + i * 256;
            int hl = idx >> 10;
            int row = (idx >> 3) & 127;
            int u = idx & 7;
            const __nv_bfloat16* src = (hl ? g_klo : g_khi) + ((size_t)bh * SEQ + c * 128 + row) * DH + u * 8;
            uint32_t d = base + hl * 16384 + row * 128 + ((u ^ (row & 7)) * 16);
            CP_ASYNC16(d, src);
        }
        CP_COMMIT();
    };
    loadK(0, 0);
    loadK(1, 1);

    float acc[16][4];
#pragma unroll
    for (int t = 0; t < 16; t++)
#pragma unroll
        for (int e = 0; e < 4; e++) acc[t][e] = 0.0f;

    int arow_ = (lane & 7) | (((lane >> 3) & 1) << 3);   // 0..15
    int asel = lane >> 4;
    int brow_ = (lane & 7) | ((lane >> 4) << 3);
    int bsel = (lane >> 3) & 1;
    int krow_ = wid * 16 + brow_;
    uint32_t QHb = sb + EOFF_QH, QLb = sb + EOFF_QL;

    // fully unrolled chunk loop: acc indices compile-time; all warps compute
#pragma unroll
    for (int c = 0; c < 8; c++) {
        if (c >= 7) { CP_WAIT0(); } else { CP_WAIT1(); }
        __syncthreads();
        uint32_t KHb = sb + EOFF_K + (c & 1) * 32768;
        uint32_t KLb = KHb + 16384;
#pragma unroll
        for (int kc = 0; kc < 4; kc++) {
            uint32_t au = (uint32_t)(kc * 2 + asel);
            uint32_t aoff = arow_ * 128 + ((au ^ (arow_ & 7)) * 16);
            uint32_t ah[4], al[4];
            LDSM4(ah[0], ah[1], ah[2], ah[3], QHb + aoff);
            LDSM4(al[0], al[1], al[2], al[3], QLb + aoff);
            uint32_t bu = (uint32_t)(kc * 2 + bsel);
            uint32_t boff = krow_ * 128 + ((bu ^ (krow_ & 7)) * 16);
            uint32_t bh4[4], bl4[4];
            LDSM4(bh4[0], bh4[1], bh4[2], bh4[3], KHb + boff);
            LDSM4(bl4[0], bl4[1], bl4[2], bl4[3], KLb + boff);
            MMA16816(acc[2 * c + 0], ah, bh4[0], bh4[1]);
            MMA16816(acc[2 * c + 1], ah, bh4[2], bh4[3]);
            MMA16816(acc[2 * c + 0], ah, bl4[0], bl4[1]);
            MMA16816(acc[2 * c + 1], ah, bl4[2], bl4[3]);
            MMA16816(acc[2 * c + 0], al, bh4[0], bh4[1]);
            MMA16816(acc[2 * c + 1], al, bh4[2], bh4[3]);
            MMA16816(acc[2 * c + 0], al, bl4[0], bl4[1]);
            MMA16816(acc[2 * c + 1], al, bl4[2], bl4[3]);
        }
        __syncthreads();
        if (c + 2 < 8) loadK(c + 2, c & 1);
    }

    // --- entmax (rows 0..15), redundant all-thread reductions ---
    int r0 = lane >> 2;       // rows for acc[t][0..1]
    int r1 = r0 + 8;          // rows for acc[t][2..3]
    bool qlead = (lane & 3) == 0;
    int par = 0;

#pragma unroll
    for (int t = 0; t < 16; t++)
#pragma unroll
        for (int e = 0; e < 4; e++) acc[t][e] *= SCALE;

    // Phase A: row max
    float tloA, tloB;
    {
        float mA = -1e30f, mB = -1e30f;
#pragma unroll
        for (int t = 0; t < 16; t++) {
            mA = fmaxf(mA, fmaxf(acc[t][0], acc[t][1]));
            mB = fmaxf(mB, fmaxf(acc[t][2], acc[t][3]));
        }
        mA = fmaxf(mA, __shfl_xor_sync(0xffffffffu, mA, 1));
        mA = fmaxf(mA, __shfl_xor_sync(0xffffffffu, mA, 2));
        mB = fmaxf(mB, __shfl_xor_sync(0xffffffffu, mB, 1));
        mB = fmaxf(mB, __shfl_xor_sync(0xffffffffu, mB, 2));
        float* RP = RED + par * 384;
        if (qlead) { RP[r0 * 8 + wid] = mA; RP[r1 * 8 + wid] = mB; }
        __syncthreads();
        tloA = max8(RP, r0) - 1.0f;
        tloB = max8(RP, r1) - 1.0f;
        par ^= 1;
    }

    // Phase B: f_lo
    float flA, flB;
    {
        float c0 = 0.f, c1 = 0.f, c2 = 0.f, c3 = 0.f;
#pragma unroll
        for (int t = 0; t < 16; t++) {
            float u;
            u = fmaxf(acc[t][0] - tloA, 0.f); c0 = fmaf(u, u, c0);
            u = fmaxf(acc[t][1] - tloA, 0.f); c1 = fmaf(u, u, c1);
            u = fmaxf(acc[t][2] - tloB, 0.f); c2 = fmaf(u, u, c2);
            u = fmaxf(acc[t][3] - tloB, 0.f); c3 = fmaf(u, u, c3);
        }
        float vA = c0 + c1, vB = c2 + c3;
        vA += __shfl_xor_sync(0xffffffffu, vA, 1);
        vA += __shfl_xor_sync(0xffffffffu, vA, 2);
        vB += __shfl_xor_sync(0xffffffffu, vB, 1);
        vB += __shfl_xor_sync(0xffffffffu, vB, 2);
        float* RP = RED + par * 384;
        if (qlead) { RP[r0 * 8 + wid] = vA; RP[r1 * 8 + wid] = vB; }
        __syncthreads();
        flA = sum8(RP, r0) - 1.0f;
        flB = sum8(RP, r1) - 1.0f;
        par ^= 1;
    }

    float dm = 0.484375f;
    float tmA = tloA + dm, tmB = tloB + dm;

    // Phase C: bisection
#pragma unroll 1
    for (int it = 0; it < BISECT_ITERS; it++) {
        float c0 = 0.f, c1 = 0.f, c2 = 0.f, c3 = 0.f;
#pragma unroll
        for (int t = 0; t < 16; t++) {
            float u;
            u = fmaxf(acc[t][0] - tmA, 0.f); c0 = fmaf(u, u, c0);
            u = fmaxf(acc[t][1] - tmA, 0.f); c1 = fmaf(u, u, c1);
            u = fmaxf(acc[t][2] - tmB, 0.f); c2 = fmaf(u, u, c2);
            u = fmaxf(acc[t][3] - tmB, 0.f); c3 = fmaf(u, u, c3);
        }
        float vA = c0 + c1, vB = c2 + c3;
        vA += __shfl_xor_sync(0xffffffffu, vA, 1);
        vA += __shfl_xor_sync(0xffffffffu, vA, 2);
        vB += __shfl_xor_sync(0xffffffffu, vB, 1);
        vB += __shfl_xor_sync(0xffffffffu, vB, 2);
        float* RP = RED + par * 384;
        if (qlead) { RP[r0 * 8 + wid] = vA; RP[r1 * 8 + wid] = vB; }
        __syncthreads();
        float fmA = sum8(RP, r0) - 1.0f;
        float fmB = sum8(RP, r1) - 1.0f;
        if (fmA * flA >= 0.f) tloA = tmA;
        if (fmB * flB >= 0.f) tloB = tmB;
        if (it < BISECT_ITERS - 1) {
            dm *= 0.5f;
            tmA = tloA + dm;
            tmB = tloB + dm;
        }
        par ^= 1;
    }

    // Phase D: analytic support-fixpoint solves
#pragma unroll 1
    for (int ps = 0; ps < SOLVE_ITERS; ps++) {
        float nA = 0.f, s1A = 0.f, s2A = 0.f;
        float nB = 0.f, s1B = 0.f, s2B = 0.f;
#pragma unroll
        for (int t = 0; t < 16; t++) {
#pragma unroll
            for (int e = 0; e < 2; e++) {
                float a = acc[t][e];
                if (a > tmA) { nA += 1.f; s1A += a; s2A = fmaf(a, a, s2A); }
                float b = acc[t][e + 2];
                if (b > tmB) { nB += 1.f; s1B += b; s2B = fmaf(b, b, s2B); }
            }
        }
#pragma unroll
        for (int o = 1; o <= 2; o <<= 1) {
            nA += __shfl_xor_sync(0xffffffffu, nA, o);
            s1A += __shfl_xor_sync(0xffffffffu, s1A, o);
            s2A += __shfl_xor_sync(0xffffffffu, s2A, o);
            nB += __shfl_xor_sync(0xffffffffu, nB, o);
            s1B += __shfl_xor_sync(0xffffffffu, s1B, o);
            s2B += __shfl_xor_sync(0xffffffffu, s2B, o);
        }
        float* RP = RED + par * 384;
        if (qlead) {
            RP[r0 * 8 + wid] = nA;        RP[r1 * 8 + wid] = nB;
            RP[128 + r0 * 8 + wid] = s1A; RP[128 + r1 * 8 + wid] = s1B;
            RP[256 + r0 * 8 + wid] = s2A; RP[256 + r1 * 8 + wid] = s2B;
        }
        __syncthreads();
        {
            float n = sum8(RP, r0), s1 = sum8(RP + 128, r0), s2 = sum8(RP + 256, r0);
            float D = fmaxf(fmaf(s1, s1, -n * (s2 - 1.0f)), 0.f);
            tmA = (s1 - sqrtf(D)) / n;
            n = sum8(RP, r1); s1 = sum8(RP + 128, r1); s2 = sum8(RP + 256, r1);
            D = fmaxf(fmaf(s1, s1, -n * (s2 - 1.0f)), 0.f);
            tmB = (s1 - sqrtf(D)) / n;
        }
        par ^= 1;
    }

    // Phase E: final p + normalize + write
    float ivA, ivB;
    {
        float c0 = 0.f, c1 = 0.f, c2 = 0.f, c3 = 0.f;
#pragma unroll
        for (int t = 0; t < 16; t++) {
            float u;
            u = fmaxf(acc[t][0] - tmA, 0.f); acc[t][0] = u * u; c0 += acc[t][0];
            u = fmaxf(acc[t][1] - tmA, 0.f); acc[t][1] = u * u; c1 += acc[t][1];
            u = fmaxf(acc[t][2] - tmB, 0.f); acc[t][2] = u * u; c2 += acc[t][2];
            u = fmaxf(acc[t][3] - tmB, 0.f); acc[t][3] = u * u; c3 += acc[t][3];
        }
        float vA = c0 + c1, vB = c2 + c3;
        vA += __shfl_xor_sync(0xffffffffu, vA, 1);
        vA += __shfl_xor_sync(0xffffffffu, vA, 2);
        vB += __shfl_xor_sync(0xffffffffu, vB, 1);
        vB += __shfl_xor_sync(0xffffffffu, vB, 2);
        float* RP = RED + par * 384;
        if (qlead) { RP[r0 * 8 + wid] = vA; RP[r1 * 8 + wid] = vB; }
        __syncthreads();
        ivA = 1.0f / sum8(RP, r0);
        ivB = 1.0f / sum8(RP, r1);
    }
    {
        // acc[t][*]: chunk c = t>>1, col = c*128 + wid*16 + (t&1)*8 + (lane&3)*2
        size_t rb0 = ((size_t)bh * SEQ + R0 + r0) * SEQ + wid * 16 + (lane & 3) * 2;
        size_t rb1 = ((size_t)bh * SEQ + R0 + r1) * SEQ + wid * 16 + (lane & 3) * 2;
#pragma unroll
        for (int t = 0; t < 16; t++) {
            int off = (t >> 1) * 128 + (t & 1) * 8;
            float p0 = acc[t][0] * ivA, p1 = acc[t][1] * ivA;
            float p2 = acc[t][2] * ivB, p3 = acc[t][3] * ivB;
            *(float2*)(attn + rb0 + off) = {p0, p1};
            *(float2*)(attn + rb1 + off) = {p2, p3};
            __nv_bfloat16 h0, l0, h1, l1;
            split1(p0, h0, l0); split1(p1, h1, l1);
            *(__nv_bfloat162*)(phi + rb0 + off) = {h0, h1};
            *(__nv_bfloat162*)(plo + rb0 + off) = {l0, l1};
            split1(p2, h0, l0); split1(p3, h1, l1);
            *(__nv_bfloat162*)(phi + rb1 + off) = {h0, h1};
            *(__nv_bfloat162*)(plo + rb1 + off) = {l0, l1};
        }
    }
}

// ===================== attn @ V via HMMA (split-bf16) ======================
#define VSTAGE 24576
#define VSMEM (2 * VSTAGE)

__global__ __launch_bounds__(256, 2) void gemm_av_mma(
    const __nv_bfloat16* __restrict__ Ph, const __nv_bfloat16* __restrict__ Pl)
{
    extern __shared__ char sm[];
    uint32_t sb = smem_u32(sm);
    int tid = threadIdx.x, lane = tid & 31, wid = tid >> 5;
    int wm = wid >> 1, wn = wid & 1;
    int m0 = blockIdx.x * 128;
    int bh = blockIdx.y;

    const __nv_bfloat16* pa[2] = { Ph + ((size_t)bh * SEQ + m0) * SEQ,
                                   Pl + ((size_t)bh * SEQ + m0) * SEQ };
    const __nv_bfloat16* pb[2] = { g_vthi + (size_t)bh * DH * SEQ,
                                   g_vtlo + (size_t)bh * DH * SEQ };

    auto load_stage = [&](int kt, int s) {
        uint32_t base = sb + s * VSTAGE;
#pragma unroll
        for (int i = 0; i < 4; i++) {
            int idx = tid + i * 256;
            int hl = idx >> 9;
            int row = (idx >> 2) & 127;
            int u = idx & 3;
            const __nv_bfloat16* g = pa[hl] + (size_t)row * SEQ + kt * 32 + u * 8;
            uint32_t d = base + hl * 8192 + row * 64 + ((u ^ (row & 3)) * 16);
            CP_ASYNC16(d, g);
        }
#pragma unroll
        for (int i = 0; i < 2; i++) {
            int idx = tid + i * 256;
            int hl = idx >> 8;
            int row = (idx >> 2) & 63;
            int u = idx & 3;
            const __nv_bfloat16* g = pb[hl] + (size_t)row * SEQ + kt * 32 + u * 8;
            uint32_t d = base + 16384 + hl * 4096 + row * 64 + ((u ^ (row & 3)) * 16);
            CP_ASYNC16(d, g);
        }
        CP_COMMIT();
    };

    float acc[2][4][4];
#pragma unroll
    for (int a = 0; a < 2; a++)
#pragma unroll
        for (int b = 0; b < 4; b++)
#pragma unroll
            for (int c = 0; c < 4; c++) acc[a][b][c] = 0.0f;

    int arow = (lane & 7) | (((lane >> 3) & 1) << 3);
    int asel = lane >> 4;
    int brow = (lane & 7) | ((lane >> 4) << 3);
    int bsel = (lane >> 3) & 1;

    load_stage(0, 0);
    load_stage(1, 1);

#pragma unroll 1
    for (int t = 0; t < 32; t++) {
        if (t >= 31) { CP_WAIT0(); } else { CP_WAIT1(); }
        __syncthreads();

        uint32_t base = sb + (t & 1) * VSTAGE;
        uint32_t Ahb = base, Alb = base + 8192, Bhb = base + 16384, Blb = base + 20480;

#pragma unroll
        for (int ks = 0; ks < 2; ks++) {
            int akc = ks * 2 + asel;
            int bkc = ks * 2 + bsel;
            uint32_t ah[2][4], al[2][4], bh4[2][4], bl4[2][4];
#pragma unroll
            for (int mt = 0; mt < 2; mt++) {
                int row = wm * 32 + mt * 16 + arow;
                uint32_t off = row * 64 + ((akc ^ (row & 3)) * 16);
                LDSM4(ah[mt][0], ah[mt][1], ah[mt][2], ah[mt][3], Ahb + off);
                LDSM4(al[mt][0], al[mt][1], al[mt][2], al[mt][3], Alb + off);
            }
#pragma unroll
            for (int nt = 0; nt < 2; nt++) {
                int row = wn * 32 + nt * 16 + brow;
                uint32_t off = row * 64 + ((bkc ^ (row & 3)) * 16);
                LDSM4(bh4[nt][0], bh4[nt][1], bh4[nt][2], bh4[nt][3], Bhb + off);
                LDSM4(bl4[nt][0], bl4[nt][1], bl4[nt][2], bl4[nt][3], Blb + off);
            }
#pragma unroll
            for (int mt = 0; mt < 2; mt++)
#pragma unroll
                for (int nt = 0; nt < 2; nt++) {
                    MMA16816(acc[mt][nt * 2 + 0], ah[mt], bh4[nt][0], bh4[nt][1]);
                    MMA16816(acc[mt][nt * 2 + 1], ah[mt], bh4[nt][2], bh4[nt][3]);
                    MMA16816(acc[mt][nt * 2 + 0], ah[mt], bl4[nt][0], bl4[nt][1]);
                    MMA16816(acc[mt][nt * 2 + 1], ah[mt], bl4[nt][2], bl4[nt][3]);
                    MMA16816(acc[mt][nt * 2 + 0], al[mt], bh4[nt][0], bh4[nt][1]);
                    MMA16816(acc[mt][nt * 2 + 1], al[mt], bh4[nt][2], bh4[nt][3]);
                }
        }
        __syncthreads();
        if (t + 2 < 32) load_stage(t + 2, t & 1);
    }

    int r = lane >> 2, c2 = (lane & 3) * 2;
    int bidx = bh >> 4, h = bh & 15;
#pragma unroll
    for (int mt = 0; mt < 2; mt++) {
        int mrow = m0 + wm * 32 + mt * 16 + r;
        size_t tok0 = (size_t)(bidx * SEQ + mrow) * CH;
        size_t tok1 = (size_t)(bidx * SEQ + mrow + 8) * CH;
#pragma unroll
        for (int nt8 = 0; nt8 < 4; nt8++) {
            int col = h * DH + wn * 32 + nt8 * 8 + c2;
            __nv_bfloat16 h0, l0, h1, l1;
            split1(acc[mt][nt8][0], h0, l0); split1(acc[mt][nt8][1], h1, l1);
            *(__nv_bfloat162*)(g_chi + tok0 + col) = {h0, h1};
            *(__nv_bfloat162*)(g_clo + tok0 + col) = {l0, l1};
            split1(acc[mt][nt8][2], h0, l0); split1(acc[mt][nt8][3], h1, l1);
            *(__nv_bfloat162*)(g_chi + tok1 + col) = {h0, h1};
            *(__nv_bfloat162*)(g_clo + tok1 + col) = {l0, l1};
        }
    }
}

// ---------------------------------------------------------------------------
extern "C" void kernel_launch(void* const* d_in, const int* in_sizes, int n_in,
                              void* d_out, int out_size)
{
    const float* x  = (const float*)d_in[0];
    const float* Wq = (const float*)d_in[1];
    const float* bq = (const float*)d_in[2];
    const float* Wk = (const float*)d_in[3];
    const float* bk = (const float*)d_in[4];
    const float* Wv = (const float*)d_in[5];
    const float* bv = (const float*)d_in[6];
    const float* Wo = (const float*)d_in[7];
    const float* bo = (const float*)d_in[8];

    float* out_ptr  = (float*)d_out;
    float* attn_ptr = out_ptr + OUT_ELEMS;

    __nv_bfloat16 *p_xhi, *p_xlo, *p_phi, *p_plo;
    cudaGetSymbolAddress((void**)&p_xhi, g_xhi);
    cudaGetSymbolAddress((void**)&p_xlo, g_xlo);
    cudaGetSymbolAddress((void**)&p_phi, g_phi);
    cudaGetSymbolAddress((void**)&p_plo, g_plo);

    cudaFuncSetAttribute(gemm_qkv, cudaFuncAttributeMaxDynamicSharedMemorySize, GSMEM);
    cudaFuncSetAttribute(gemm_out, cudaFuncAttributeMaxDynamicSharedMemorySize, GSMEM);
    cudaFuncSetAttribute(attn_entmax_mma, cudaFuncAttributeMaxDynamicSharedMemorySize, ESMEM);
    cudaFuncSetAttribute(gemm_av_mma, cudaFuncAttributeMaxDynamicSharedMemorySize, VSMEM);

    split_convert<<<OUT_ELEMS / 4 / 256, 256>>>(x, p_xhi, p_xlo, OUT_ELEMS / 4);
    dim3 wt4(32, 32, 4), wb(32, 8);
    wtrans_convert4<<<wt4, wb>>>(Wq, Wk, Wv, Wo);

    dim3 gq(24, 32);
    gemm_qkv<<<gq, 256, GSMEM>>>(bq, bk, bv);

    dim3 ge(64, BH);   // 16 rows/CTA
    attn_entmax_mma<<<ge, 256, ESMEM>>>(attn_ptr, p_phi, p_plo);

    dim3 ga(8, BH);
    gemm_av_mma<<<ga, 256, VSMEM>>>(p_phi, p_plo);

    dim3 gg(8, 32);
    gemm_out<<<gg, 256, GSMEM>>>(bo, out_ptr);
}

// round 13
// speedup vs baseline: 1.4857x; 1.0874x over previous
#include <cuda_runtime.h>
#include <cuda_bf16.h>
#include <cstdint>

#define BATCH 4
#define SEQ   1024
#define CH    1024
#define HEADS 16
#define DH    64
#define TOKENS (BATCH * SEQ)
#define BH (BATCH * HEADS)
#define OUT_ELEMS (TOKENS * CH)

#define BISECT_ITERS 12
#define SOLVE_ITERS 3
#define SCALE 0.0625f   // (1/sqrt(64)) * (alpha-1)

// bf16 split scratch
__device__ __nv_bfloat16 g_xhi[TOKENS * CH];
__device__ __nv_bfloat16 g_xlo[TOKENS * CH];
__device__ __nv_bfloat16 g_wthi[4 * CH * CH];
__device__ __nv_bfloat16 g_wtlo[4 * CH * CH];
__device__ __nv_bfloat16 g_qhi[BH * SEQ * DH];
__device__ __nv_bfloat16 g_qlo[BH * SEQ * DH];
__device__ __nv_bfloat16 g_khi[BH * SEQ * DH];
__device__ __nv_bfloat16 g_klo[BH * SEQ * DH];
__device__ __nv_bfloat16 g_vthi[BH * DH * SEQ];   // transposed V: [bh][dh][tok]
__device__ __nv_bfloat16 g_vtlo[BH * DH * SEQ];
__device__ __nv_bfloat16 g_chi[TOKENS * CH];
__device__ __nv_bfloat16 g_clo[TOKENS * CH];

// ===================== PTX helpers =========================================
__device__ __forceinline__ uint32_t smem_u32(const void* p) {
    uint32_t a;
    asm("{ .reg .u64 t; cvta.to.shared.u64 t, %1; cvt.u32.u64 %0, t; }" : "=r"(a) : "l"(p));
    return a;
}
#define CP_ASYNC16(sa, g) \
    asm volatile("cp.async.cg.shared.global [%0], [%1], 16;" :: "r"(sa), "l"(g))
#define CP_COMMIT() asm volatile("cp.async.commit_group;" ::: "memory")
#define CP_WAIT0() asm volatile("cp.async.wait_group 0;" ::: "memory")
#define CP_WAIT1() asm volatile("cp.async.wait_group 1;" ::: "memory")
#define LDSM4(r0, r1, r2, r3, addr) \
    asm volatile("ldmatrix.sync.aligned.m8n8.x4.shared.b16 {%0,%1,%2,%3}, [%4];" \
        : "=r"(r0), "=r"(r1), "=r"(r2), "=r"(r3) : "r"(addr))
#define MMA16816(d, a, b0, b1) \
    asm volatile("mma.sync.aligned.m16n8k16.row.col.f32.bf16.bf16.f32 " \
        "{%0,%1,%2,%3}, {%4,%5,%6,%7}, {%8,%9}, {%0,%1,%2,%3};" \
        : "+f"((d)[0]), "+f"((d)[1]), "+f"((d)[2]), "+f"((d)[3]) \
        : "r"((a)[0]), "r"((a)[1]), "r"((a)[2]), "r"((a)[3]), "r"(b0), "r"(b1))

__device__ __forceinline__ void split1(float v, __nv_bfloat16& h, __nv_bfloat16& l) {
    h = __float2bfloat16_rn(v);
    l = __float2bfloat16_rn(v - __bfloat162float(h));
}
__device__ __forceinline__ uint32_t pack2(__nv_bfloat16 a, __nv_bfloat16 b) {
    __nv_bfloat162 t; t.x = a; t.y = b;
    return *reinterpret_cast<uint32_t*>(&t);
}
__device__ __forceinline__ float sum8(const float* base, int row) {
    float4 a = ((const float4*)base)[row * 2];
    float4 b = ((const float4*)base)[row * 2 + 1];
    return ((a.x + a.y) + (a.z + a.w)) + ((b.x + b.y) + (b.z + b.w));
}
__device__ __forceinline__ float max8(const float* base, int row) {
    float4 a = ((const float4*)base)[row * 2];
    float4 b = ((const float4*)base)[row * 2 + 1];
    return fmaxf(fmaxf(fmaxf(a.x, a.y), fmaxf(a.z, a.w)),
                 fmaxf(fmaxf(b.x, b.y), fmaxf(b.z, b.w)));
}

// ===================== convert kernels =====================================
__global__ __launch_bounds__(256) void split_convert(
    const float* __restrict__ in, __nv_bfloat16* __restrict__ hi,
    __nv_bfloat16* __restrict__ lo, int n4)
{
    int i = blockIdx.x * 256 + threadIdx.x;
    if (i >= n4) return;
    float4 v = ((const float4*)in)[i];
    union { ushort u[4]; uint2 q; } H, L;
    float a[4] = {v.x, v.y, v.z, v.w};
#pragma unroll
    for (int j = 0; j < 4; j++) {
        __nv_bfloat16 h, l; split1(a[j], h, l);
        H.u[j] = __bfloat16_as_ushort(h);
        L.u[j] = __bfloat16_as_ushort(l);
    }
    ((uint2*)hi)[i] = H.q;
    ((uint2*)lo)[i] = L.q;
}

__global__ __launch_bounds__(256) void wtrans_convert4(
    const float* __restrict__ W0, const float* __restrict__ W1,
    const float* __restrict__ W2, const float* __restrict__ W3)
{
    __shared__ float t[32][33];
    int tx = threadIdx.x, ty = threadIdx.y;
    int bx = blockIdx.x, by = blockIdx.y, bz = blockIdx.z;
    const float* W = (bz == 0) ? W0 : (bz == 1) ? W1 : (bz == 2) ? W2 : W3;
    __nv_bfloat16* hi = g_wthi + (size_t)bz * 1048576;
    __nv_bfloat16* lo = g_wtlo + (size_t)bz * 1048576;
#pragma unroll
    for (int i = 0; i < 4; i++)
        t[ty + i * 8][tx] = W[(size_t)(by * 32 + ty + i * 8) * 1024 + bx * 32 + tx];
    __syncthreads();
#pragma unroll
    for (int i = 0; i < 4; i++) {
        float v = t[tx][ty + i * 8];
        __nv_bfloat16 h, l; split1(v, h, l);
        size_t o = (size_t)(bx * 32 + ty + i * 8) * 1024 + by * 32 + tx;
        hi[o] = h;
        lo[o] = l;
    }
}

// ===================== GEMM core ===========================================
#define GSTAGE 32768
#define GSMEM (2 * GSTAGE)

__device__ __forceinline__ void gemm_mainloop(
    uint32_t sb, int tid, int wm, int wn,
    const __nv_bfloat16* Ah, const __nv_bfloat16* Al,
    const __nv_bfloat16* Bh, const __nv_bfloat16* Bl,
    float acc[4][4][4])
{
    int lane = tid & 31;
    const __nv_bfloat16* gsrc[4] = { Ah, Al, Bh, Bl };
    int l_row0 = tid >> 2,         l_c0 = tid & 3;
    int l_row1 = (tid + 256) >> 2, l_c1 = (tid + 256) & 3;

    auto load_stage = [&](int kt, int s) {
        uint32_t sbase = sb + s * GSTAGE;
#pragma unroll
        for (int t = 0; t < 4; t++) {
            const char* g0 = (const char*)(gsrc[t] + (size_t)l_row0 * 1024 + kt * 32) + l_c0 * 16;
            const char* g1 = (const char*)(gsrc[t] + (size_t)l_row1 * 1024 + kt * 32) + l_c1 * 16;
            uint32_t s0 = sbase + t * 8192 + l_row0 * 64 + ((l_c0 ^ (l_row0 & 3)) * 16);
            uint32_t s1 = sbase + t * 8192 + l_row1 * 64 + ((l_c1 ^ (l_row1 & 3)) * 16);
            CP_ASYNC16(s0, g0);
            CP_ASYNC16(s1, g1);
        }
        CP_COMMIT();
    };

    int arow = (lane & 7) | (((lane >> 3) & 1) << 3);
    int asel = lane >> 4;
    int brow = (lane & 7) | ((lane >> 4) << 3);
    int bsel = (lane >> 3) & 1;

    load_stage(0, 0);
    load_stage(1, 1);

#pragma unroll 1
    for (int t = 0; t < 32; t++) {
        if (t >= 31) { CP_WAIT0(); } else { CP_WAIT1(); }
        __syncthreads();

        uint32_t base = sb + (t & 1) * GSTAGE;
        uint32_t Ahb = base, Alb = base + 8192, Bhb = base + 16384, Blb = base + 24576;

#pragma unroll
        for (int ks = 0; ks < 2; ks++) {
            int akc = ks * 2 + asel;
            int bkc = ks * 2 + bsel;
            uint32_t ah[4][4], al[4][4], bhf[2][4], blf[2][4];
#pragma unroll
            for (int mt = 0; mt < 4; mt++) {
                int row = wm * 64 + mt * 16 + arow;
                uint32_t off = row * 64 + ((akc ^ (row & 3)) * 16);
                LDSM4(ah[mt][0], ah[mt][1], ah[mt][2], ah[mt][3], Ahb + off);
            }
#pragma unroll
            for (int nt = 0; nt < 2; nt++) {
                int row = wn * 32 + nt * 16 + brow;
                uint32_t off = row * 64 + ((bkc ^ (row & 3)) * 16);
                LDSM4(bhf[nt][0], bhf[nt][1], bhf[nt][2], bhf[nt][3], Bhb + off);
            }
#pragma unroll
            for (int mt = 0; mt < 4; mt++)
#pragma unroll
                for (int nt = 0; nt < 2; nt++) {
                    MMA16816(acc[mt][nt * 2 + 0], ah[mt], bhf[nt][0], bhf[nt][1]);
                    MMA16816(acc[mt][nt * 2 + 1], ah[mt], bhf[nt][2], bhf[nt][3]);
                }
#pragma unroll
            for (int nt = 0; nt < 2; nt++) {
                int row = wn * 32 + nt * 16 + brow;
                uint32_t off = row * 64 + ((bkc ^ (row & 3)) * 16);
                LDSM4(blf[nt][0], blf[nt][1], blf[nt][2], blf[nt][3], Blb + off);
            }
#pragma unroll
            for (int mt = 0; mt < 4; mt++)
#pragma unroll
                for (int nt = 0; nt < 2; nt++) {
                    MMA16816(acc[mt][nt * 2 + 0], ah[mt], blf[nt][0], blf[nt][1]);
                    MMA16816(acc[mt][nt * 2 + 1], ah[mt], blf[nt][2], blf[nt][3]);
                }
#pragma unroll
            for (int mt = 0; mt < 4; mt++) {
                int row = wm * 64 + mt * 16 + arow;
                uint32_t off = row * 64 + ((akc ^ (row & 3)) * 16);
                LDSM4(al[mt][0], al[mt][1], al[mt][2], al[mt][3], Alb + off);
            }
#pragma unroll
            for (int mt = 0; mt < 4; mt++)
#pragma unroll
                for (int nt = 0; nt < 2; nt++) {
                    MMA16816(acc[mt][nt * 2 + 0], al[mt], bhf[nt][0], bhf[nt][1]);
                    MMA16816(acc[mt][nt * 2 + 1], al[mt], bhf[nt][2], bhf[nt][3]);
                }
        }
        __syncthreads();
        if (t + 2 < 32) load_stage(t + 2, t & 1);
    }
}

// Fused QKV projection: grid (24, 32). bx 0-7 -> Q, 8-15 -> K, 16-23 -> V.
__global__ __launch_bounds__(256, 2) void gemm_qkv(
    const float* __restrict__ bq, const float* __restrict__ bk,
    const float* __restrict__ bv)
{
    extern __shared__ char sm[];
    uint32_t sb = smem_u32(sm);
    int tid = threadIdx.x, lane = tid & 31, wid = tid >> 5;
    int wm = wid >> 2, wn = wid & 3;
    int widx = blockIdx.x >> 3;
    int n0 = (blockIdx.x & 7) * 128;
    int m0 = blockIdx.y * 128;

    const float* bias = (widx == 0) ? bq : (widx == 1) ? bk : bv;
    const __nv_bfloat16* Bh = g_wthi + (size_t)widx * 1048576 + (size_t)n0 * 1024;
    const __nv_bfloat16* Bl = g_wtlo + (size_t)widx * 1048576 + (size_t)n0 * 1024;

    float acc[4][4][4];
#pragma unroll
    for (int a = 0; a < 4; a++)
#pragma unroll
        for (int b = 0; b < 4; b++)
#pragma unroll
            for (int c = 0; c < 4; c++) acc[a][b][c] = 0.0f;

    gemm_mainloop(sb, tid, wm, wn,
                  g_xhi + (size_t)m0 * 1024, g_xlo + (size_t)m0 * 1024, Bh, Bl, acc);

    int r = lane >> 2, c2 = (lane & 3) * 2;
    __nv_bfloat16* dhi = (widx == 0) ? g_qhi : (widx == 1) ? g_khi : g_vthi;
    __nv_bfloat16* dlo = (widx == 0) ? g_qlo : (widx == 1) ? g_klo : g_vtlo;
#pragma unroll
    for (int mt = 0; mt < 4; mt++) {
        int mrow = m0 + wm * 64 + mt * 16 + r;
        int bidx = mrow >> 10, ntok = mrow & 1023;
#pragma unroll
        for (int nt8 = 0; nt8 < 4; nt8++) {
            int col = n0 + wn * 32 + nt8 * 8 + c2;
            float b0 = bias[col], b1 = bias[col + 1];
            float v00 = acc[mt][nt8][0] + b0, v01 = acc[mt][nt8][1] + b1;
            float v10 = acc[mt][nt8][2] + b0, v11 = acc[mt][nt8][3] + b1;
            int h = col >> 6, dh = col & 63;
            if (widx < 2) {
                size_t base = ((size_t)(bidx * HEADS + h) * SEQ + ntok) * DH + dh;
                __nv_bfloat16 h0, l0, h1, l1;
                split1(v00, h0, l0); split1(v01, h1, l1);
                *(__nv_bfloat162*)(dhi + base) = {h0, h1};
                *(__nv_bfloat162*)(dlo + base) = {l0, l1};
                split1(v10, h0, l0); split1(v11, h1, l1);
                *(__nv_bfloat162*)(dhi + base + 8 * DH) = {h0, h1};
                *(__nv_bfloat162*)(dlo + base + 8 * DH) = {l0, l1};
            } else {
                size_t vb = ((size_t)(bidx * HEADS + h) * DH + dh) * SEQ + ntok;
                __nv_bfloat16 hh, ll;
                split1(v00, hh, ll); dhi[vb] = hh; dlo[vb] = ll;
                split1(v01, hh, ll); dhi[vb + SEQ] = hh; dlo[vb + SEQ] = ll;
                split1(v10, hh, ll); dhi[vb + 8] = hh; dlo[vb + 8] = ll;
                split1(v11, hh, ll); dhi[vb + SEQ + 8] = hh; dlo[vb + SEQ + 8] = ll;
            }
        }
    }
}

// Output projection: ctx_split @ Wo^T + bo -> fp32 out
__global__ __launch_bounds__(256, 2) void gemm_out(
    const float* __restrict__ bias, float* __restrict__ dstf)
{
    extern __shared__ char sm[];
    uint32_t sb = smem_u32(sm);
    int tid = threadIdx.x, lane = tid & 31, wid = tid >> 5;
    int wm = wid >> 2, wn = wid & 3;
    int n0 = blockIdx.x * 128, m0 = blockIdx.y * 128;

    float acc[4][4][4];
#pragma unroll
    for (int a = 0; a < 4; a++)
#pragma unroll
        for (int b = 0; b < 4; b++)
#pragma unroll
            for (int c = 0; c < 4; c++) acc[a][b][c] = 0.0f;

    gemm_mainloop(sb, tid, wm, wn,
                  g_chi + (size_t)m0 * 1024, g_clo + (size_t)m0 * 1024,
                  g_wthi + 3u * 1048576 + (size_t)n0 * 1024,
                  g_wtlo + 3u * 1048576 + (size_t)n0 * 1024, acc);

    int r = lane >> 2, c2 = (lane & 3) * 2;
#pragma unroll
    for (int mt = 0; mt < 4; mt++) {
        int mrow = m0 + wm * 64 + mt * 16 + r;
#pragma unroll
        for (int nt8 = 0; nt8 < 4; nt8++) {
            int col = n0 + wn * 32 + nt8 * 8 + c2;
            float b0 = bias[col], b1 = bias[col + 1];
            float* p = dstf + (size_t)mrow * CH + col;
            *(float2*)p = {acc[mt][nt8][0] + b0, acc[mt][nt8][1] + b1};
            *(float2*)(p + 8 * CH) = {acc[mt][nt8][2] + b0, acc[mt][nt8][3] + b1};
        }
    }
}

// ===================== fused HMMA scores + entmax + P@V ====================
// 256 thr = 8 warps, 16 q-rows/CTA, 2 CTAs/SM. QK: warp w owns 16-col tile w
// per 128-kv chunk. P@V fused: acc fragments ARE the A fragments; V streamed
// through the dead K smem; cross-warp 16x64 reduction -> ctx split.
#define EOFF_QH 0
#define EOFF_QL 2048
#define EOFF_K  4096
#define EOFF_RED (4096 + 2 * 32768)
#define ESMEM (EOFF_RED + 2 * 384 * 4)

__global__ __launch_bounds__(256, 2) void attn_entmax_mma(float* __restrict__ attn)
{
    extern __shared__ char sm[];
    uint32_t sb = smem_u32(sm);
    float* RED = (float*)(sm + EOFF_RED);   // [2][384]

    int tid = threadIdx.x, lane = tid & 31, wid = tid >> 5;   // wid 0..7
    int bh = blockIdx.y;
    int R0 = blockIdx.x * 16;

    {   // Q: 16 rows x 8 u x {hi,lo} = 256 chunks, 1/thread
        int hl = tid >> 7;
        int row = (tid >> 3) & 15;
        int u = tid & 7;
        const __nv_bfloat16* src = (hl ? g_qlo : g_qhi) + ((size_t)bh * SEQ + R0 + row) * DH + u * 8;
        uint32_t d = sb + EOFF_QH + hl * 2048 + row * 128 + ((u ^ (row & 7)) * 16);
        CP_ASYNC16(d, src);
    }
    auto loadK = [&](int c, int s) {
        uint32_t base = sb + EOFF_K + s * 32768;
#pragma unroll
        for (int i = 0; i < 8; i++) {
            int idx = tid + i * 256;
            int hl = idx >> 10;
            int row = (idx >> 3) & 127;
            int u = idx & 7;
            const __nv_bfloat16* src = (hl ? g_klo : g_khi) + ((size_t)bh * SEQ + c * 128 + row) * DH + u * 8;
            uint32_t d = base + hl * 16384 + row * 128 + ((u ^ (row & 7)) * 16);
            CP_ASYNC16(d, src);
        }
        CP_COMMIT();
    };
    // V chunk: [2 hl][2 planes of 64 kv][64 dh rows][64 bf16] -> 32KB/stage
    auto loadV = [&](int c, int s) {
        uint32_t base = sb + EOFF_K + s * 32768;
#pragma unroll
        for (int i = 0; i < 8; i++) {
            int idx = tid + i * 256;
            int hl = idx >> 10;
            int plane = (idx >> 9) & 1;
            int row = (idx >> 3) & 63;
            int u = idx & 7;
            const __nv_bfloat16* src = (hl ? g_vtlo : g_vthi)
                + (size_t)bh * DH * SEQ + (size_t)row * SEQ + c * 128 + plane * 64 + u * 8;
            uint32_t d = base + hl * 16384 + plane * 8192 + row * 128 + ((u ^ (row & 7)) * 16);
            CP_ASYNC16(d, src);
        }
        CP_COMMIT();
    };
    loadK(0, 0);
    loadK(1, 1);

    float acc[16][4];
#pragma unroll
    for (int t = 0; t < 16; t++)
#pragma unroll
        for (int e = 0; e < 4; e++) acc[t][e] = 0.0f;

    int arow_ = (lane & 7) | (((lane >> 3) & 1) << 3);
    int asel = lane >> 4;
    int brow_ = (lane & 7) | ((lane >> 4) << 3);
    int bsel = (lane >> 3) & 1;
    int krow_ = wid * 16 + brow_;
    uint32_t QHb = sb + EOFF_QH, QLb = sb + EOFF_QL;

#pragma unroll
    for (int c = 0; c < 8; c++) {
        if (c >= 7) { CP_WAIT0(); } else { CP_WAIT1(); }
        __syncthreads();
        uint32_t KHb = sb + EOFF_K + (c & 1) * 32768;
        uint32_t KLb = KHb + 16384;
#pragma unroll
        for (int kc = 0; kc < 4; kc++) {
            uint32_t au = (uint32_t)(kc * 2 + asel);
            uint32_t aoff = arow_ * 128 + ((au ^ (arow_ & 7)) * 16);
            uint32_t ah[4], al[4];
            LDSM4(ah[0], ah[1], ah[2], ah[3], QHb + aoff);
            LDSM4(al[0], al[1], al[2], al[3], QLb + aoff);
            uint32_t bu = (uint32_t)(kc * 2 + bsel);
            uint32_t boff = krow_ * 128 + ((bu ^ (krow_ & 7)) * 16);
            uint32_t bh4[4], bl4[4];
            LDSM4(bh4[0], bh4[1], bh4[2], bh4[3], KHb + boff);
            LDSM4(bl4[0], bl4[1], bl4[2], bl4[3], KLb + boff);
            MMA16816(acc[2 * c + 0], ah, bh4[0], bh4[1]);
            MMA16816(acc[2 * c + 1], ah, bh4[2], bh4[3]);
            MMA16816(acc[2 * c + 0], ah, bl4[0], bl4[1]);
            MMA16816(acc[2 * c + 1], ah, bl4[2], bl4[3]);
            MMA16816(acc[2 * c + 0], al, bh4[0], bh4[1]);
            MMA16816(acc[2 * c + 1], al, bh4[2], bh4[3]);
            MMA16816(acc[2 * c + 0], al, bl4[0], bl4[1]);
            MMA16816(acc[2 * c + 1], al, bl4[2], bl4[3]);
        }
        __syncthreads();
        if (c + 2 < 8) loadK(c + 2, c & 1);
    }

    // Prefetch V chunks 0,1 into the (dead) K stages; they land while the
    // entmax iterations run below.
    loadV(0, 0);
    loadV(1, 1);

    // --- entmax (rows 0..15), redundant all-thread reductions ---
    int r0 = lane >> 2;
    int r1 = r0 + 8;
    bool qlead = (lane & 3) == 0;
    int par = 0;

#pragma unroll
    for (int t = 0; t < 16; t++)
#pragma unroll
        for (int e = 0; e < 4; e++) acc[t][e] *= SCALE;

    // Phase A: row max
    float tloA, tloB;
    {
        float mA = -1e30f, mB = -1e30f;
#pragma unroll
        for (int t = 0; t < 16; t++) {
            mA = fmaxf(mA, fmaxf(acc[t][0], acc[t][1]));
            mB = fmaxf(mB, fmaxf(acc[t][2], acc[t][3]));
        }
        mA = fmaxf(mA, __shfl_xor_sync(0xffffffffu, mA, 1));
        mA = fmaxf(mA, __shfl_xor_sync(0xffffffffu, mA, 2));
        mB = fmaxf(mB, __shfl_xor_sync(0xffffffffu, mB, 1));
        mB = fmaxf(mB, __shfl_xor_sync(0xffffffffu, mB, 2));
        float* RP = RED + par * 384;
        if (qlead) { RP[r0 * 8 + wid] = mA; RP[r1 * 8 + wid] = mB; }
        __syncthreads();
        tloA = max8(RP, r0) - 1.0f;
        tloB = max8(RP, r1) - 1.0f;
        par ^= 1;
    }

    // Phase B: f_lo
    float flA, flB;
    {
        float c0 = 0.f, c1 = 0.f, c2 = 0.f, c3 = 0.f;
#pragma unroll
        for (int t = 0; t < 16; t++) {
            float u;
            u = fmaxf(acc[t][0] - tloA, 0.f); c0 = fmaf(u, u, c0);
            u = fmaxf(acc[t][1] - tloA, 0.f); c1 = fmaf(u, u, c1);
            u = fmaxf(acc[t][2] - tloB, 0.f); c2 = fmaf(u, u, c2);
            u = fmaxf(acc[t][3] - tloB, 0.f); c3 = fmaf(u, u, c3);
        }
        float vA = c0 + c1, vB = c2 + c3;
        vA += __shfl_xor_sync(0xffffffffu, vA, 1);
        vA += __shfl_xor_sync(0xffffffffu, vA, 2);
        vB += __shfl_xor_sync(0xffffffffu, vB, 1);
        vB += __shfl_xor_sync(0xffffffffu, vB, 2);
        float* RP = RED + par * 384;
        if (qlead) { RP[r0 * 8 + wid] = vA; RP[r1 * 8 + wid] = vB; }
        __syncthreads();
        flA = sum8(RP, r0) - 1.0f;
        flB = sum8(RP, r1) - 1.0f;
        par ^= 1;
    }

    float dm = 0.484375f;
    float tmA = tloA + dm, tmB = tloB + dm;

    // Phase C: bisection
#pragma unroll 1
    for (int it = 0; it < BISECT_ITERS; it++) {
        float c0 = 0.f, c1 = 0.f, c2 = 0.f, c3 = 0.f;
#pragma unroll
        for (int t = 0; t < 16; t++) {
            float u;
            u = fmaxf(acc[t][0] - tmA, 0.f); c0 = fmaf(u, u, c0);
            u = fmaxf(acc[t][1] - tmA, 0.f); c1 = fmaf(u, u, c1);
            u = fmaxf(acc[t][2] - tmB, 0.f); c2 = fmaf(u, u, c2);
            u = fmaxf(acc[t][3] - tmB, 0.f); c3 = fmaf(u, u, c3);
        }
        float vA = c0 + c1, vB = c2 + c3;
        vA += __shfl_xor_sync(0xffffffffu, vA, 1);
        vA += __shfl_xor_sync(0xffffffffu, vA, 2);
        vB += __shfl_xor_sync(0xffffffffu, vB, 1);
        vB += __shfl_xor_sync(0xffffffffu, vB, 2);
        float* RP = RED + par * 384;
        if (qlead) { RP[r0 * 8 + wid] = vA; RP[r1 * 8 + wid] = vB; }
        __syncthreads();
        float fmA = sum8(RP, r0) - 1.0f;
        float fmB = sum8(RP, r1) - 1.0f;
        if (fmA * flA >= 0.f) tloA = tmA;
        if (fmB * flB >= 0.f) tloB = tmB;
        if (it < BISECT_ITERS - 1) {
            dm *= 0.5f;
            tmA = tloA + dm;
            tmB = tloB + dm;
        }
        par ^= 1;
    }

    // Phase D: analytic support-fixpoint solves
#pragma unroll 1
    for (int ps = 0; ps < SOLVE_ITERS; ps++) {
        float nA = 0.f, s1A = 0.f, s2A = 0.f;
        float nB = 0.f, s1B = 0.f, s2B = 0.f;
#pragma unroll
        for (int t = 0; t < 16; t++) {
#pragma unroll
            for (int e = 0; e < 2; e++) {
                float a = acc[t][e];
                if (a > tmA) { nA += 1.f; s1A += a; s2A = fmaf(a, a, s2A); }
                float b = acc[t][e + 2];
                if (b > tmB) { nB += 1.f; s1B += b; s2B = fmaf(b, b, s2B); }
            }
        }
#pragma unroll
        for (int o = 1; o <= 2; o <<= 1) {
            nA += __shfl_xor_sync(0xffffffffu, nA, o);
            s1A += __shfl_xor_sync(0xffffffffu, s1A, o);
            s2A += __shfl_xor_sync(0xffffffffu, s2A, o);
            nB += __shfl_xor_sync(0xffffffffu, nB, o);
            s1B += __shfl_xor_sync(0xffffffffu, s1B, o);
            s2B += __shfl_xor_sync(0xffffffffu, s2B, o);
        }
        float* RP = RED + par * 384;
        if (qlead) {
            RP[r0 * 8 + wid] = nA;        RP[r1 * 8 + wid] = nB;
            RP[128 + r0 * 8 + wid] = s1A; RP[128 + r1 * 8 + wid] = s1B;
            RP[256 + r0 * 8 + wid] = s2A; RP[256 + r1 * 8 + wid] = s2B;
        }
        __syncthreads();
        {
            float n = sum8(RP, r0), s1 = sum8(RP + 128, r0), s2 = sum8(RP + 256, r0);
            float D = fmaxf(fmaf(s1, s1, -n * (s2 - 1.0f)), 0.f);
            tmA = (s1 - sqrtf(D)) / n;
            n = sum8(RP, r1); s1 = sum8(RP + 128, r1); s2 = sum8(RP + 256, r1);
            D = fmaxf(fmaf(s1, s1, -n * (s2 - 1.0f)), 0.f);
            tmB = (s1 - sqrtf(D)) / n;
        }
        par ^= 1;
    }

    // Phase E: final p + normalize
    float ivA, ivB;
    {
        float c0 = 0.f, c1 = 0.f, c2 = 0.f, c3 = 0.f;
#pragma unroll
        for (int t = 0; t < 16; t++) {
            float u;
            u = fmaxf(acc[t][0] - tmA, 0.f); acc[t][0] = u * u; c0 += acc[t][0];
            u = fmaxf(acc[t][1] - tmA, 0.f); acc[t][1] = u * u; c1 += acc[t][1];
            u = fmaxf(acc[t][2] - tmB, 0.f); acc[t][2] = u * u; c2 += acc[t][2];
            u = fmaxf(acc[t][3] - tmB, 0.f); acc[t][3] = u * u; c3 += acc[t][3];
        }
        float vA = c0 + c1, vB = c2 + c3;
        vA += __shfl_xor_sync(0xffffffffu, vA, 1);
        vA += __shfl_xor_sync(0xffffffffu, vA, 2);
        vB += __shfl_xor_sync(0xffffffffu, vB, 1);
        vB += __shfl_xor_sync(0xffffffffu, vB, 2);
        float* RP = RED + par * 384;
        if (qlead) { RP[r0 * 8 + wid] = vA; RP[r1 * 8 + wid] = vB; }
        __syncthreads();
        ivA = 1.0f / sum8(RP, r0);
        ivB = 1.0f / sum8(RP, r1);
    }

    // normalize in-register, write attn fp32, pack p -> bf16 split A-fragments
    uint32_t pH[16][2], pL[16][2];
    {
        size_t rb0 = ((size_t)bh * SEQ + R0 + r0) * SEQ + wid * 16 + (lane & 3) * 2;
        size_t rb1 = ((size_t)bh * SEQ + R0 + r1) * SEQ + wid * 16 + (lane & 3) * 2;
#pragma unroll
        for (int t = 0; t < 16; t++) {
            int off = (t >> 1) * 128 + (t & 1) * 8;
            float p0 = acc[t][0] * ivA, p1 = acc[t][1] * ivA;
            float p2 = acc[t][2] * ivB, p3 = acc[t][3] * ivB;
            *(float2*)(attn + rb0 + off) = {p0, p1};
            *(float2*)(attn + rb1 + off) = {p2, p3};
            __nv_bfloat16 h0, l0, h1, l1;
            split1(p0, h0, l0); split1(p1, h1, l1);
            pH[t][0] = pack2(h0, h1);
            pL[t][0] = pack2(l0, l1);
            split1(p2, h0, l0); split1(p3, h1, l1);
            pH[t][1] = pack2(h0, h1);
            pL[t][1] = pack2(l0, l1);
        }
    }

    // --- fused P@V: ctx[16 x 64] = P[16 x 1024] @ V[1024 x 64] (3-term) ---
    float cacc[8][4];
#pragma unroll
    for (int n8 = 0; n8 < 8; n8++)
#pragma unroll
        for (int e = 0; e < 4; e++) cacc[n8][e] = 0.0f;

    int vplane = wid >> 2;
    uint32_t vku = (uint32_t)((wid & 3) * 2 + bsel);

#pragma unroll
    for (int v = 0; v < 8; v++) {
        if (v >= 7) { CP_WAIT0(); } else { CP_WAIT1(); }
        __syncthreads();
        uint32_t VHb = sb + EOFF_K + (v & 1) * 32768;
        uint32_t VLb = VHb + 16384;
        uint32_t pa_h[4] = { pH[2 * v][0], pH[2 * v][1], pH[2 * v + 1][0], pH[2 * v + 1][1] };
        uint32_t pa_l[4] = { pL[2 * v][0], pL[2 * v][1], pL[2 * v + 1][0], pL[2 * v + 1][1] };
#pragma unroll
        for (int nt = 0; nt < 4; nt++) {
            int row = nt * 16 + brow_;
            uint32_t off = vplane * 8192 + row * 128 + ((vku ^ (row & 7)) * 16);
            uint32_t vh[4], vl[4];
            LDSM4(vh[0], vh[1], vh[2], vh[3], VHb + off);
            LDSM4(vl[0], vl[1], vl[2], vl[3], VLb + off);
            MMA16816(cacc[nt * 2 + 0], pa_h, vh[0], vh[1]);
            MMA16816(cacc[nt * 2 + 1], pa_h, vh[2], vh[3]);
            MMA16816(cacc[nt * 2 + 0], pa_h, vl[0], vl[1]);
            MMA16816(cacc[nt * 2 + 1], pa_h, vl[2], vl[3]);
            MMA16816(cacc[nt * 2 + 0], pa_l, vh[0], vh[1]);
            MMA16816(cacc[nt * 2 + 1], pa_l, vh[2], vh[3]);
        }
        __syncthreads();
        if (v + 2 < 8) loadV(v + 2, v & 1);
    }

    // cross-warp reduction: 8 partials of [16][64] -> ctx split
    float* PART = (float*)(sm + EOFF_K);   // 32KB, stage-0 region (dead)
#pragma unroll
    for (int n8 = 0; n8 < 8; n8++) {
        int dh = (n8 >> 1) * 16 + (n8 & 1) * 8 + (lane & 3) * 2;
        *(float2*)&PART[wid * 1024 + r0 * 64 + dh] = {cacc[n8][0], cacc[n8][1]};
        *(float2*)&PART[wid * 1024 + r1 * 64 + dh] = {cacc[n8][2], cacc[n8][3]};
    }
    __syncthreads();
    {
        int r = tid >> 4, d4 = (tid & 15) * 4;
        float4 s = {0.f, 0.f, 0.f, 0.f};
#pragma unroll
        for (int w = 0; w < 8; w++) {
            float4 t4 = *(float4*)&PART[w * 1024 + r * 64 + d4];
            s.x += t4.x; s.y += t4.y; s.z += t4.z; s.w += t4.w;
        }
        int bidx = bh >> 4, h = bh & 15;
        size_t o = (size_t)(bidx * SEQ + R0 + r) * CH + h * DH + d4;
        __nv_bfloat16 h0, l0, h1, l1, h2, l2, h3, l3;
        split1(s.x, h0, l0); split1(s.y, h1, l1);
        split1(s.z, h2, l2); split1(s.w, h3, l3);
        *(__nv_bfloat162*)(g_chi + o)     = {h0, h1};
        *(__nv_bfloat162*)(g_chi + o + 2) = {h2, h3};
        *(__nv_bfloat162*)(g_clo + o)     = {l0, l1};
        *(__nv_bfloat162*)(g_clo + o + 2) = {l2, l3};
    }
}

// ---------------------------------------------------------------------------
extern "C" void kernel_launch(void* const* d_in, const int* in_sizes, int n_in,
                              void* d_out, int out_size)
{
    const float* x  = (const float*)d_in[0];
    const float* Wq = (const float*)d_in[1];
    const float* bq = (const float*)d_in[2];
    const float* Wk = (const float*)d_in[3];
    const float* bk = (const float*)d_in[4];
    const float* Wv = (const float*)d_in[5];
    const float* bv = (const float*)d_in[6];
    const float* Wo = (const float*)d_in[7];
    const float* bo = (const float*)d_in[8];

    float* out_ptr  = (float*)d_out;
    float* attn_ptr = out_ptr + OUT_ELEMS;

    __nv_bfloat16 *p_xhi, *p_xlo;
    cudaGetSymbolAddress((void**)&p_xhi, g_xhi);
    cudaGetSymbolAddress((void**)&p_xlo, g_xlo);

    cudaFuncSetAttribute(gemm_qkv, cudaFuncAttributeMaxDynamicSharedMemorySize, GSMEM);
    cudaFuncSetAttribute(gemm_out, cudaFuncAttributeMaxDynamicSharedMemorySize, GSMEM);
    cudaFuncSetAttribute(attn_entmax_mma, cudaFuncAttributeMaxDynamicSharedMemorySize, ESMEM);

    split_convert<<<OUT_ELEMS / 4 / 256, 256>>>(x, p_xhi, p_xlo, OUT_ELEMS / 4);
    dim3 wt4(32, 32, 4), wb(32, 8);
    wtrans_convert4<<<wt4, wb>>>(Wq, Wk, Wv, Wo);

    dim3 gq(24, 32);
    gemm_qkv<<<gq, 256, GSMEM>>>(bq, bk, bv);

    dim3 ge(64, BH);   // 16 rows/CTA
    attn_entmax_mma<<<ge, 256, ESMEM>>>(attn_ptr);

    dim3 gg(8, 32);
    gemm_out<<<gg, 256, GSMEM>>>(bo, out_ptr);
}

// round 14
// speedup vs baseline: 1.5702x; 1.0569x over previous
#include <cuda_runtime.h>
#include <cuda_bf16.h>
#include <cstdint>

#define BATCH 4
#define SEQ   1024
#define CH    1024
#define HEADS 16
#define DH    64
#define TOKENS (BATCH * SEQ)
#define BH (BATCH * HEADS)
#define OUT_ELEMS (TOKENS * CH)

#define BISECT_ITERS 8
#define SOLVE_ITERS 3
#define SCALE 0.0625f   // (1/sqrt(64)) * (alpha-1)

// bf16 split scratch
__device__ __nv_bfloat16 g_xhi[TOKENS * CH];
__device__ __nv_bfloat16 g_xlo[TOKENS * CH];
__device__ __nv_bfloat16 g_wthi[4 * CH * CH];
__device__ __nv_bfloat16 g_wtlo[4 * CH * CH];
__device__ __nv_bfloat16 g_qhi[BH * SEQ * DH];
__device__ __nv_bfloat16 g_qlo[BH * SEQ * DH];
__device__ __nv_bfloat16 g_khi[BH * SEQ * DH];
__device__ __nv_bfloat16 g_klo[BH * SEQ * DH];
__device__ __nv_bfloat16 g_vthi[BH * DH * SEQ];   // transposed V: [bh][dh][tok]
__device__ __nv_bfloat16 g_vtlo[BH * DH * SEQ];
__device__ __nv_bfloat16 g_chi[TOKENS * CH];
__device__ __nv_bfloat16 g_clo[TOKENS * CH];

// ===================== PTX helpers =========================================
__device__ __forceinline__ uint32_t smem_u32(const void* p) {
    uint32_t a;
    asm("{ .reg .u64 t; cvta.to.shared.u64 t, %1; cvt.u32.u64 %0, t; }" : "=r"(a) : "l"(p));
    return a;
}
#define CP_ASYNC16(sa, g) \
    asm volatile("cp.async.cg.shared.global [%0], [%1], 16;" :: "r"(sa), "l"(g))
#define CP_COMMIT() asm volatile("cp.async.commit_group;" ::: "memory")
#define CP_WAIT0() asm volatile("cp.async.wait_group 0;" ::: "memory")
#define CP_WAIT1() asm volatile("cp.async.wait_group 1;" ::: "memory")
#define LDSM4(r0, r1, r2, r3, addr) \
    asm volatile("ldmatrix.sync.aligned.m8n8.x4.shared.b16 {%0,%1,%2,%3}, [%4];" \
        : "=r"(r0), "=r"(r1), "=r"(r2), "=r"(r3) : "r"(addr))
#define MMA16816(d, a, b0, b1) \
    asm volatile("mma.sync.aligned.m16n8k16.row.col.f32.bf16.bf16.f32 " \
        "{%0,%1,%2,%3}, {%4,%5,%6,%7}, {%8,%9}, {%0,%1,%2,%3};" \
        : "+f"((d)[0]), "+f"((d)[1]), "+f"((d)[2]), "+f"((d)[3]) \
        : "r"((a)[0]), "r"((a)[1]), "r"((a)[2]), "r"((a)[3]), "r"(b0), "r"(b1))

__device__ __forceinline__ void split1(float v, __nv_bfloat16& h, __nv_bfloat16& l) {
    h = __float2bfloat16_rn(v);
    l = __float2bfloat16_rn(v - __bfloat162float(h));
}
__device__ __forceinline__ uint32_t pack2(__nv_bfloat16 a, __nv_bfloat16 b) {
    __nv_bfloat162 t; t.x = a; t.y = b;
    return *reinterpret_cast<uint32_t*>(&t);
}
__device__ __forceinline__ float sum8(const float* base, int row) {
    float4 a = ((const float4*)base)[row * 2];
    float4 b = ((const float4*)base)[row * 2 + 1];
    return ((a.x + a.y) + (a.z + a.w)) + ((b.x + b.y) + (b.z + b.w));
}
__device__ __forceinline__ float max8(const float* base, int row) {
    float4 a = ((const float4*)base)[row * 2];
    float4 b = ((const float4*)base)[row * 2 + 1];
    return fmaxf(fmaxf(fmaxf(a.x, a.y), fmaxf(a.z, a.w)),
                 fmaxf(fmaxf(b.x, b.y), fmaxf(b.z, b.w)));
}

// ===================== convert kernels =====================================
__global__ __launch_bounds__(256) void split_convert(
    const float* __restrict__ in, __nv_bfloat16* __restrict__ hi,
    __nv_bfloat16* __restrict__ lo, int n4)
{
    int i = blockIdx.x * 256 + threadIdx.x;
    if (i >= n4) return;
    float4 v = ((const float4*)in)[i];
    union { ushort u[4]; uint2 q; } H, L;
    float a[4] = {v.x, v.y, v.z, v.w};
#pragma unroll
    for (int j = 0; j < 4; j++) {
        __nv_bfloat16 h, l; split1(a[j], h, l);
        H.u[j] = __bfloat16_as_ushort(h);
        L.u[j] = __bfloat16_as_ushort(l);
    }
    ((uint2*)hi)[i] = H.q;
    ((uint2*)lo)[i] = L.q;
}

__global__ __launch_bounds__(256) void wtrans_convert4(
    const float* __restrict__ W0, const float* __restrict__ W1,
    const float* __restrict__ W2, const float* __restrict__ W3)
{
    __shared__ float t[32][33];
    int tx = threadIdx.x, ty = threadIdx.y;
    int bx = blockIdx.x, by = blockIdx.y, bz = blockIdx.z;
    const float* W = (bz == 0) ? W0 : (bz == 1) ? W1 : (bz == 2) ? W2 : W3;
    __nv_bfloat16* hi = g_wthi + (size_t)bz * 1048576;
    __nv_bfloat16* lo = g_wtlo + (size_t)bz * 1048576;
#pragma unroll
    for (int i = 0; i < 4; i++)
        t[ty + i * 8][tx] = W[(size_t)(by * 32 + ty + i * 8) * 1024 + bx * 32 + tx];
    __syncthreads();
#pragma unroll
    for (int i = 0; i < 4; i++) {
        float v = t[tx][ty + i * 8];
        __nv_bfloat16 h, l; split1(v, h, l);
        size_t o = (size_t)(bx * 32 + ty + i * 8) * 1024 + by * 32 + tx;
        hi[o] = h;
        lo[o] = l;
    }
}

// ===================== GEMM core ===========================================
#define GSTAGE 32768
#define GSMEM (2 * GSTAGE)

__device__ __forceinline__ void gemm_mainloop(
    uint32_t sb, int tid, int wm, int wn,
    const __nv_bfloat16* Ah, const __nv_bfloat16* Al,
    const __nv_bfloat16* Bh, const __nv_bfloat16* Bl,
    float acc[4][4][4])
{
    int lane = tid & 31;
    const __nv_bfloat16* gsrc[4] = { Ah, Al, Bh, Bl };
    int l_row0 = tid >> 2,         l_c0 = tid & 3;
    int l_row1 = (tid + 256) >> 2, l_c1 = (tid + 256) & 3;

    auto load_stage = [&](int kt, int s) {
        uint32_t sbase = sb + s * GSTAGE;
#pragma unroll
        for (int t = 0; t < 4; t++) {
            const char* g0 = (const char*)(gsrc[t] + (size_t)l_row0 * 1024 + kt * 32) + l_c0 * 16;
            const char* g1 = (const char*)(gsrc[t] + (size_t)l_row1 * 1024 + kt * 32) + l_c1 * 16;
            uint32_t s0 = sbase + t * 8192 + l_row0 * 64 + ((l_c0 ^ (l_row0 & 3)) * 16);
            uint32_t s1 = sbase + t * 8192 + l_row1 * 64 + ((l_c1 ^ (l_row1 & 3)) * 16);
            CP_ASYNC16(s0, g0);
            CP_ASYNC16(s1, g1);
        }
        CP_COMMIT();
    };

    int arow = (lane & 7) | (((lane >> 3) & 1) << 3);
    int asel = lane >> 4;
    int brow = (lane & 7) | ((lane >> 4) << 3);
    int bsel = (lane >> 3) & 1;

    load_stage(0, 0);
    load_stage(1, 1);

#pragma unroll 1
    for (int t = 0; t < 32; t++) {
        if (t >= 31) { CP_WAIT0(); } else { CP_WAIT1(); }
        __syncthreads();

        uint32_t base = sb + (t & 1) * GSTAGE;
        uint32_t Ahb = base, Alb = base + 8192, Bhb = base + 16384, Blb = base + 24576;

#pragma unroll
        for (int ks = 0; ks < 2; ks++) {
            int akc = ks * 2 + asel;
            int bkc = ks * 2 + bsel;
            uint32_t ah[4][4], al[4][4], bhf[2][4], blf[2][4];
#pragma unroll
            for (int mt = 0; mt < 4; mt++) {
                int row = wm * 64 + mt * 16 + arow;
                uint32_t off = row * 64 + ((akc ^ (row & 3)) * 16);
                LDSM4(ah[mt][0], ah[mt][1], ah[mt][2], ah[mt][3], Ahb + off);
            }
#pragma unroll
            for (int nt = 0; nt < 2; nt++) {
                int row = wn * 32 + nt * 16 + brow;
                uint32_t off = row * 64 + ((bkc ^ (row & 3)) * 16);
                LDSM4(bhf[nt][0], bhf[nt][1], bhf[nt][2], bhf[nt][3], Bhb + off);
            }
#pragma unroll
            for (int mt = 0; mt < 4; mt++)
#pragma unroll
                for (int nt = 0; nt < 2; nt++) {
                    MMA16816(acc[mt][nt * 2 + 0], ah[mt], bhf[nt][0], bhf[nt][1]);
                    MMA16816(acc[mt][nt * 2 + 1], ah[mt], bhf[nt][2], bhf[nt][3]);
                }
#pragma unroll
            for (int nt = 0; nt < 2; nt++) {
                int row = wn * 32 + nt * 16 + brow;
                uint32_t off = row * 64 + ((bkc ^ (row & 3)) * 16);
                LDSM4(blf[nt][0], blf[nt][1], blf[nt][2], blf[nt][3], Blb + off);
            }
#pragma unroll
            for (int mt = 0; mt < 4; mt++)
#pragma unroll
                for (int nt = 0; nt < 2; nt++) {
                    MMA16816(acc[mt][nt * 2 + 0], ah[mt], blf[nt][0], blf[nt][1]);
                    MMA16816(acc[mt][nt * 2 + 1], ah[mt], blf[nt][2], blf[nt][3]);
                }
#pragma unroll
            for (int mt = 0; mt < 4; mt++) {
                int row = wm * 64 + mt * 16 + arow;
                uint32_t off = row * 64 + ((akc ^ (row & 3)) * 16);
                LDSM4(al[mt][0], al[mt][1], al[mt][2], al[mt][3], Alb + off);
            }
#pragma unroll
            for (int mt = 0; mt < 4; mt++)
#pragma unroll
                for (int nt = 0; nt < 2; nt++) {
                    MMA16816(acc[mt][nt * 2 + 0], al[mt], bhf[nt][0], bhf[nt][1]);
                    MMA16816(acc[mt][nt * 2 + 1], al[mt], bhf[nt][2], bhf[nt][3]);
                }
        }
        __syncthreads();
        if (t + 2 < 32) load_stage(t + 2, t & 1);
    }
}

// Fused QKV projection: grid (24, 32). bx 0-7 -> Q, 8-15 -> K, 16-23 -> V.
__global__ __launch_bounds__(256, 2) void gemm_qkv(
    const float* __restrict__ bq, const float* __restrict__ bk,
    const float* __restrict__ bv)
{
    extern __shared__ char sm[];
    uint32_t sb = smem_u32(sm);
    int tid = threadIdx.x, lane = tid & 31, wid = tid >> 5;
    int wm = wid >> 2, wn = wid & 3;
    int widx = blockIdx.x >> 3;
    int n0 = (blockIdx.x & 7) * 128;
    int m0 = blockIdx.y * 128;

    const float* bias = (widx == 0) ? bq : (widx == 1) ? bk : bv;
    const __nv_bfloat16* Bh = g_wthi + (size_t)widx * 1048576 + (size_t)n0 * 1024;
    const __nv_bfloat16* Bl = g_wtlo + (size_t)widx * 1048576 + (size_t)n0 * 1024;

    float acc[4][4][4];
#pragma unroll
    for (int a = 0; a < 4; a++)
#pragma unroll
        for (int b = 0; b < 4; b++)
#pragma unroll
            for (int c = 0; c < 4; c++) acc[a][b][c] = 0.0f;

    gemm_mainloop(sb, tid, wm, wn,
                  g_xhi + (size_t)m0 * 1024, g_xlo + (size_t)m0 * 1024, Bh, Bl, acc);

    int r = lane >> 2, c2 = (lane & 3) * 2;
    __nv_bfloat16* dhi = (widx == 0) ? g_qhi : (widx == 1) ? g_khi : g_vthi;
    __nv_bfloat16* dlo = (widx == 0) ? g_qlo : (widx == 1) ? g_klo : g_vtlo;
#pragma unroll
    for (int mt = 0; mt < 4; mt++) {
        int mrow = m0 + wm * 64 + mt * 16 + r;
        int bidx = mrow >> 10, ntok = mrow & 1023;
#pragma unroll
        for (int nt8 = 0; nt8 < 4; nt8++) {
            int col = n0 + wn * 32 + nt8 * 8 + c2;
            float b0 = bias[col], b1 = bias[col + 1];
            float v00 = acc[mt][nt8][0] + b0, v01 = acc[mt][nt8][1] + b1;
            float v10 = acc[mt][nt8][2] + b0, v11 = acc[mt][nt8][3] + b1;
            int h = col >> 6, dh = col & 63;
            if (widx < 2) {
                size_t base = ((size_t)(bidx * HEADS + h) * SEQ + ntok) * DH + dh;
                __nv_bfloat16 h0, l0, h1, l1;
                split1(v00, h0, l0); split1(v01, h1, l1);
                *(__nv_bfloat162*)(dhi + base) = {h0, h1};
                *(__nv_bfloat162*)(dlo + base) = {l0, l1};
                split1(v10, h0, l0); split1(v11, h1, l1);
                *(__nv_bfloat162*)(dhi + base + 8 * DH) = {h0, h1};
                *(__nv_bfloat162*)(dlo + base + 8 * DH) = {l0, l1};
            } else {
                size_t vb = ((size_t)(bidx * HEADS + h) * DH + dh) * SEQ + ntok;
                __nv_bfloat16 hh, ll;
                split1(v00, hh, ll); dhi[vb] = hh; dlo[vb] = ll;
                split1(v01, hh, ll); dhi[vb + SEQ] = hh; dlo[vb + SEQ] = ll;
                split1(v10, hh, ll); dhi[vb + 8] = hh; dlo[vb + 8] = ll;
                split1(v11, hh, ll); dhi[vb + SEQ + 8] = hh; dlo[vb + SEQ + 8] = ll;
            }
        }
    }
}

// Output projection: ctx_split @ Wo^T + bo -> fp32 out
__global__ __launch_bounds__(256, 2) void gemm_out(
    const float* __restrict__ bias, float* __restrict__ dstf)
{
    extern __shared__ char sm[];
    uint32_t sb = smem_u32(sm);
    int tid = threadIdx.x, lane = tid & 31, wid = tid >> 5;
    int wm = wid >> 2, wn = wid & 3;
    int n0 = blockIdx.x * 128, m0 = blockIdx.y * 128;

    float acc[4][4][4];
#pragma unroll
    for (int a = 0; a < 4; a++)
#pragma unroll
        for (int b = 0; b < 4; b++)
#pragma unroll
            for (int c = 0; c < 4; c++) acc[a][b][c] = 0.0f;

    gemm_mainloop(sb, tid, wm, wn,
                  g_chi + (size_t)m0 * 1024, g_clo + (size_t)m0 * 1024,
                  g_wthi + 3u * 1048576 + (size_t)n0 * 1024,
                  g_wtlo + 3u * 1048576 + (size_t)n0 * 1024, acc);

    int r = lane >> 2, c2 = (lane & 3) * 2;
#pragma unroll
    for (int mt = 0; mt < 4; mt++) {
        int mrow = m0 + wm * 64 + mt * 16 + r;
#pragma unroll
        for (int nt8 = 0; nt8 < 4; nt8++) {
            int col = n0 + wn * 32 + nt8 * 8 + c2;
            float b0 = bias[col], b1 = bias[col + 1];
            float* p = dstf + (size_t)mrow * CH + col;
            *(float2*)p = {acc[mt][nt8][0] + b0, acc[mt][nt8][1] + b1};
            *(float2*)(p + 8 * CH) = {acc[mt][nt8][2] + b0, acc[mt][nt8][3] + b1};
        }
    }
}

// ===================== fused HMMA scores + entmax + P@V ====================
#define EOFF_QH 0
#define EOFF_QL 2048
#define EOFF_K  4096
#define EOFF_RED (4096 + 2 * 32768)
#define ESMEM (EOFF_RED + 2 * 384 * 4)

__global__ __launch_bounds__(256, 2) void attn_entmax_mma(float* __restrict__ attn)
{
    extern __shared__ char sm[];
    uint32_t sb = smem_u32(sm);
    float* RED = (float*)(sm + EOFF_RED);   // [2][384]

    int tid = threadIdx.x, lane = tid & 31, wid = tid >> 5;
    int bh = blockIdx.y;
    int R0 = blockIdx.x * 16;

    {   // Q: 16 rows x 8 u x {hi,lo} = 256 chunks, 1/thread
        int hl = tid >> 7;
        int row = (tid >> 3) & 15;
        int u = tid & 7;
        const __nv_bfloat16* src = (hl ? g_qlo : g_qhi) + ((size_t)bh * SEQ + R0 + row) * DH + u * 8;
        uint32_t d = sb + EOFF_QH + hl * 2048 + row * 128 + ((u ^ (row & 7)) * 16);
        CP_ASYNC16(d, src);
    }
    auto loadK = [&](int c, int s) {
        uint32_t base = sb + EOFF_K + s * 32768;
#pragma unroll
        for (int i = 0; i < 8; i++) {
            int idx = tid + i * 256;
            int hl = idx >> 10;
            int row = (idx >> 3) & 127;
            int u = idx & 7;
            const __nv_bfloat16* src = (hl ? g_klo : g_khi) + ((size_t)bh * SEQ + c * 128 + row) * DH + u * 8;
            uint32_t d = base + hl * 16384 + row * 128 + ((u ^ (row & 7)) * 16);
            CP_ASYNC16(d, src);
        }
        CP_COMMIT();
    };
    auto loadV = [&](int c, int s) {
        uint32_t base = sb + EOFF_K + s * 32768;
#pragma unroll
        for (int i = 0; i < 8; i++) {
            int idx = tid + i * 256;
            int hl = idx >> 10;
            int plane = (idx >> 9) & 1;
            int row = (idx >> 3) & 63;
            int u = idx & 7;
            const __nv_bfloat16* src = (hl ? g_vtlo : g_vthi)
                + (size_t)bh * DH * SEQ + (size_t)row * SEQ + c * 128 + plane * 64 + u * 8;
            uint32_t d = base + hl * 16384 + plane * 8192 + row * 128 + ((u ^ (row & 7)) * 16);
            CP_ASYNC16(d, src);
        }
        CP_COMMIT();
    };
    loadK(0, 0);
    loadK(1, 1);

    float acc[16][4];
#pragma unroll
    for (int t = 0; t < 16; t++)
#pragma unroll
        for (int e = 0; e < 4; e++) acc[t][e] = 0.0f;

    int arow_ = (lane & 7) | (((lane >> 3) & 1) << 3);
    int asel = lane >> 4;
    int brow_ = (lane & 7) | ((lane >> 4) << 3);
    int bsel = (lane >> 3) & 1;
    int krow_ = wid * 16 + brow_;
    uint32_t QHb = sb + EOFF_QH, QLb = sb + EOFF_QL;

#pragma unroll
    for (int c = 0; c < 8; c++) {
        if (c >= 7) { CP_WAIT0(); } else { CP_WAIT1(); }
        __syncthreads();
        uint32_t KHb = sb + EOFF_K + (c & 1) * 32768;
        uint32_t KLb = KHb + 16384;
#pragma unroll
        for (int kc = 0; kc < 4; kc++) {
            uint32_t au = (uint32_t)(kc * 2 + asel);
            uint32_t aoff = arow_ * 128 + ((au ^ (arow_ & 7)) * 16);
            uint32_t ah[4], al[4];
            LDSM4(ah[0], ah[1], ah[2], ah[3], QHb + aoff);
            LDSM4(al[0], al[1], al[2], al[3], QLb + aoff);
            uint32_t bu = (uint32_t)(kc * 2 + bsel);
            uint32_t boff = krow_ * 128 + ((bu ^ (krow_ & 7)) * 16);
            uint32_t bh4[4], bl4[4];
            LDSM4(bh4[0], bh4[1], bh4[2], bh4[3], KHb + boff);
            LDSM4(bl4[0], bl4[1], bl4[2], bl4[3], KLb + boff);
            MMA16816(acc[2 * c + 0], ah, bh4[0], bh4[1]);
            MMA16816(acc[2 * c + 1], ah, bh4[2], bh4[3]);
            MMA16816(acc[2 * c + 0], ah, bl4[0], bl4[1]);
            MMA16816(acc[2 * c + 1], ah, bl4[2], bl4[3]);
            MMA16816(acc[2 * c + 0], al, bh4[0], bh4[1]);
            MMA16816(acc[2 * c + 1], al, bh4[2], bh4[3]);
            MMA16816(acc[2 * c + 0], al, bl4[0], bl4[1]);
            MMA16816(acc[2 * c + 1], al, bl4[2], bl4[3]);
        }
        __syncthreads();
        if (c + 2 < 8) loadK(c + 2, c & 1);
    }

    // Prefetch V chunks 0,1; land during entmax iterations.
    loadV(0, 0);
    loadV(1, 1);

    // --- entmax (rows 0..15), redundant all-thread reductions ---
    int r0 = lane >> 2;
    int r1 = r0 + 8;
    bool qlead = (lane & 3) == 0;
    int par = 0;

#pragma unroll
    for (int t = 0; t < 16; t++)
#pragma unroll
        for (int e = 0; e < 4; e++) acc[t][e] *= SCALE;

    // Phase A: row max
    float tloA, tloB;
    {
        float mA = -1e30f, mB = -1e30f;
#pragma unroll
        for (int t = 0; t < 16; t++) {
            mA = fmaxf(mA, fmaxf(acc[t][0], acc[t][1]));
            mB = fmaxf(mB, fmaxf(acc[t][2], acc[t][3]));
        }
        mA = fmaxf(mA, __shfl_xor_sync(0xffffffffu, mA, 1));
        mA = fmaxf(mA, __shfl_xor_sync(0xffffffffu, mA, 2));
        mB = fmaxf(mB, __shfl_xor_sync(0xffffffffu, mB, 1));
        mB = fmaxf(mB, __shfl_xor_sync(0xffffffffu, mB, 2));
        float* RP = RED + par * 384;
        if (qlead) { RP[r0 * 8 + wid] = mA; RP[r1 * 8 + wid] = mB; }
        __syncthreads();
        tloA = max8(RP, r0) - 1.0f;
        tloB = max8(RP, r1) - 1.0f;
        par ^= 1;
    }

    // (Phase B dropped: f_lo >= 0 analytically, so the bisection test
    //  f_m * f_lo >= 0 reduces to f_m >= 0.)

    float dm = 0.484375f;
    float tmA = tloA + dm, tmB = tloB + dm;

    // Phase C: bisection
#pragma unroll 1
    for (int it = 0; it < BISECT_ITERS; it++) {
        float c0 = 0.f, c1 = 0.f, c2 = 0.f, c3 = 0.f;
#pragma unroll
        for (int t = 0; t < 16; t++) {
            float u;
            u = fmaxf(acc[t][0] - tmA, 0.f); c0 = fmaf(u, u, c0);
            u = fmaxf(acc[t][1] - tmA, 0.f); c1 = fmaf(u, u, c1);
            u = fmaxf(acc[t][2] - tmB, 0.f); c2 = fmaf(u, u, c2);
            u = fmaxf(acc[t][3] - tmB, 0.f); c3 = fmaf(u, u, c3);
        }
        float vA = c0 + c1, vB = c2 + c3;
        vA += __shfl_xor_sync(0xffffffffu, vA, 1);
        vA += __shfl_xor_sync(0xffffffffu, vA, 2);
        vB += __shfl_xor_sync(0xffffffffu, vB, 1);
        vB += __shfl_xor_sync(0xffffffffu, vB, 2);
        float* RP = RED + par * 384;
        if (qlead) { RP[r0 * 8 + wid] = vA; RP[r1 * 8 + wid] = vB; }
        __syncthreads();
        float fmA = sum8(RP, r0) - 1.0f;
        float fmB = sum8(RP, r1) - 1.0f;
        if (fmA >= 0.f) tloA = tmA;
        if (fmB >= 0.f) tloB = tmB;
        if (it < BISECT_ITERS - 1) {
            dm *= 0.5f;
            tmA = tloA + dm;
            tmB = tloB + dm;
        }
        par ^= 1;
    }

    // Phase D: analytic support-fixpoint solves
#pragma unroll 1
    for (int ps = 0; ps < SOLVE_ITERS; ps++) {
        float nA = 0.f, s1A = 0.f, s2A = 0.f;
        float nB = 0.f, s1B = 0.f, s2B = 0.f;
#pragma unroll
        for (int t = 0; t < 16; t++) {
#pragma unroll
            for (int e = 0; e < 2; e++) {
                float a = acc[t][e];
                if (a > tmA) { nA += 1.f; s1A += a; s2A = fmaf(a, a, s2A); }
                float b = acc[t][e + 2];
                if (b > tmB) { nB += 1.f; s1B += b; s2B = fmaf(b, b, s2B); }
            }
        }
#pragma unroll
        for (int o = 1; o <= 2; o <<= 1) {
            nA += __shfl_xor_sync(0xffffffffu, nA, o);
            s1A += __shfl_xor_sync(0xffffffffu, s1A, o);
            s2A += __shfl_xor_sync(0xffffffffu, s2A, o);
            nB += __shfl_xor_sync(0xffffffffu, nB, o);
            s1B += __shfl_xor_sync(0xffffffffu, s1B, o);
            s2B += __shfl_xor_sync(0xffffffffu, s2B, o);
        }
        float* RP = RED + par * 384;
        if (qlead) {
            RP[r0 * 8 + wid] = nA;        RP[r1 * 8 + wid] = nB;
            RP[128 + r0 * 8 + wid] = s1A; RP[128 + r1 * 8 + wid] = s1B;
            RP[256 + r0 * 8 + wid] = s2A; RP[256 + r1 * 8 + wid] = s2B;
        }
        __syncthreads();
        {
            float n = sum8(RP, r0), s1 = sum8(RP + 128, r0), s2 = sum8(RP + 256, r0);
            float D = fmaxf(fmaf(s1, s1, -n * (s2 - 1.0f)), 0.f);
            tmA = (s1 - sqrtf(D)) / n;
            n = sum8(RP, r1); s1 = sum8(RP + 128, r1); s2 = sum8(RP + 256, r1);
            D = fmaxf(fmaf(s1, s1, -n * (s2 - 1.0f)), 0.f);
            tmB = (s1 - sqrtf(D)) / n;
        }
        par ^= 1;
    }

    // Phase E: final p + normalize
    float ivA, ivB;
    {
        float c0 = 0.f, c1 = 0.f, c2 = 0.f, c3 = 0.f;
#pragma unroll
        for (int t = 0; t < 16; t++) {
            float u;
            u = fmaxf(acc[t][0] - tmA, 0.f); acc[t][0] = u * u; c0 += acc[t][0];
            u = fmaxf(acc[t][1] - tmA, 0.f); acc[t][1] = u * u; c1 += acc[t][1];
            u = fmaxf(acc[t][2] - tmB, 0.f); acc[t][2] = u * u; c2 += acc[t][2];
            u = fmaxf(acc[t][3] - tmB, 0.f); acc[t][3] = u * u; c3 += acc[t][3];
        }
        float vA = c0 + c1, vB = c2 + c3;
        vA += __shfl_xor_sync(0xffffffffu, vA, 1);
        vA += __shfl_xor_sync(0xffffffffu, vA, 2);
        vB += __shfl_xor_sync(0xffffffffu, vB, 1);
        vB += __shfl_xor_sync(0xffffffffu, vB, 2);
        float* RP = RED + par * 384;
        if (qlead) { RP[r0 * 8 + wid] = vA; RP[r1 * 8 + wid] = vB; }
        __syncthreads();
        ivA = 1.0f / sum8(RP, r0);
        ivB = 1.0f / sum8(RP, r1);
    }

    // normalize in-register, write attn fp32, pack p -> bf16 split A-fragments
    uint32_t pH[16][2], pL[16][2];
    {
        size_t rb0 = ((size_t)bh * SEQ + R0 + r0) * SEQ + wid * 16 + (lane & 3) * 2;
        size_t rb1 = ((size_t)bh * SEQ + R0 + r1) * SEQ + wid * 16 + (lane & 3) * 2;
#pragma unroll
        for (int t = 0; t < 16; t++) {
            int off = (t >> 1) * 128 + (t & 1) * 8;
            float p0 = acc[t][0] * ivA, p1 = acc[t][1] * ivA;
            float p2 = acc[t][2] * ivB, p3 = acc[t][3] * ivB;
            *(float2*)(attn + rb0 + off) = {p0, p1};
            *(float2*)(attn + rb1 + off) = {p2, p3};
            __nv_bfloat16 h0, l0, h1, l1;
            split1(p0, h0, l0); split1(p1, h1, l1);
            pH[t][0] = pack2(h0, h1);
            pL[t][0] = pack2(l0, l1);
            split1(p2, h0, l0); split1(p3, h1, l1);
            pH[t][1] = pack2(h0, h1);
            pL[t][1] = pack2(l0, l1);
        }
    }

    // --- fused P@V: ctx[16 x 64] = P[16 x 1024] @ V[1024 x 64] (3-term) ---
    float cacc[8][4];
#pragma unroll
    for (int n8 = 0; n8 < 8; n8++)
#pragma unroll
        for (int e = 0; e < 4; e++) cacc[n8][e] = 0.0f;

    int vplane = wid >> 2;
    uint32_t vku = (uint32_t)((wid & 3) * 2 + bsel);

#pragma unroll
    for (int v = 0; v < 8; v++) {
        if (v >= 7) { CP_WAIT0(); } else { CP_WAIT1(); }
        __syncthreads();
        uint32_t VHb = sb + EOFF_K + (v & 1) * 32768;
        uint32_t VLb = VHb + 16384;
        uint32_t pa_h[4] = { pH[2 * v][0], pH[2 * v][1], pH[2 * v + 1][0], pH[2 * v + 1][1] };
        uint32_t pa_l[4] = { pL[2 * v][0], pL[2 * v][1], pL[2 * v + 1][0], pL[2 * v + 1][1] };
#pragma unroll
        for (int nt = 0; nt < 4; nt++) {
            int row = nt * 16 + brow_;
            uint32_t off = vplane * 8192 + row * 128 + ((vku ^ (row & 7)) * 16);
            uint32_t vh[4], vl[4];
            LDSM4(vh[0], vh[1], vh[2], vh[3], VHb + off);
            LDSM4(vl[0], vl[1], vl[2], vl[3], VLb + off);
            MMA16816(cacc[nt * 2 + 0], pa_h, vh[0], vh[1]);
            MMA16816(cacc[nt * 2 + 1], pa_h, vh[2], vh[3]);
            MMA16816(cacc[nt * 2 + 0], pa_h, vl[0], vl[1]);
            MMA16816(cacc[nt * 2 + 1], pa_h, vl[2], vl[3]);
            MMA16816(cacc[nt * 2 + 0], pa_l, vh[0], vh[1]);
            MMA16816(cacc[nt * 2 + 1], pa_l, vh[2], vh[3]);
        }
        __syncthreads();
        if (v + 2 < 8) loadV(v + 2, v & 1);
    }

    // cross-warp reduction: 8 partials of [16][64] -> ctx split
    float* PART = (float*)(sm + EOFF_K);
#pragma unroll
    for (int n8 = 0; n8 < 8; n8++) {
        int dh = (n8 >> 1) * 16 + (n8 & 1) * 8 + (lane & 3) * 2;
        *(float2*)&PART[wid * 1024 + r0 * 64 + dh] = {cacc[n8][0], cacc[n8][1]};
        *(float2*)&PART[wid * 1024 + r1 * 64 + dh] = {cacc[n8][2], cacc[n8][3]};
    }
    __syncthreads();
    {
        int r = tid >> 4, d4 = (tid & 15) * 4;
        float4 s = {0.f, 0.f, 0.f, 0.f};
#pragma unroll
        for (int w = 0; w < 8; w++) {
            float4 t4 = *(float4*)&PART[w * 1024 + r * 64 + d4];
            s.x += t4.x; s.y += t4.y; s.z += t4.z; s.w += t4.w;
        }
        int bidx = bh >> 4, h = bh & 15;
        size_t o = (size_t)(bidx * SEQ + R0 + r) * CH + h * DH + d4;
        __nv_bfloat16 h0, l0, h1, l1, h2, l2, h3, l3;
        split1(s.x, h0, l0); split1(s.y, h1, l1);
        split1(s.z, h2, l2); split1(s.w, h3, l3);
        *(__nv_bfloat162*)(g_chi + o)     = {h0, h1};
        *(__nv_bfloat162*)(g_chi + o + 2) = {h2, h3};
        *(__nv_bfloat162*)(g_clo + o)     = {l0, l1};
        *(__nv_bfloat162*)(g_clo + o + 2) = {l2, l3};
    }
}

// ---------------------------------------------------------------------------
extern "C" void kernel_launch(void* const* d_in, const int* in_sizes, int n_in,
                              void* d_out, int out_size)
{
    const float* x  = (const float*)d_in[0];
    const float* Wq = (const float*)d_in[1];
    const float* bq = (const float*)d_in[2];
    const float* Wk = (const float*)d_in[3];
    const float* bk = (const float*)d_in[4];
    const float* Wv = (const float*)d_in[5];
    const float* bv = (const float*)d_in[6];
    const float* Wo = (const float*)d_in[7];
    const float* bo = (const float*)d_in[8];

    float* out_ptr  = (float*)d_out;
    float* attn_ptr = out_ptr + OUT_ELEMS;

    __nv_bfloat16 *p_xhi, *p_xlo;
    cudaGetSymbolAddress((void**)&p_xhi, g_xhi);
    cudaGetSymbolAddress((void**)&p_xlo, g_xlo);

    cudaFuncSetAttribute(gemm_qkv, cudaFuncAttributeMaxDynamicSharedMemorySize, GSMEM);
    cudaFuncSetAttribute(gemm_out, cudaFuncAttributeMaxDynamicSharedMemorySize, GSMEM);
    cudaFuncSetAttribute(attn_entmax_mma, cudaFuncAttributeMaxDynamicSharedMemorySize, ESMEM);

    split_convert<<<OUT_ELEMS / 4 / 256, 256>>>(x, p_xhi, p_xlo, OUT_ELEMS / 4);
    dim3 wt4(32, 32, 4), wb(32, 8);
    wtrans_convert4<<<wt4, wb>>>(Wq, Wk, Wv, Wo);

    dim3 gq(24, 32);
    gemm_qkv<<<gq, 256, GSMEM>>>(bq, bk, bv);

    dim3 ge(64, BH);
    attn_entmax_mma<<<ge, 256, ESMEM>>>(attn_ptr);

    dim3 gg(8, 32);
    gemm_out<<<gg, 256, GSMEM>>>(bo, out_ptr);
}

// round 15
// speedup vs baseline: 1.6069x; 1.0234x over previous
#include <cuda_runtime.h>
#include <cuda_bf16.h>
#include <cstdint>

#define BATCH 4
#define SEQ   1024
#define CH    1024
#define HEADS 16
#define DH    64
#define TOKENS (BATCH * SEQ)
#define BH (BATCH * HEADS)
#define OUT_ELEMS (TOKENS * CH)

#define BISECT_ITERS 8
#define SOLVE_ITERS 2
#define SCALE 0.0625f   // (1/sqrt(64)) * (alpha-1)

// bf16 split scratch
__device__ __nv_bfloat16 g_xhi[TOKENS * CH];
__device__ __nv_bfloat16 g_xlo[TOKENS * CH];
__device__ __nv_bfloat16 g_wthi[4 * CH * CH];
__device__ __nv_bfloat16 g_wtlo[4 * CH * CH];
__device__ __nv_bfloat16 g_qhi[BH * SEQ * DH];
__device__ __nv_bfloat16 g_qlo[BH * SEQ * DH];
__device__ __nv_bfloat16 g_khi[BH * SEQ * DH];
__device__ __nv_bfloat16 g_klo[BH * SEQ * DH];
__device__ __nv_bfloat16 g_vthi[BH * DH * SEQ];   // transposed V: [bh][dh][tok]
__device__ __nv_bfloat16 g_vtlo[BH * DH * SEQ];
__device__ __nv_bfloat16 g_chi[TOKENS * CH];
__device__ __nv_bfloat16 g_clo[TOKENS * CH];

// ===================== PTX helpers =========================================
__device__ __forceinline__ uint32_t smem_u32(const void* p) {
    uint32_t a;
    asm("{ .reg .u64 t; cvta.to.shared.u64 t, %1; cvt.u32.u64 %0, t; }" : "=r"(a) : "l"(p));
    return a;
}
#define CP_ASYNC16(sa, g) \
    asm volatile("cp.async.cg.shared.global [%0], [%1], 16;" :: "r"(sa), "l"(g))
#define CP_COMMIT() asm volatile("cp.async.commit_group;" ::: "memory")
#define CP_WAIT0() asm volatile("cp.async.wait_group 0;" ::: "memory")
#define CP_WAIT1() asm volatile("cp.async.wait_group 1;" ::: "memory")
#define LDSM4(r0, r1, r2, r3, addr) \
    asm volatile("ldmatrix.sync.aligned.m8n8.x4.shared.b16 {%0,%1,%2,%3}, [%4];" \
        : "=r"(r0), "=r"(r1), "=r"(r2), "=r"(r3) : "r"(addr))
#define MMA16816(d, a, b0, b1) \
    asm volatile("mma.sync.aligned.m16n8k16.row.col.f32.bf16.bf16.f32 " \
        "{%0,%1,%2,%3}, {%4,%5,%6,%7}, {%8,%9}, {%0,%1,%2,%3};" \
        : "+f"((d)[0]), "+f"((d)[1]), "+f"((d)[2]), "+f"((d)[3]) \
        : "r"((a)[0]), "r"((a)[1]), "r"((a)[2]), "r"((a)[3]), "r"(b0), "r"(b1))

__device__ __forceinline__ void split1(float v, __nv_bfloat16& h, __nv_bfloat16& l) {
    h = __float2bfloat16_rn(v);
    l = __float2bfloat16_rn(v - __bfloat162float(h));
}
__device__ __forceinline__ uint32_t pack2(__nv_bfloat16 a, __nv_bfloat16 b) {
    __nv_bfloat162 t; t.x = a; t.y = b;
    return *reinterpret_cast<uint32_t*>(&t);
}
__device__ __forceinline__ float sum8(const float* base, int row) {
    float4 a = ((const float4*)base)[row * 2];
    float4 b = ((const float4*)base)[row * 2 + 1];
    return ((a.x + a.y) + (a.z + a.w)) + ((b.x + b.y) + (b.z + b.w));
}
__device__ __forceinline__ float max8(const float* base, int row) {
    float4 a = ((const float4*)base)[row * 2];
    float4 b = ((const float4*)base)[row * 2 + 1];
    return fmaxf(fmaxf(fmaxf(a.x, a.y), fmaxf(a.z, a.w)),
                 fmaxf(fmaxf(b.x, b.y), fmaxf(b.z, b.w)));
}

// ===================== convert kernels =====================================
__global__ __launch_bounds__(256) void split_convert(
    const float* __restrict__ in, __nv_bfloat16* __restrict__ hi,
    __nv_bfloat16* __restrict__ lo, int n4)
{
    int i = blockIdx.x * 256 + threadIdx.x;
    if (i >= n4) return;
    float4 v = ((const float4*)in)[i];
    union { ushort u[4]; uint2 q; } H, L;
    float a[4] = {v.x, v.y, v.z, v.w};
#pragma unroll
    for (int j = 0; j < 4; j++) {
        __nv_bfloat16 h, l; split1(a[j], h, l);
        H.u[j] = __bfloat16_as_ushort(h);
        L.u[j] = __bfloat16_as_ushort(l);
    }
    ((uint2*)hi)[i] = H.q;
    ((uint2*)lo)[i] = L.q;
}

__global__ __launch_bounds__(256) void wtrans_convert4(
    const float* __restrict__ W0, const float* __restrict__ W1,
    const float* __restrict__ W2, const float* __restrict__ W3)
{
    __shared__ float t[32][33];
    int tx = threadIdx.x, ty = threadIdx.y;
    int bx = blockIdx.x, by = blockIdx.y, bz = blockIdx.z;
    const float* W = (bz == 0) ? W0 : (bz == 1) ? W1 : (bz == 2) ? W2 : W3;
    __nv_bfloat16* hi = g_wthi + (size_t)bz * 1048576;
    __nv_bfloat16* lo = g_wtlo + (size_t)bz * 1048576;
#pragma unroll
    for (int i = 0; i < 4; i++)
        t[ty + i * 8][tx] = W[(size_t)(by * 32 + ty + i * 8) * 1024 + bx * 32 + tx];
    __syncthreads();
#pragma unroll
    for (int i = 0; i < 4; i++) {
        float v = t[tx][ty + i * 8];
        __nv_bfloat16 h, l; split1(v, h, l);
        size_t o = (size_t)(bx * 32 + ty + i * 8) * 1024 + by * 32 + tx;
        hi[o] = h;
        lo[o] = l;
    }
}

// ===================== GEMM core (3-stage, 1 barrier/iter) =================
#define GSTAGE 32768
#define GSMEM (3 * GSTAGE)

__device__ __forceinline__ void gemm_mainloop(
    uint32_t sb, int tid, int wm, int wn,
    const __nv_bfloat16* Ah, const __nv_bfloat16* Al,
    const __nv_bfloat16* Bh, const __nv_bfloat16* Bl,
    float acc[4][4][4])
{
    int lane = tid & 31;
    const __nv_bfloat16* gsrc[4] = { Ah, Al, Bh, Bl };
    int l_row0 = tid >> 2,         l_c0 = tid & 3;
    int l_row1 = (tid + 256) >> 2, l_c1 = (tid + 256) & 3;

    auto load_stage = [&](int kt, int s) {
        uint32_t sbase = sb + s * GSTAGE;
#pragma unroll
        for (int t = 0; t < 4; t++) {
            const char* g0 = (const char*)(gsrc[t] + (size_t)l_row0 * 1024 + kt * 32) + l_c0 * 16;
            const char* g1 = (const char*)(gsrc[t] + (size_t)l_row1 * 1024 + kt * 32) + l_c1 * 16;
            uint32_t s0 = sbase + t * 8192 + l_row0 * 64 + ((l_c0 ^ (l_row0 & 3)) * 16);
            uint32_t s1 = sbase + t * 8192 + l_row1 * 64 + ((l_c1 ^ (l_row1 & 3)) * 16);
            CP_ASYNC16(s0, g0);
            CP_ASYNC16(s1, g1);
        }
        CP_COMMIT();
    };

    int arow = (lane & 7) | (((lane >> 3) & 1) << 3);
    int asel = lane >> 4;
    int brow = (lane & 7) | ((lane >> 4) << 3);
    int bsel = (lane >> 3) & 1;

    load_stage(0, 0);
    load_stage(1, 1);

#pragma unroll 1
    for (int t = 0; t < 32; t++) {
        if (t >= 31) { CP_WAIT0(); } else { CP_WAIT1(); }
        __syncthreads();
        if (t + 2 < 32) load_stage(t + 2, (t + 2) % 3);

        uint32_t base = sb + (t % 3) * GSTAGE;
        uint32_t Ahb = base, Alb = base + 8192, Bhb = base + 16384, Blb = base + 24576;

#pragma unroll
        for (int ks = 0; ks < 2; ks++) {
            int akc = ks * 2 + asel;
            int bkc = ks * 2 + bsel;
            uint32_t ah[4][4], al[4][4], bhf[2][4], blf[2][4];
#pragma unroll
            for (int mt = 0; mt < 4; mt++) {
                int row = wm * 64 + mt * 16 + arow;
                uint32_t off = row * 64 + ((akc ^ (row & 3)) * 16);
                LDSM4(ah[mt][0], ah[mt][1], ah[mt][2], ah[mt][3], Ahb + off);
            }
#pragma unroll
            for (int nt = 0; nt < 2; nt++) {
                int row = wn * 32 + nt * 16 + brow;
                uint32_t off = row * 64 + ((bkc ^ (row & 3)) * 16);
                LDSM4(bhf[nt][0], bhf[nt][1], bhf[nt][2], bhf[nt][3], Bhb + off);
            }
#pragma unroll
            for (int mt = 0; mt < 4; mt++)
#pragma unroll
                for (int nt = 0; nt < 2; nt++) {
                    MMA16816(acc[mt][nt * 2 + 0], ah[mt], bhf[nt][0], bhf[nt][1]);
                    MMA16816(acc[mt][nt * 2 + 1], ah[mt], bhf[nt][2], bhf[nt][3]);
                }
#pragma unroll
            for (int nt = 0; nt < 2; nt++) {
                int row = wn * 32 + nt * 16 + brow;
                uint32_t off = row * 64 + ((bkc ^ (row & 3)) * 16);
                LDSM4(blf[nt][0], blf[nt][1], blf[nt][2], blf[nt][3], Blb + off);
            }
#pragma unroll
            for (int mt = 0; mt < 4; mt++)
#pragma unroll
                for (int nt = 0; nt < 2; nt++) {
                    MMA16816(acc[mt][nt * 2 + 0], ah[mt], blf[nt][0], blf[nt][1]);
                    MMA16816(acc[mt][nt * 2 + 1], ah[mt], blf[nt][2], blf[nt][3]);
                }
#pragma unroll
            for (int mt = 0; mt < 4; mt++) {
                int row = wm * 64 + mt * 16 + arow;
                uint32_t off = row * 64 + ((akc ^ (row & 3)) * 16);
                LDSM4(al[mt][0], al[mt][1], al[mt][2], al[mt][3], Alb + off);
            }
#pragma unroll
            for (int mt = 0; mt < 4; mt++)
#pragma unroll
                for (int nt = 0; nt < 2; nt++) {
                    MMA16816(acc[mt][nt * 2 + 0], al[mt], bhf[nt][0], bhf[nt][1]);
                    MMA16816(acc[mt][nt * 2 + 1], al[mt], bhf[nt][2], bhf[nt][3]);
                }
        }
        // no trailing barrier: next iteration's leading barrier frees this stage
    }
}

// Fused QKV projection: grid (24, 32). bx 0-7 -> Q, 8-15 -> K, 16-23 -> V.
__global__ __launch_bounds__(256, 2) void gemm_qkv(
    const float* __restrict__ bq, const float* __restrict__ bk,
    const float* __restrict__ bv)
{
    extern __shared__ char sm[];
    uint32_t sb = smem_u32(sm);
    int tid = threadIdx.x, lane = tid & 31, wid = tid >> 5;
    int wm = wid >> 2, wn = wid & 3;
    int widx = blockIdx.x >> 3;
    int n0 = (blockIdx.x & 7) * 128;
    int m0 = blockIdx.y * 128;

    const float* bias = (widx == 0) ? bq : (widx == 1) ? bk : bv;
    const __nv_bfloat16* Bh = g_wthi + (size_t)widx * 1048576 + (size_t)n0 * 1024;
    const __nv_bfloat16* Bl = g_wtlo + (size_t)widx * 1048576 + (size_t)n0 * 1024;

    float acc[4][4][4];
#pragma unroll
    for (int a = 0; a < 4; a++)
#pragma unroll
        for (int b = 0; b < 4; b++)
#pragma unroll
            for (int c = 0; c < 4; c++) acc[a][b][c] = 0.0f;

    gemm_mainloop(sb, tid, wm, wn,
                  g_xhi + (size_t)m0 * 1024, g_xlo + (size_t)m0 * 1024, Bh, Bl, acc);

    int r = lane >> 2, c2 = (lane & 3) * 2;
    __nv_bfloat16* dhi = (widx == 0) ? g_qhi : (widx == 1) ? g_khi : g_vthi;
    __nv_bfloat16* dlo = (widx == 0) ? g_qlo : (widx == 1) ? g_klo : g_vtlo;
#pragma unroll
    for (int mt = 0; mt < 4; mt++) {
        int mrow = m0 + wm * 64 + mt * 16 + r;
        int bidx = mrow >> 10, ntok = mrow & 1023;
#pragma unroll
        for (int nt8 = 0; nt8 < 4; nt8++) {
            int col = n0 + wn * 32 + nt8 * 8 + c2;
            float b0 = bias[col], b1 = bias[col + 1];
            float v00 = acc[mt][nt8][0] + b0, v01 = acc[mt][nt8][1] + b1;
            float v10 = acc[mt][nt8][2] + b0, v11 = acc[mt][nt8][3] + b1;
            int h = col >> 6, dh = col & 63;
            if (widx < 2) {
                size_t base = ((size_t)(bidx * HEADS + h) * SEQ + ntok) * DH + dh;
                __nv_bfloat16 h0, l0, h1, l1;
                split1(v00, h0, l0); split1(v01, h1, l1);
                *(__nv_bfloat162*)(dhi + base) = {h0, h1};
                *(__nv_bfloat162*)(dlo + base) = {l0, l1};
                split1(v10, h0, l0); split1(v11, h1, l1);
                *(__nv_bfloat162*)(dhi + base + 8 * DH) = {h0, h1};
                *(__nv_bfloat162*)(dlo + base + 8 * DH) = {l0, l1};
            } else {
                size_t vb = ((size_t)(bidx * HEADS + h) * DH + dh) * SEQ + ntok;
                __nv_bfloat16 hh, ll;
                split1(v00, hh, ll); dhi[vb] = hh; dlo[vb] = ll;
                split1(v01, hh, ll); dhi[vb + SEQ] = hh; dlo[vb + SEQ] = ll;
                split1(v10, hh, ll); dhi[vb + 8] = hh; dlo[vb + 8] = ll;
                split1(v11, hh, ll); dhi[vb + SEQ + 8] = hh; dlo[vb + SEQ + 8] = ll;
            }
        }
    }
}

// Output projection: ctx_split @ Wo^T + bo -> fp32 out
__global__ __launch_bounds__(256, 2) void gemm_out(
    const float* __restrict__ bias, float* __restrict__ dstf)
{
    extern __shared__ char sm[];
    uint32_t sb = smem_u32(sm);
    int tid = threadIdx.x, lane = tid & 31, wid = tid >> 5;
    int wm = wid >> 2, wn = wid & 3;
    int n0 = blockIdx.x * 128, m0 = blockIdx.y * 128;

    float acc[4][4][4];
#pragma unroll
    for (int a = 0; a < 4; a++)
#pragma unroll
        for (int b = 0; b < 4; b++)
#pragma unroll
            for (int c = 0; c < 4; c++) acc[a][b][c] = 0.0f;

    gemm_mainloop(sb, tid, wm, wn,
                  g_chi + (size_t)m0 * 1024, g_clo + (size_t)m0 * 1024,
                  g_wthi + 3u * 1048576 + (size_t)n0 * 1024,
                  g_wtlo + 3u * 1048576 + (size_t)n0 * 1024, acc);

    int r = lane >> 2, c2 = (lane & 3) * 2;
#pragma unroll
    for (int mt = 0; mt < 4; mt++) {
        int mrow = m0 + wm * 64 + mt * 16 + r;
#pragma unroll
        for (int nt8 = 0; nt8 < 4; nt8++) {
            int col = n0 + wn * 32 + nt8 * 8 + c2;
            float b0 = bias[col], b1 = bias[col + 1];
            float* p = dstf + (size_t)mrow * CH + col;
            *(float2*)p = {acc[mt][nt8][0] + b0, acc[mt][nt8][1] + b1};
            *(float2*)(p + 8 * CH) = {acc[mt][nt8][2] + b0, acc[mt][nt8][3] + b1};
        }
    }
}

// ===================== fused HMMA scores + entmax + P@V ====================
// 3-stage K/V ring, 1 barrier per chunk.
#define EOFF_QH 0
#define EOFF_QL 2048
#define EOFF_K  4096
#define EOFF_RED (4096 + 3 * 32768)
#define ESMEM (EOFF_RED + 2 * 384 * 4)

__global__ __launch_bounds__(256, 2) void attn_entmax_mma(float* __restrict__ attn)
{
    extern __shared__ char sm[];
    uint32_t sb = smem_u32(sm);
    float* RED = (float*)(sm + EOFF_RED);   // [2][384]

    int tid = threadIdx.x, lane = tid & 31, wid = tid >> 5;
    int bh = blockIdx.y;
    int R0 = blockIdx.x * 16;

    {   // Q: 16 rows x 8 u x {hi,lo} = 256 chunks, 1/thread
        int hl = tid >> 7;
        int row = (tid >> 3) & 15;
        int u = tid & 7;
        const __nv_bfloat16* src = (hl ? g_qlo : g_qhi) + ((size_t)bh * SEQ + R0 + row) * DH + u * 8;
        uint32_t d = sb + EOFF_QH + hl * 2048 + row * 128 + ((u ^ (row & 7)) * 16);
        CP_ASYNC16(d, src);
    }
    auto loadK = [&](int c, int s) {
        uint32_t base = sb + EOFF_K + s * 32768;
#pragma unroll
        for (int i = 0; i < 8; i++) {
            int idx = tid + i * 256;
            int hl = idx >> 10;
            int row = (idx >> 3) & 127;
            int u = idx & 7;
            const __nv_bfloat16* src = (hl ? g_klo : g_khi) + ((size_t)bh * SEQ + c * 128 + row) * DH + u * 8;
            uint32_t d = base + hl * 16384 + row * 128 + ((u ^ (row & 7)) * 16);
            CP_ASYNC16(d, src);
        }
        CP_COMMIT();
    };
    auto loadV = [&](int c, int s) {
        uint32_t base = sb + EOFF_K + s * 32768;
#pragma unroll
        for (int i = 0; i < 8; i++) {
            int idx = tid + i * 256;
            int hl = idx >> 10;
            int plane = (idx >> 9) & 1;
            int row = (idx >> 3) & 63;
            int u = idx & 7;
            const __nv_bfloat16* src = (hl ? g_vtlo : g_vthi)
                + (size_t)bh * DH * SEQ + (size_t)row * SEQ + c * 128 + plane * 64 + u * 8;
            uint32_t d = base + hl * 16384 + plane * 8192 + row * 128 + ((u ^ (row & 7)) * 16);
            CP_ASYNC16(d, src);
        }
        CP_COMMIT();
    };
    loadK(0, 0);
    loadK(1, 1);

    float acc[16][4];
#pragma unroll
    for (int t = 0; t < 16; t++)
#pragma unroll
        for (int e = 0; e < 4; e++) acc[t][e] = 0.0f;

    int arow_ = (lane & 7) | (((lane >> 3) & 1) << 3);
    int asel = lane >> 4;
    int brow_ = (lane & 7) | ((lane >> 4) << 3);
    int bsel = (lane >> 3) & 1;
    int krow_ = wid * 16 + brow_;
    uint32_t QHb = sb + EOFF_QH, QLb = sb + EOFF_QL;

    // QK: 3-stage ring, stage = c % 3, single barrier per chunk.
#pragma unroll
    for (int c = 0; c < 8; c++) {
        if (c >= 7) { CP_WAIT0(); } else { CP_WAIT1(); }
        __syncthreads();
        if (c + 2 < 8) loadK(c + 2, (c + 2) % 3);
        uint32_t KHb = sb + EOFF_K + (c % 3) * 32768;
        uint32_t KLb = KHb + 16384;
#pragma unroll
        for (int kc = 0; kc < 4; kc++) {
            uint32_t au = (uint32_t)(kc * 2 + asel);
            uint32_t aoff = arow_ * 128 + ((au ^ (arow_ & 7)) * 16);
            uint32_t ah[4], al[4];
            LDSM4(ah[0], ah[1], ah[2], ah[3], QHb + aoff);
            LDSM4(al[0], al[1], al[2], al[3], QLb + aoff);
            uint32_t bu = (uint32_t)(kc * 2 + bsel);
            uint32_t boff = krow_ * 128 + ((bu ^ (krow_ & 7)) * 16);
            uint32_t bh4[4], bl4[4];
            LDSM4(bh4[0], bh4[1], bh4[2], bh4[3], KHb + boff);
            LDSM4(bl4[0], bl4[1], bl4[2], bl4[3], KLb + boff);
            MMA16816(acc[2 * c + 0], ah, bh4[0], bh4[1]);
            MMA16816(acc[2 * c + 1], ah, bh4[2], bh4[3]);
            MMA16816(acc[2 * c + 0], ah, bl4[0], bl4[1]);
            MMA16816(acc[2 * c + 1], ah, bl4[2], bl4[3]);
            MMA16816(acc[2 * c + 0], al, bh4[0], bh4[1]);
            MMA16816(acc[2 * c + 1], al, bh4[2], bh4[3]);
            MMA16816(acc[2 * c + 0], al, bl4[0], bl4[1]);
            MMA16816(acc[2 * c + 1], al, bl4[2], bl4[3]);
        }
    }

    // Prefetch V chunks 0,1 into stages 2,0 (chunk 7 lives in stage 1 and
    // may still be in use until the next block barrier; stages 2 (K5) and
    // 0 (K6) were confirmed free by the c=7 leading barrier).
    loadV(0, 2);
    loadV(1, 0);

    // --- entmax (rows 0..15), redundant all-thread reductions ---
    int r0 = lane >> 2;
    int r1 = r0 + 8;
    bool qlead = (lane & 3) == 0;
    int par = 0;

#pragma unroll
    for (int t = 0; t < 16; t++)
#pragma unroll
        for (int e = 0; e < 4; e++) acc[t][e] *= SCALE;

    // Phase A: row max
    float tloA, tloB;
    {
        float mA = -1e30f, mB = -1e30f;
#pragma unroll
        for (int t = 0; t < 16; t++) {
            mA = fmaxf(mA, fmaxf(acc[t][0], acc[t][1]));
            mB = fmaxf(mB, fmaxf(acc[t][2], acc[t][3]));
        }
        mA = fmaxf(mA, __shfl_xor_sync(0xffffffffu, mA, 1));
        mA = fmaxf(mA, __shfl_xor_sync(0xffffffffu, mA, 2));
        mB = fmaxf(mB, __shfl_xor_sync(0xffffffffu, mB, 1));
        mB = fmaxf(mB, __shfl_xor_sync(0xffffffffu, mB, 2));
        float* RP = RED + par * 384;
        if (qlead) { RP[r0 * 8 + wid] = mA; RP[r1 * 8 + wid] = mB; }
        __syncthreads();
        tloA = max8(RP, r0) - 1.0f;
        tloB = max8(RP, r1) - 1.0f;
        par ^= 1;
    }

    float dm = 0.484375f;
    float tmA = tloA + dm, tmB = tloB + dm;

    // Phase C: bisection (f_lo >= 0 analytically => test is f_m >= 0)
#pragma unroll 1
    for (int it = 0; it < BISECT_ITERS; it++) {
        float c0 = 0.f, c1 = 0.f, c2 = 0.f, c3 = 0.f;
#pragma unroll
        for (int t = 0; t < 16; t++) {
            float u;
            u = fmaxf(acc[t][0] - tmA, 0.f); c0 = fmaf(u, u, c0);
            u = fmaxf(acc[t][1] - tmA, 0.f); c1 = fmaf(u, u, c1);
            u = fmaxf(acc[t][2] - tmB, 0.f); c2 = fmaf(u, u, c2);
            u = fmaxf(acc[t][3] - tmB, 0.f); c3 = fmaf(u, u, c3);
        }
        float vA = c0 + c1, vB = c2 + c3;
        vA += __shfl_xor_sync(0xffffffffu, vA, 1);
        vA += __shfl_xor_sync(0xffffffffu, vA, 2);
        vB += __shfl_xor_sync(0xffffffffu, vB, 1);
        vB += __shfl_xor_sync(0xffffffffu, vB, 2);
        float* RP = RED + par * 384;
        if (qlead) { RP[r0 * 8 + wid] = vA; RP[r1 * 8 + wid] = vB; }
        __syncthreads();
        float fmA = sum8(RP, r0) - 1.0f;
        float fmB = sum8(RP, r1) - 1.0f;
        if (fmA >= 0.f) tloA = tmA;
        if (fmB >= 0.f) tloB = tmB;
        if (it < BISECT_ITERS - 1) {
            dm *= 0.5f;
            tmA = tloA + dm;
            tmB = tloB + dm;
        }
        par ^= 1;
    }

    // Phase D: analytic support-fixpoint solves
#pragma unroll 1
    for (int ps = 0; ps < SOLVE_ITERS; ps++) {
        float nA = 0.f, s1A = 0.f, s2A = 0.f;
        float nB = 0.f, s1B = 0.f, s2B = 0.f;
#pragma unroll
        for (int t = 0; t < 16; t++) {
#pragma unroll
            for (int e = 0; e < 2; e++) {
                float a = acc[t][e];
                if (a > tmA) { nA += 1.f; s1A += a; s2A = fmaf(a, a, s2A); }
                float b = acc[t][e + 2];
                if (b > tmB) { nB += 1.f; s1B += b; s2B = fmaf(b, b, s2B); }
            }
        }
#pragma unroll
        for (int o = 1; o <= 2; o <<= 1) {
            nA += __shfl_xor_sync(0xffffffffu, nA, o);
            s1A += __shfl_xor_sync(0xffffffffu, s1A, o);
            s2A += __shfl_xor_sync(0xffffffffu, s2A, o);
            nB += __shfl_xor_sync(0xffffffffu, nB, o);
            s1B += __shfl_xor_sync(0xffffffffu, s1B, o);
            s2B += __shfl_xor_sync(0xffffffffu, s2B, o);
        }
        float* RP = RED + par * 384;
        if (qlead) {
            RP[r0 * 8 + wid] = nA;        RP[r1 * 8 + wid] = nB;
            RP[128 + r0 * 8 + wid] = s1A; RP[128 + r1 * 8 + wid] = s1B;
            RP[256 + r0 * 8 + wid] = s2A; RP[256 + r1 * 8 + wid] = s2B;
        }
        __syncthreads();
        {
            float n = sum8(RP, r0), s1 = sum8(RP + 128, r0), s2 = sum8(RP + 256, r0);
            float D = fmaxf(fmaf(s1, s1, -n * (s2 - 1.0f)), 0.f);
            tmA = (s1 - sqrtf(D)) / n;
            n = sum8(RP, r1); s1 = sum8(RP + 128, r1); s2 = sum8(RP + 256, r1);
            D = fmaxf(fmaf(s1, s1, -n * (s2 - 1.0f)), 0.f);
            tmB = (s1 - sqrtf(D)) / n;
        }
        par ^= 1;
    }

    // Phase E: final p + normalize
    float ivA, ivB;
    {
        float c0 = 0.f, c1 = 0.f, c2 = 0.f, c3 = 0.f;
#pragma unroll
        for (int t = 0; t < 16; t++) {
            float u;
            u = fmaxf(acc[t][0] - tmA, 0.f); acc[t][0] = u * u; c0 += acc[t][0];
            u = fmaxf(acc[t][1] - tmA, 0.f); acc[t][1] = u * u; c1 += acc[t][1];
            u = fmaxf(acc[t][2] - tmB, 0.f); acc[t][2] = u * u; c2 += acc[t][2];
            u = fmaxf(acc[t][3] - tmB, 0.f); acc[t][3] = u * u; c3 += acc[t][3];
        }
        float vA = c0 + c1, vB = c2 + c3;
        vA += __shfl_xor_sync(0xffffffffu, vA, 1);
        vA += __shfl_xor_sync(0xffffffffu, vA, 2);
        vB += __shfl_xor_sync(0xffffffffu, vB, 1);
        vB += __shfl_xor_sync(0xffffffffu, vB, 2);
        float* RP = RED + par * 384;
        if (qlead) { RP[r0 * 8 + wid] = vA; RP[r1 * 8 + wid] = vB; }
        __syncthreads();
        ivA = 1.0f / sum8(RP, r0);
        ivB = 1.0f / sum8(RP, r1);
    }

    // normalize in-register, write attn fp32, pack p -> bf16 split A-fragments
    uint32_t pH[16][2], pL[16][2];
    {
        size_t rb0 = ((size_t)bh * SEQ + R0 + r0) * SEQ + wid * 16 + (lane & 3) * 2;
        size_t rb1 = ((size_t)bh * SEQ + R0 + r1) * SEQ + wid * 16 + (lane & 3) * 2;
#pragma unroll
        for (int t = 0; t < 16; t++) {
            int off = (t >> 1) * 128 + (t & 1) * 8;
            float p0 = acc[t][0] * ivA, p1 = acc[t][1] * ivA;
            float p2 = acc[t][2] * ivB, p3 = acc[t][3] * ivB;
            *(float2*)(attn + rb0 + off) = {p0, p1};
            *(float2*)(attn + rb1 + off) = {p2, p3};
            __nv_bfloat16 h0, l0, h1, l1;
            split1(p0, h0, l0); split1(p1, h1, l1);
            pH[t][0] = pack2(h0, h1);
            pL[t][0] = pack2(l0, l1);
            split1(p2, h0, l0); split1(p3, h1, l1);
            pH[t][1] = pack2(h0, h1);
            pL[t][1] = pack2(l0, l1);
        }
    }

    // --- fused P@V (3-term), 3-stage ring: chunk v in stage (v+2)%3 ---
    float cacc[8][4];
#pragma unroll
    for (int n8 = 0; n8 < 8; n8++)
#pragma unroll
        for (int e = 0; e < 4; e++) cacc[n8][e] = 0.0f;

    int vplane = wid >> 2;
    uint32_t vku = (uint32_t)((wid & 3) * 2 + bsel);

#pragma unroll
    for (int v = 0; v < 8; v++) {
        if (v >= 7) { CP_WAIT0(); } else { CP_WAIT1(); }
        __syncthreads();
        if (v + 2 < 8) loadV(v + 2, (v + 1) % 3);   // stage (v+4)%3 == (v+1)%3
        uint32_t VHb = sb + EOFF_K + ((v + 2) % 3) * 32768;
        uint32_t VLb = VHb + 16384;
        uint32_t pa_h[4] = { pH[2 * v][0], pH[2 * v][1], pH[2 * v + 1][0], pH[2 * v + 1][1] };
        uint32_t pa_l[4] = { pL[2 * v][0], pL[2 * v][1], pL[2 * v + 1][0], pL[2 * v + 1][1] };
#pragma unroll
        for (int nt = 0; nt < 4; nt++) {
            int row = nt * 16 + brow_;
            uint32_t off = vplane * 8192 + row * 128 + ((vku ^ (row & 7)) * 16);
            uint32_t vh[4], vl[4];
            LDSM4(vh[0], vh[1], vh[2], vh[3], VHb + off);
            LDSM4(vl[0], vl[1], vl[2], vl[3], VLb + off);
            MMA16816(cacc[nt * 2 + 0], pa_h, vh[0], vh[1]);
            MMA16816(cacc[nt * 2 + 1], pa_h, vh[2], vh[3]);
            MMA16816(cacc[nt * 2 + 0], pa_h, vl[0], vl[1]);
            MMA16816(cacc[nt * 2 + 1], pa_h, vl[2], vl[3]);
            MMA16816(cacc[nt * 2 + 0], pa_l, vh[0], vh[1]);
            MMA16816(cacc[nt * 2 + 1], pa_l, vh[2], vh[3]);
        }
    }
    __syncthreads();   // protect PART region (overlaps V stage 0)

    // cross-warp reduction: 8 partials of [16][64] -> ctx split
    float* PART = (float*)(sm + EOFF_K);
#pragma unroll
    for (int n8 = 0; n8 < 8; n8++) {
        int dh = (n8 >> 1) * 16 + (n8 & 1) * 8 + (lane & 3) * 2;
        *(float2*)&PART[wid * 1024 + r0 * 64 + dh] = {cacc[n8][0], cacc[n8][1]};
        *(float2*)&PART[wid * 1024 + r1 * 64 + dh] = {cacc[n8][2], cacc[n8][3]};
    }
    __syncthreads();
    {
        int r = tid >> 4, d4 = (tid & 15) * 4;
        float4 s = {0.f, 0.f, 0.f, 0.f};
#pragma unroll
        for (int w = 0; w < 8; w++) {
            float4 t4 = *(float4*)&PART[w * 1024 + r * 64 + d4];
            s.x += t4.x; s.y += t4.y; s.z += t4.z; s.w += t4.w;
        }
        int bidx = bh >> 4, h = bh & 15;
        size_t o = (size_t)(bidx * SEQ + R0 + r) * CH + h * DH + d4;
        __nv_bfloat16 h0, l0, h1, l1, h2, l2, h3, l3;
        split1(s.x, h0, l0); split1(s.y, h1, l1);
        split1(s.z, h2, l2); split1(s.w, h3, l3);
        *(__nv_bfloat162*)(g_chi + o)     = {h0, h1};
        *(__nv_bfloat162*)(g_chi + o + 2) = {h2, h3};
        *(__nv_bfloat162*)(g_clo + o)     = {l0, l1};
        *(__nv_bfloat162*)(g_clo + o + 2) = {l2, l3};
    }
}

// ---------------------------------------------------------------------------
extern "C" void kernel_launch(void* const* d_in, const int* in_sizes, int n_in,
                              void* d_out, int out_size)
{
    const float* x  = (const float*)d_in[0];
    const float* Wq = (const float*)d_in[1];
    const float* bq = (const float*)d_in[2];
    const float* Wk = (const float*)d_in[3];
    const float* bk = (const float*)d_in[4];
    const float* Wv = (const float*)d_in[5];
    const float* bv = (const float*)d_in[6];
    const float* Wo = (const float*)d_in[7];
    const float* bo = (const float*)d_in[8];

    float* out_ptr  = (float*)d_out;
    float* attn_ptr = out_ptr + OUT_ELEMS;

    __nv_bfloat16 *p_xhi, *p_xlo;
    cudaGetSymbolAddress((void**)&p_xhi, g_xhi);
    cudaGetSymbolAddress((void**)&p_xlo, g_xlo);

    cudaFuncSetAttribute(gemm_qkv, cudaFuncAttributeMaxDynamicSharedMemorySize, GSMEM);
    cudaFuncSetAttribute(gemm_out, cudaFuncAttributeMaxDynamicSharedMemorySize, GSMEM);
    cudaFuncSetAttribute(attn_entmax_mma, cudaFuncAttributeMaxDynamicSharedMemorySize, ESMEM);

    split_convert<<<OUT_ELEMS / 4 / 256, 256>>>(x, p_xhi, p_xlo, OUT_ELEMS / 4);
    dim3 wt4(32, 32, 4), wb(32, 8);
    wtrans_convert4<<<wt4, wb>>>(Wq, Wk, Wv, Wo);

    dim3 gq(24, 32);
    gemm_qkv<<<gq, 256, GSMEM>>>(bq, bk, bv);

    dim3 ge(64, BH);
    attn_entmax_mma<<<ge, 256, ESMEM>>>(attn_ptr);

    dim3 gg(8, 32);
    gemm_out<<<gg, 256, GSMEM>>>(bo, out_ptr);
}

// round 16
// speedup vs baseline: 1.6417x; 1.0216x over previous
#include <cuda_runtime.h>
#include <cuda_bf16.h>
#include <cstdint>

#define BATCH 4
#define SEQ   1024
#define CH    1024
#define HEADS 16
#define DH    64
#define TOKENS (BATCH * SEQ)
#define BH (BATCH * HEADS)
#define OUT_ELEMS (TOKENS * CH)

#define BISECT_ITERS 6
#define SOLVE_ITERS 2
#define SCALE 0.0625f   // (1/sqrt(64)) * (alpha-1)

// bf16 split scratch
__device__ __nv_bfloat16 g_xhi[TOKENS * CH];
__device__ __nv_bfloat16 g_xlo[TOKENS * CH];
__device__ __nv_bfloat16 g_wthi[4 * CH * CH];
__device__ __nv_bfloat16 g_wtlo[4 * CH * CH];
__device__ __nv_bfloat16 g_qhi[BH * SEQ * DH];
__device__ __nv_bfloat16 g_qlo[BH * SEQ * DH];
__device__ __nv_bfloat16 g_khi[BH * SEQ * DH];
__device__ __nv_bfloat16 g_klo[BH * SEQ * DH];
__device__ __nv_bfloat16 g_vthi[BH * DH * SEQ];   // transposed V: [bh][dh][tok]
__device__ __nv_bfloat16 g_vtlo[BH * DH * SEQ];
__device__ __nv_bfloat16 g_chi[TOKENS * CH];
__device__ __nv_bfloat16 g_clo[TOKENS * CH];

// ===================== PTX helpers =========================================
__device__ __forceinline__ uint32_t smem_u32(const void* p) {
    uint32_t a;
    asm("{ .reg .u64 t; cvta.to.shared.u64 t, %1; cvt.u32.u64 %0, t; }" : "=r"(a) : "l"(p));
    return a;
}
#define CP_ASYNC16(sa, g) \
    asm volatile("cp.async.cg.shared.global [%0], [%1], 16;" :: "r"(sa), "l"(g))
#define CP_COMMIT() asm volatile("cp.async.commit_group;" ::: "memory")
#define CP_WAIT0() asm volatile("cp.async.wait_group 0;" ::: "memory")
#define CP_WAIT1() asm volatile("cp.async.wait_group 1;" ::: "memory")
#define LDSM4(r0, r1, r2, r3, addr) \
    asm volatile("ldmatrix.sync.aligned.m8n8.x4.shared.b16 {%0,%1,%2,%3}, [%4];" \
        : "=r"(r0), "=r"(r1), "=r"(r2), "=r"(r3) : "r"(addr))
#define MMA16816(d, a, b0, b1) \
    asm volatile("mma.sync.aligned.m16n8k16.row.col.f32.bf16.bf16.f32 " \
        "{%0,%1,%2,%3}, {%4,%5,%6,%7}, {%8,%9}, {%0,%1,%2,%3};" \
        : "+f"((d)[0]), "+f"((d)[1]), "+f"((d)[2]), "+f"((d)[3]) \
        : "r"((a)[0]), "r"((a)[1]), "r"((a)[2]), "r"((a)[3]), "r"(b0), "r"(b1))

__device__ __forceinline__ void split1(float v, __nv_bfloat16& h, __nv_bfloat16& l) {
    h = __float2bfloat16_rn(v);
    l = __float2bfloat16_rn(v - __bfloat162float(h));
}
__device__ __forceinline__ uint32_t pack2(__nv_bfloat16 a, __nv_bfloat16 b) {
    __nv_bfloat162 t; t.x = a; t.y = b;
    return *reinterpret_cast<uint32_t*>(&t);
}
__device__ __forceinline__ float sum8(const float* base, int row) {
    float4 a = ((const float4*)base)[row * 2];
    float4 b = ((const float4*)base)[row * 2 + 1];
    return ((a.x + a.y) + (a.z + a.w)) + ((b.x + b.y) + (b.z + b.w));
}
__device__ __forceinline__ float max8(const float* base, int row) {
    float4 a = ((const float4*)base)[row * 2];
    float4 b = ((const float4*)base)[row * 2 + 1];
    return fmaxf(fmaxf(fmaxf(a.x, a.y), fmaxf(a.z, a.w)),
                 fmaxf(fmaxf(b.x, b.y), fmaxf(b.z, b.w)));
}

// ===================== fused convert kernel ================================
// bz 0..3: weight transpose+split; bz 4..8 would exceed x tiling needs:
// x is 4096x1024 = 128x32 tiles of 32x32 -> use bz=4 with gridDim.y*4 planes.
// Simpler: bz 0..3 weights; bz 4..7 cover x rows [bz-4]*1024 .. +1023.
__global__ __launch_bounds__(256) void convert_all(
    const float* __restrict__ W0, const float* __restrict__ W1,
    const float* __restrict__ W2, const float* __restrict__ W3,
    const float* __restrict__ x)
{
    int tx = threadIdx.x, ty = threadIdx.y;
    int bx = blockIdx.x, by = blockIdx.y, bz = blockIdx.z;
    if (bz < 4) {
        __shared__ float t[32][33];
        const float* W = (bz == 0) ? W0 : (bz == 1) ? W1 : (bz == 2) ? W2 : W3;
        __nv_bfloat16* hi = g_wthi + (size_t)bz * 1048576;
        __nv_bfloat16* lo = g_wtlo + (size_t)bz * 1048576;
#pragma unroll
        for (int i = 0; i < 4; i++)
            t[ty + i * 8][tx] = W[(size_t)(by * 32 + ty + i * 8) * 1024 + bx * 32 + tx];
        __syncthreads();
#pragma unroll
        for (int i = 0; i < 4; i++) {
            float v = t[tx][ty + i * 8];
            __nv_bfloat16 h, l; split1(v, h, l);
            size_t o = (size_t)(bx * 32 + ty + i * 8) * 1024 + by * 32 + tx;
            hi[o] = h;
            lo[o] = l;
        }
    } else {
        // x split: plane p = bz-4 covers rows p*1024..p*1024+1023.
        // 1024 rows x 1024 cols; block (bx, by) handles 4-float chunks.
        int tid = ty * 32 + tx;                 // 0..255
        size_t base4 = ((size_t)(bz - 4) * 1024 + by * 32) * 256 + bx * 8 * 256;
        // each block: 32 rows x (8*4=32? ) -- simpler: linear mapping
        size_t i = base4 + tid;                 // float4 index
        // guard: total float4 = 1024*256 per plane; by in [0,32), bx in [0,32):
        // base4 spans by*8192 + bx*2048; 32*8192 = 262144 = plane size. OK.
        float4 v = ((const float4*)(x))[ (size_t)(bz - 4) * 262144 + (size_t)by * 8192 + (size_t)bx * 2048 / 8 * 8 + bx * 0 + (size_t)blockIdx.x * 0 + ((size_t)by * 0) + ((size_t)bx * 2048) / 2048 * 2048 + tid ];
        // NOTE: simplified below in cleaned form
        (void)v; (void)i;
    }
}

// (The x-split path above is error-prone; use a dedicated clean kernel.)
__global__ __launch_bounds__(256) void split_convert(
    const float* __restrict__ in, __nv_bfloat16* __restrict__ hi,
    __nv_bfloat16* __restrict__ lo, int n4)
{
    int i = blockIdx.x * 256 + threadIdx.x;
    if (i >= n4) return;
    float4 v = ((const float4*)in)[i];
    union { ushort u[4]; uint2 q; } H, L;
    float a[4] = {v.x, v.y, v.z, v.w};
#pragma unroll
    for (int j = 0; j < 4; j++) {
        __nv_bfloat16 h, l; split1(a[j], h, l);
        H.u[j] = __bfloat16_as_ushort(h);
        L.u[j] = __bfloat16_as_ushort(l);
    }
    ((uint2*)hi)[i] = H.q;
    ((uint2*)lo)[i] = L.q;
}

__global__ __launch_bounds__(256) void wtrans_convert4(
    const float* __restrict__ W0, const float* __restrict__ W1,
    const float* __restrict__ W2, const float* __restrict__ W3)
{
    __shared__ float t[32][33];
    int tx = threadIdx.x, ty = threadIdx.y;
    int bx = blockIdx.x, by = blockIdx.y, bz = blockIdx.z;
    const float* W = (bz == 0) ? W0 : (bz == 1) ? W1 : (bz == 2) ? W2 : W3;
    __nv_bfloat16* hi = g_wthi + (size_t)bz * 1048576;
    __nv_bfloat16* lo = g_wtlo + (size_t)bz * 1048576;
#pragma unroll
    for (int i = 0; i < 4; i++)
        t[ty + i * 8][tx] = W[(size_t)(by * 32 + ty + i * 8) * 1024 + bx * 32 + tx];
    __syncthreads();
#pragma unroll
    for (int i = 0; i < 4; i++) {
        float v = t[tx][ty + i * 8];
        __nv_bfloat16 h, l; split1(v, h, l);
        size_t o = (size_t)(bx * 32 + ty + i * 8) * 1024 + by * 32 + tx;
        hi[o] = h;
        lo[o] = l;
    }
}

// ===================== GEMM core (3-stage, 1 barrier/iter) =================
#define GSTAGE 32768
#define GSMEM (3 * GSTAGE)

__device__ __forceinline__ void gemm_mainloop(
    uint32_t sb, int tid, int wm, int wn,
    const __nv_bfloat16* Ah, const __nv_bfloat16* Al,
    const __nv_bfloat16* Bh, const __nv_bfloat16* Bl,
    float acc[4][4][4])
{
    int lane = tid & 31;
    const __nv_bfloat16* gsrc[4] = { Ah, Al, Bh, Bl };
    int l_row0 = tid >> 2,         l_c0 = tid & 3;
    int l_row1 = (tid + 256) >> 2, l_c1 = (tid + 256) & 3;

    auto load_stage = [&](int kt, int s) {
        uint32_t sbase = sb + s * GSTAGE;
#pragma unroll
        for (int t = 0; t < 4; t++) {
            const char* g0 = (const char*)(gsrc[t] + (size_t)l_row0 * 1024 + kt * 32) + l_c0 * 16;
            const char* g1 = (const char*)(gsrc[t] + (size_t)l_row1 * 1024 + kt * 32) + l_c1 * 16;
            uint32_t s0 = sbase + t * 8192 + l_row0 * 64 + ((l_c0 ^ (l_row0 & 3)) * 16);
            uint32_t s1 = sbase + t * 8192 + l_row1 * 64 + ((l_c1 ^ (l_row1 & 3)) * 16);
            CP_ASYNC16(s0, g0);
            CP_ASYNC16(s1, g1);
        }
        CP_COMMIT();
    };

    int arow = (lane & 7) | (((lane >> 3) & 1) << 3);
    int asel = lane >> 4;
    int brow = (lane & 7) | ((lane >> 4) << 3);
    int bsel = (lane >> 3) & 1;

    load_stage(0, 0);
    load_stage(1, 1);

#pragma unroll 1
    for (int t = 0; t < 32; t++) {
        if (t >= 31) { CP_WAIT0(); } else { CP_WAIT1(); }
        __syncthreads();
        if (t + 2 < 32) load_stage(t + 2, (t + 2) % 3);

        uint32_t base = sb + (t % 3) * GSTAGE;
        uint32_t Ahb = base, Alb = base + 8192, Bhb = base + 16384, Blb = base + 24576;

#pragma unroll
        for (int ks = 0; ks < 2; ks++) {
            int akc = ks * 2 + asel;
            int bkc = ks * 2 + bsel;
            uint32_t ah[4][4], al[4][4], bhf[2][4], blf[2][4];
#pragma unroll
            for (int mt = 0; mt < 4; mt++) {
                int row = wm * 64 + mt * 16 + arow;
                uint32_t off = row * 64 + ((akc ^ (row & 3)) * 16);
                LDSM4(ah[mt][0], ah[mt][1], ah[mt][2], ah[mt][3], Ahb + off);
            }
#pragma unroll
            for (int nt = 0; nt < 2; nt++) {
                int row = wn * 32 + nt * 16 + brow;
                uint32_t off = row * 64 + ((bkc ^ (row & 3)) * 16);
                LDSM4(bhf[nt][0], bhf[nt][1], bhf[nt][2], bhf[nt][3], Bhb + off);
            }
#pragma unroll
            for (int mt = 0; mt < 4; mt++)
#pragma unroll
                for (int nt = 0; nt < 2; nt++) {
                    MMA16816(acc[mt][nt * 2 + 0], ah[mt], bhf[nt][0], bhf[nt][1]);
                    MMA16816(acc[mt][nt * 2 + 1], ah[mt], bhf[nt][2], bhf[nt][3]);
                }
#pragma unroll
            for (int nt = 0; nt < 2; nt++) {
                int row = wn * 32 + nt * 16 + brow;
                uint32_t off = row * 64 + ((bkc ^ (row & 3)) * 16);
                LDSM4(blf[nt][0], blf[nt][1], blf[nt][2], blf[nt][3], Blb + off);
            }
#pragma unroll
            for (int mt = 0; mt < 4; mt++)
#pragma unroll
                for (int nt = 0; nt < 2; nt++) {
                    MMA16816(acc[mt][nt * 2 + 0], ah[mt], blf[nt][0], blf[nt][1]);
                    MMA16816(acc[mt][nt * 2 + 1], ah[mt], blf[nt][2], blf[nt][3]);
                }
#pragma unroll
            for (int mt = 0; mt < 4; mt++) {
                int row = wm * 64 + mt * 16 + arow;
                uint32_t off = row * 64 + ((akc ^ (row & 3)) * 16);
                LDSM4(al[mt][0], al[mt][1], al[mt][2], al[mt][3], Alb + off);
            }
#pragma unroll
            for (int mt = 0; mt < 4; mt++)
#pragma unroll
                for (int nt = 0; nt < 2; nt++) {
                    MMA16816(acc[mt][nt * 2 + 0], al[mt], bhf[nt][0], bhf[nt][1]);
                    MMA16816(acc[mt][nt * 2 + 1], al[mt], bhf[nt][2], bhf[nt][3]);
                }
        }
    }
}

// Fused QKV projection: grid (24, 32). bx 0-7 -> Q, 8-15 -> K, 16-23 -> V.
__global__ __launch_bounds__(256, 2) void gemm_qkv(
    const float* __restrict__ bq, const float* __restrict__ bk,
    const float* __restrict__ bv)
{
    extern __shared__ char sm[];
    uint32_t sb = smem_u32(sm);
    int tid = threadIdx.x, lane = tid & 31, wid = tid >> 5;
    int wm = wid >> 2, wn = wid & 3;
    int widx = blockIdx.x >> 3;
    int n0 = (blockIdx.x & 7) * 128;
    int m0 = blockIdx.y * 128;

    const float* bias = (widx == 0) ? bq : (widx == 1) ? bk : bv;
    const __nv_bfloat16* Bh = g_wthi + (size_t)widx * 1048576 + (size_t)n0 * 1024;
    const __nv_bfloat16* Bl = g_wtlo + (size_t)widx * 1048576 + (size_t)n0 * 1024;

    float acc[4][4][4];
#pragma unroll
    for (int a = 0; a < 4; a++)
#pragma unroll
        for (int b = 0; b < 4; b++)
#pragma unroll
            for (int c = 0; c < 4; c++) acc[a][b][c] = 0.0f;

    gemm_mainloop(sb, tid, wm, wn,
                  g_xhi + (size_t)m0 * 1024, g_xlo + (size_t)m0 * 1024, Bh, Bl, acc);

    int r = lane >> 2, c2 = (lane & 3) * 2;
    __nv_bfloat16* dhi = (widx == 0) ? g_qhi : (widx == 1) ? g_khi : g_vthi;
    __nv_bfloat16* dlo = (widx == 0) ? g_qlo : (widx == 1) ? g_klo : g_vtlo;
#pragma unroll
    for (int mt = 0; mt < 4; mt++) {
        int mrow = m0 + wm * 64 + mt * 16 + r;
        int bidx = mrow >> 10, ntok = mrow & 1023;
#pragma unroll
        for (int nt8 = 0; nt8 < 4; nt8++) {
            int col = n0 + wn * 32 + nt8 * 8 + c2;
            float b0 = bias[col], b1 = bias[col + 1];
            float v00 = acc[mt][nt8][0] + b0, v01 = acc[mt][nt8][1] + b1;
            float v10 = acc[mt][nt8][2] + b0, v11 = acc[mt][nt8][3] + b1;
            int h = col >> 6, dh = col & 63;
            if (widx < 2) {
                size_t base = ((size_t)(bidx * HEADS + h) * SEQ + ntok) * DH + dh;
                __nv_bfloat16 h0, l0, h1, l1;
                split1(v00, h0, l0); split1(v01, h1, l1);
                *(__nv_bfloat162*)(dhi + base) = {h0, h1};
                *(__nv_bfloat162*)(dlo + base) = {l0, l1};
                split1(v10, h0, l0); split1(v11, h1, l1);
                *(__nv_bfloat162*)(dhi + base + 8 * DH) = {h0, h1};
                *(__nv_bfloat162*)(dlo + base + 8 * DH) = {l0, l1};
            } else {
                size_t vb = ((size_t)(bidx * HEADS + h) * DH + dh) * SEQ + ntok;
                __nv_bfloat16 hh, ll;
                split1(v00, hh, ll); dhi[vb] = hh; dlo[vb] = ll;
                split1(v01, hh, ll); dhi[vb + SEQ] = hh; dlo[vb + SEQ] = ll;
                split1(v10, hh, ll); dhi[vb + 8] = hh; dlo[vb + 8] = ll;
                split1(v11, hh, ll); dhi[vb + SEQ + 8] = hh; dlo[vb + SEQ + 8] = ll;
            }
        }
    }
}

// Output projection: ctx_split @ Wo^T + bo -> fp32 out
__global__ __launch_bounds__(256, 2) void gemm_out(
    const float* __restrict__ bias, float* __restrict__ dstf)
{
    extern __shared__ char sm[];
    uint32_t sb = smem_u32(sm);
    int tid = threadIdx.x, lane = tid & 31, wid = tid >> 5;
    int wm = wid >> 2, wn = wid & 3;
    int n0 = blockIdx.x * 128, m0 = blockIdx.y * 128;

    float acc[4][4][4];
#pragma unroll
    for (int a = 0; a < 4; a++)
#pragma unroll
        for (int b = 0; b < 4; b++)
#pragma unroll
            for (int c = 0; c < 4; c++) acc[a][b][c] = 0.0f;

    gemm_mainloop(sb, tid, wm, wn,
                  g_chi + (size_t)m0 * 1024, g_clo + (size_t)m0 * 1024,
                  g_wthi + 3u * 1048576 + (size_t)n0 * 1024,
                  g_wtlo + 3u * 1048576 + (size_t)n0 * 1024, acc);

    int r = lane >> 2, c2 = (lane & 3) * 2;
#pragma unroll
    for (int mt = 0; mt < 4; mt++) {
        int mrow = m0 + wm * 64 + mt * 16 + r;
#pragma unroll
        for (int nt8 = 0; nt8 < 4; nt8++) {
            int col = n0 + wn * 32 + nt8 * 8 + c2;
            float b0 = bias[col], b1 = bias[col + 1];
            float* p = dstf + (size_t)mrow * CH + col;
            *(float2*)p = {acc[mt][nt8][0] + b0, acc[mt][nt8][1] + b1};
            *(float2*)(p + 8 * CH) = {acc[mt][nt8][2] + b0, acc[mt][nt8][3] + b1};
        }
    }
}

// ===================== fused HMMA scores + entmax + P@V ====================
#define EOFF_QH 0
#define EOFF_QL 2048
#define EOFF_K  4096
#define EOFF_RED (4096 + 3 * 32768)
#define ESMEM (EOFF_RED + 2 * 384 * 4)

__global__ __launch_bounds__(256, 2) void attn_entmax_mma(float* __restrict__ attn)
{
    extern __shared__ char sm[];
    uint32_t sb = smem_u32(sm);
    float* RED = (float*)(sm + EOFF_RED);   // [2][384]

    int tid = threadIdx.x, lane = tid & 31, wid = tid >> 5;
    int bh = blockIdx.y;
    int R0 = blockIdx.x * 16;

    {   // Q: 16 rows x 8 u x {hi,lo} = 256 chunks, 1/thread
        int hl = tid >> 7;
        int row = (tid >> 3) & 15;
        int u = tid & 7;
        const __nv_bfloat16* src = (hl ? g_qlo : g_qhi) + ((size_t)bh * SEQ + R0 + row) * DH + u * 8;
        uint32_t d = sb + EOFF_QH + hl * 2048 + row * 128 + ((u ^ (row & 7)) * 16);
        CP_ASYNC16(d, src);
    }
    auto loadK = [&](int c, int s) {
        uint32_t base = sb + EOFF_K + s * 32768;
#pragma unroll
        for (int i = 0; i < 8; i++) {
            int idx = tid + i * 256;
            int hl = idx >> 10;
            int row = (idx >> 3) & 127;
            int u = idx & 7;
            const __nv_bfloat16* src = (hl ? g_klo : g_khi) + ((size_t)bh * SEQ + c * 128 + row) * DH + u * 8;
            uint32_t d = base + hl * 16384 + row * 128 + ((u ^ (row & 7)) * 16);
            CP_ASYNC16(d, src);
        }
        CP_COMMIT();
    };
    auto loadV = [&](int c, int s) {
        uint32_t base = sb + EOFF_K + s * 32768;
#pragma unroll
        for (int i = 0; i < 8; i++) {
            int idx = tid + i * 256;
            int hl = idx >> 10;
            int plane = (idx >> 9) & 1;
            int row = (idx >> 3) & 63;
            int u = idx & 7;
            const __nv_bfloat16* src = (hl ? g_vtlo : g_vthi)
                + (size_t)bh * DH * SEQ + (size_t)row * SEQ + c * 128 + plane * 64 + u * 8;
            uint32_t d = base + hl * 16384 + plane * 8192 + row * 128 + ((u ^ (row & 7)) * 16);
            CP_ASYNC16(d, src);
        }
        CP_COMMIT();
    };
    loadK(0, 0);
    loadK(1, 1);

    float acc[16][4];
#pragma unroll
    for (int t = 0; t < 16; t++)
#pragma unroll
        for (int e = 0; e < 4; e++) acc[t][e] = 0.0f;

    int arow_ = (lane & 7) | (((lane >> 3) & 1) << 3);
    int asel = lane >> 4;
    int brow_ = (lane & 7) | ((lane >> 4) << 3);
    int bsel = (lane >> 3) & 1;
    int krow_ = wid * 16 + brow_;
    uint32_t QHb = sb + EOFF_QH, QLb = sb + EOFF_QL;

#pragma unroll
    for (int c = 0; c < 8; c++) {
        if (c >= 7) { CP_WAIT0(); } else { CP_WAIT1(); }
        __syncthreads();
        if (c + 2 < 8) loadK(c + 2, (c + 2) % 3);
        uint32_t KHb = sb + EOFF_K + (c % 3) * 32768;
        uint32_t KLb = KHb + 16384;
#pragma unroll
        for (int kc = 0; kc < 4; kc++) {
            uint32_t au = (uint32_t)(kc * 2 + asel);
            uint32_t aoff = arow_ * 128 + ((au ^ (arow_ & 7)) * 16);
            uint32_t ah[4], al[4];
            LDSM4(ah[0], ah[1], ah[2], ah[3], QHb + aoff);
            LDSM4(al[0], al[1], al[2], al[3], QLb + aoff);
            uint32_t bu = (uint32_t)(kc * 2 + bsel);
            uint32_t boff = krow_ * 128 + ((bu ^ (krow_ & 7)) * 16);
            uint32_t bh4[4], bl4[4];
            LDSM4(bh4[0], bh4[1], bh4[2], bh4[3], KHb + boff);
            LDSM4(bl4[0], bl4[1], bl4[2], bl4[3], KLb + boff);
            MMA16816(acc[2 * c + 0], ah, bh4[0], bh4[1]);
            MMA16816(acc[2 * c + 1], ah, bh4[2], bh4[3]);
            MMA16816(acc[2 * c + 0], ah, bl4[0], bl4[1]);
            MMA16816(acc[2 * c + 1], ah, bl4[2], bl4[3]);
            MMA16816(acc[2 * c + 0], al, bh4[0], bh4[1]);
            MMA16816(acc[2 * c + 1], al, bh4[2], bh4[3]);
            MMA16816(acc[2 * c + 0], al, bl4[0], bl4[1]);
            MMA16816(acc[2 * c + 1], al, bl4[2], bl4[3]);
        }
    }

    // Prefetch V chunks 0,1 into stages 2,0 (stage 1 holds in-flight K7 until
    // the next block barrier; stages 2 and 0 were freed by the c=7 barrier).
    loadV(0, 2);
    loadV(1, 0);

    // --- entmax (rows 0..15) ---
    int r0 = lane >> 2;
    int r1 = r0 + 8;
    bool qlead = (lane & 3) == 0;
    int par = 0;

#pragma unroll
    for (int t = 0; t < 16; t++)
#pragma unroll
        for (int e = 0; e < 4; e++) acc[t][e] *= SCALE;

    // Phase A: row max
    float tloA, tloB;
    {
        float mA = -1e30f, mB = -1e30f;
#pragma unroll
        for (int t = 0; t < 16; t++) {
            mA = fmaxf(mA, fmaxf(acc[t][0], acc[t][1]));
            mB = fmaxf(mB, fmaxf(acc[t][2], acc[t][3]));
        }
        mA = fmaxf(mA, __shfl_xor_sync(0xffffffffu, mA, 1));
        mA = fmaxf(mA, __shfl_xor_sync(0xffffffffu, mA, 2));
        mB = fmaxf(mB, __shfl_xor_sync(0xffffffffu, mB, 1));
        mB = fmaxf(mB, __shfl_xor_sync(0xffffffffu, mB, 2));
        float* RP = RED + par * 384;
        if (qlead) { RP[r0 * 8 + wid] = mA; RP[r1 * 8 + wid] = mB; }
        __syncthreads();
        tloA = max8(RP, r0) - 1.0f;
        tloB = max8(RP, r1) - 1.0f;
        par ^= 1;
    }

    float dm = 0.484375f;
    float tmA = tloA + dm, tmB = tloB + dm;

    // Phase C: bisection (f_lo >= 0 analytically => test is f_m >= 0)
#pragma unroll 1
    for (int it = 0; it < BISECT_ITERS; it++) {
        float c0 = 0.f, c1 = 0.f, c2 = 0.f, c3 = 0.f;
#pragma unroll
        for (int t = 0; t < 16; t++) {
            float u;
            u = fmaxf(acc[t][0] - tmA, 0.f); c0 = fmaf(u, u, c0);
            u = fmaxf(acc[t][1] - tmA, 0.f); c1 = fmaf(u, u, c1);
            u = fmaxf(acc[t][2] - tmB, 0.f); c2 = fmaf(u, u, c2);
            u = fmaxf(acc[t][3] - tmB, 0.f); c3 = fmaf(u, u, c3);
        }
        float vA = c0 + c1, vB = c2 + c3;
        vA += __shfl_xor_sync(0xffffffffu, vA, 1);
        vA += __shfl_xor_sync(0xffffffffu, vA, 2);
        vB += __shfl_xor_sync(0xffffffffu, vB, 1);
        vB += __shfl_xor_sync(0xffffffffu, vB, 2);
        float* RP = RED + par * 384;
        if (qlead) { RP[r0 * 8 + wid] = vA; RP[r1 * 8 + wid] = vB; }
        __syncthreads();
        float fmA = sum8(RP, r0) - 1.0f;
        float fmB = sum8(RP, r1) - 1.0f;
        if (fmA >= 0.f) tloA = tmA;
        if (fmB >= 0.f) tloB = tmB;
        if (it < BISECT_ITERS - 1) {
            dm *= 0.5f;
            tmA = tloA + dm;
            tmB = tloB + dm;
        }
        par ^= 1;
    }

    // Phase D: analytic support-fixpoint solves
#pragma unroll 1
    for (int ps = 0; ps < SOLVE_ITERS; ps++) {
        float nA = 0.f, s1A = 0.f, s2A = 0.f;
        float nB = 0.f, s1B = 0.f, s2B = 0.f;
#pragma unroll
        for (int t = 0; t < 16; t++) {
#pragma unroll
            for (int e = 0; e < 2; e++) {
                float a = acc[t][e];
                if (a > tmA) { nA += 1.f; s1A += a; s2A = fmaf(a, a, s2A); }
                float b = acc[t][e + 2];
                if (b > tmB) { nB += 1.f; s1B += b; s2B = fmaf(b, b, s2B); }
            }
        }
#pragma unroll
        for (int o = 1; o <= 2; o <<= 1) {
            nA += __shfl_xor_sync(0xffffffffu, nA, o);
            s1A += __shfl_xor_sync(0xffffffffu, s1A, o);
            s2A += __shfl_xor_sync(0xffffffffu, s2A, o);
            nB += __shfl_xor_sync(0xffffffffu, nB, o);
            s1B += __shfl_xor_sync(0xffffffffu, s1B, o);
            s2B += __shfl_xor_sync(0xffffffffu, s2B, o);
        }
        float* RP = RED + par * 384;
        if (qlead) {
            RP[r0 * 8 + wid] = nA;        RP[r1 * 8 + wid] = nB;
            RP[128 + r0 * 8 + wid] = s1A; RP[128 + r1 * 8 + wid] = s1B;
            RP[256 + r0 * 8 + wid] = s2A; RP[256 + r1 * 8 + wid] = s2B;
        }
        __syncthreads();
        {
            float n = sum8(RP, r0), s1 = sum8(RP + 128, r0), s2 = sum8(RP + 256, r0);
            float D = fmaxf(fmaf(s1, s1, -n * (s2 - 1.0f)), 0.f);
            tmA = (s1 - sqrtf(D)) / n;
            n = sum8(RP, r1); s1 = sum8(RP + 128, r1); s2 = sum8(RP + 256, r1);
            D = fmaxf(fmaf(s1, s1, -n * (s2 - 1.0f)), 0.f);
            tmB = (s1 - sqrtf(D)) / n;
        }
        par ^= 1;
    }

    // Phase E: final p + normalize
    float ivA, ivB;
    {
        float c0 = 0.f, c1 = 0.f, c2 = 0.f, c3 = 0.f;
#pragma unroll
        for (int t = 0; t < 16; t++) {
            float u;
            u = fmaxf(acc[t][0] - tmA, 0.f); acc[t][0] = u * u; c0 += acc[t][0];
            u = fmaxf(acc[t][1] - tmA, 0.f); acc[t][1] = u * u; c1 += acc[t][1];
            u = fmaxf(acc[t][2] - tmB, 0.f); acc[t][2] = u * u; c2 += acc[t][2];
            u = fmaxf(acc[t][3] - tmB, 0.f); acc[t][3] = u * u; c3 += acc[t][3];
        }
        float vA = c0 + c1, vB = c2 + c3;
        vA += __shfl_xor_sync(0xffffffffu, vA, 1);
        vA += __shfl_xor_sync(0xffffffffu, vA, 2);
        vB += __shfl_xor_sync(0xffffffffu, vB, 1);
        vB += __shfl_xor_sync(0xffffffffu, vB, 2);
        float* RP = RED + par * 384;
        if (qlead) { RP[r0 * 8 + wid] = vA; RP[r1 * 8 + wid] = vB; }
        __syncthreads();
        ivA = 1.0f / sum8(RP, r0);
        ivB = 1.0f / sum8(RP, r1);
    }

    // normalize in-register, write attn fp32 (streaming), pack p fragments
    uint32_t pH[16][2], pL[16][2];
    {
        size_t rb0 = ((size_t)bh * SEQ + R0 + r0) * SEQ + wid * 16 + (lane & 3) * 2;
        size_t rb1 = ((size_t)bh * SEQ + R0 + r1) * SEQ + wid * 16 + (lane & 3) * 2;
#pragma unroll
        for (int t = 0; t < 16; t++) {
            int off = (t >> 1) * 128 + (t & 1) * 8;
            float p0 = acc[t][0] * ivA, p1 = acc[t][1] * ivA;
            float p2 = acc[t][2] * ivB, p3 = acc[t][3] * ivB;
            __stcs((float2*)(attn + rb0 + off), {p0, p1});
            __stcs((float2*)(attn + rb1 + off), {p2, p3});
            __nv_bfloat16 h0, l0, h1, l1;
            split1(p0, h0, l0); split1(p1, h1, l1);
            pH[t][0] = pack2(h0, h1);
            pL[t][0] = pack2(l0, l1);
            split1(p2, h0, l0); split1(p3, h1, l1);
            pH[t][1] = pack2(h0, h1);
            pL[t][1] = pack2(l0, l1);
        }
    }

    // --- fused P@V (3-term), 3-stage ring: chunk v in stage (v+2)%3 ---
    float cacc[8][4];
#pragma unroll
    for (int n8 = 0; n8 < 8; n8++)
#pragma unroll
        for (int e = 0; e < 4; e++) cacc[n8][e] = 0.0f;

    int vplane = wid >> 2;
    uint32_t vku = (uint32_t)((wid & 3) * 2 + bsel);

#pragma unroll
    for (int v = 0; v < 8; v++) {
        if (v >= 7) { CP_WAIT0(); } else { CP_WAIT1(); }
        __syncthreads();
        if (v + 2 < 8) loadV(v + 2, (v + 1) % 3);
        uint32_t VHb = sb + EOFF_K + ((v + 2) % 3) * 32768;
        uint32_t VLb = VHb + 16384;
        uint32_t pa_h[4] = { pH[2 * v][0], pH[2 * v][1], pH[2 * v + 1][0], pH[2 * v + 1][1] };
        uint32_t pa_l[4] = { pL[2 * v][0], pL[2 * v][1], pL[2 * v + 1][0], pL[2 * v + 1][1] };
#pragma unroll
        for (int nt = 0; nt < 4; nt++) {
            int row = nt * 16 + brow_;
            uint32_t off = vplane * 8192 + row * 128 + ((vku ^ (row & 7)) * 16);
            uint32_t vh[4], vl[4];
            LDSM4(vh[0], vh[1], vh[2], vh[3], VHb + off);
            LDSM4(vl[0], vl[1], vl[2], vl[3], VLb + off);
            MMA16816(cacc[nt * 2 + 0], pa_h, vh[0], vh[1]);
            MMA16816(cacc[nt * 2 + 1], pa_h, vh[2], vh[3]);
            MMA16816(cacc[nt * 2 + 0], pa_h, vl[0], vl[1]);
            MMA16816(cacc[nt * 2 + 1], pa_h, vl[2], vl[3]);
            MMA16816(cacc[nt * 2 + 0], pa_l, vh[0], vh[1]);
            MMA16816(cacc[nt * 2 + 1], pa_l, vh[2], vh[3]);
        }
    }
    __syncthreads();   // protect PART region (overlaps V stages)

    // cross-warp reduction: 8 partials of [16][64] -> ctx split
    float* PART = (float*)(sm + EOFF_K);
#pragma unroll
    for (int n8 = 0; n8 < 8; n8++) {
        int dh = (n8 >> 1) * 16 + (n8 & 1) * 8 + (lane & 3) * 2;
        *(float2*)&PART[wid * 1024 + r0 * 64 + dh] = {cacc[n8][0], cacc[n8][1]};
        *(float2*)&PART[wid * 1024 + r1 * 64 + dh] = {cacc[n8][2], cacc[n8][3]};
    }
    __syncthreads();
    {
        int r = tid >> 4, d4 = (tid & 15) * 4;
        float4 s = {0.f, 0.f, 0.f, 0.f};
#pragma unroll
        for (int w = 0; w < 8; w++) {
            float4 t4 = *(float4*)&PART[w * 1024 + r * 64 + d4];
            s.x += t4.x; s.y += t4.y; s.z += t4.z; s.w += t4.w;
        }
        int bidx = bh >> 4, h = bh & 15;
        size_t o = (size_t)(bidx * SEQ + R0 + r) * CH + h * DH + d4;
        __nv_bfloat16 h0, l0, h1, l1, h2, l2, h3, l3;
        split1(s.x, h0, l0); split1(s.y, h1, l1);
        split1(s.z, h2, l2); split1(s.w, h3, l3);
        *(__nv_bfloat162*)(g_chi + o)     = {h0, h1};
        *(__nv_bfloat162*)(g_chi + o + 2) = {h2, h3};
        *(__nv_bfloat162*)(g_clo + o)     = {l0, l1};
        *(__nv_bfloat162*)(g_clo + o + 2) = {l2, l3};
    }
}

// ---------------------------------------------------------------------------
extern "C" void kernel_launch(void* const* d_in, const int* in_sizes, int n_in,
                              void* d_out, int out_size)
{
    const float* x  = (const float*)d_in[0];
    const float* Wq = (const float*)d_in[1];
    const float* bq = (const float*)d_in[2];
    const float* Wk = (const float*)d_in[3];
    const float* bk = (const float*)d_in[4];
    const float* Wv = (const float*)d_in[5];
    const float* bv = (const float*)d_in[6];
    const float* Wo = (const float*)d_in[7];
    const float* bo = (const float*)d_in[8];

    float* out_ptr  = (float*)d_out;
    float* attn_ptr = out_ptr + OUT_ELEMS;

    __nv_bfloat16 *p_xhi, *p_xlo;
    cudaGetSymbolAddress((void**)&p_xhi, g_xhi);
    cudaGetSymbolAddress((void**)&p_xlo, g_xlo);

    cudaFuncSetAttribute(gemm_qkv, cudaFuncAttributeMaxDynamicSharedMemorySize, GSMEM);
    cudaFuncSetAttribute(gemm_out, cudaFuncAttributeMaxDynamicSharedMemorySize, GSMEM);
    cudaFuncSetAttribute(attn_entmax_mma, cudaFuncAttributeMaxDynamicSharedMemorySize, ESMEM);

    split_convert<<<OUT_ELEMS / 4 / 256, 256>>>(x, p_xhi, p_xlo, OUT_ELEMS / 4);
    dim3 wt4(32, 32, 4), wb(32, 8);
    wtrans_convert4<<<wt4, wb>>>(Wq, Wk, Wv, Wo);

    dim3 gq(24, 32);
    gemm_qkv<<<gq, 256, GSMEM>>>(bq, bk, bv);

    dim3 ge(64, BH);
    attn_entmax_mma<<<ge, 256, ESMEM>>>(attn_ptr);

    dim3 gg(8, 32);
    gemm_out<<<gg, 256, GSMEM>>>(bo, out_ptr);
}

// round 17
// speedup vs baseline: 1.7065x; 1.0395x over previous
#include <cuda_runtime.h>
#include <cuda_bf16.h>
#include <cstdint>

#define BATCH 4
#define SEQ   1024
#define CH    1024
#define HEADS 16
#define DH    64
#define TOKENS (BATCH * SEQ)
#define BH (BATCH * HEADS)
#define OUT_ELEMS (TOKENS * CH)

#define BISECT_ITERS 4
#define SOLVE_ITERS 2
#define SCALE 0.0625f   // (1/sqrt(64)) * (alpha-1)

// bf16 split scratch
__device__ __nv_bfloat16 g_xhi[TOKENS * CH];
__device__ __nv_bfloat16 g_xlo[TOKENS * CH];
__device__ __nv_bfloat16 g_wthi[4 * CH * CH];
__device__ __nv_bfloat16 g_wtlo[4 * CH * CH];
__device__ __nv_bfloat16 g_qhi[BH * SEQ * DH];
__device__ __nv_bfloat16 g_qlo[BH * SEQ * DH];
__device__ __nv_bfloat16 g_khi[BH * SEQ * DH];
__device__ __nv_bfloat16 g_klo[BH * SEQ * DH];
__device__ __nv_bfloat16 g_vthi[BH * DH * SEQ];   // transposed V: [bh][dh][tok]
__device__ __nv_bfloat16 g_vtlo[BH * DH * SEQ];
__device__ __nv_bfloat16 g_chi[TOKENS * CH];
__device__ __nv_bfloat16 g_clo[TOKENS * CH];

// ===================== PTX helpers =========================================
__device__ __forceinline__ uint32_t smem_u32(const void* p) {
    uint32_t a;
    asm("{ .reg .u64 t; cvta.to.shared.u64 t, %1; cvt.u32.u64 %0, t; }" : "=r"(a) : "l"(p));
    return a;
}
#define CP_ASYNC16(sa, g) \
    asm volatile("cp.async.cg.shared.global [%0], [%1], 16;" :: "r"(sa), "l"(g))
#define CP_COMMIT() asm volatile("cp.async.commit_group;" ::: "memory")
#define CP_WAIT0() asm volatile("cp.async.wait_group 0;" ::: "memory")
#define CP_WAIT1() asm volatile("cp.async.wait_group 1;" ::: "memory")
#define LDSM4(r0, r1, r2, r3, addr) \
    asm volatile("ldmatrix.sync.aligned.m8n8.x4.shared.b16 {%0,%1,%2,%3}, [%4];" \
        : "=r"(r0), "=r"(r1), "=r"(r2), "=r"(r3) : "r"(addr))
#define MMA16816(d, a, b0, b1) \
    asm volatile("mma.sync.aligned.m16n8k16.row.col.f32.bf16.bf16.f32 " \
        "{%0,%1,%2,%3}, {%4,%5,%6,%7}, {%8,%9}, {%0,%1,%2,%3};" \
        : "+f"((d)[0]), "+f"((d)[1]), "+f"((d)[2]), "+f"((d)[3]) \
        : "r"((a)[0]), "r"((a)[1]), "r"((a)[2]), "r"((a)[3]), "r"(b0), "r"(b1))

__device__ __forceinline__ void split1(float v, __nv_bfloat16& h, __nv_bfloat16& l) {
    h = __float2bfloat16_rn(v);
    l = __float2bfloat16_rn(v - __bfloat162float(h));
}
__device__ __forceinline__ uint32_t pack2(__nv_bfloat16 a, __nv_bfloat16 b) {
    __nv_bfloat162 t; t.x = a; t.y = b;
    return *reinterpret_cast<uint32_t*>(&t);
}
__device__ __forceinline__ float sum8(const float* base, int row) {
    float4 a = ((const float4*)base)[row * 2];
    float4 b = ((const float4*)base)[row * 2 + 1];
    return ((a.x + a.y) + (a.z + a.w)) + ((b.x + b.y) + (b.z + b.w));
}
__device__ __forceinline__ float max8(const float* base, int row) {
    float4 a = ((const float4*)base)[row * 2];
    float4 b = ((const float4*)base)[row * 2 + 1];
    return fmaxf(fmaxf(fmaxf(a.x, a.y), fmaxf(a.z, a.w)),
                 fmaxf(fmaxf(b.x, b.y), fmaxf(b.z, b.w)));
}

// ===================== convert kernels =====================================
__global__ __launch_bounds__(256) void split_convert(
    const float* __restrict__ in, __nv_bfloat16* __restrict__ hi,
    __nv_bfloat16* __restrict__ lo, int n4)
{
    int i = blockIdx.x * 256 + threadIdx.x;
    if (i >= n4) return;
    float4 v = ((const float4*)in)[i];
    union { ushort u[4]; uint2 q; } H, L;
    float a[4] = {v.x, v.y, v.z, v.w};
#pragma unroll
    for (int j = 0; j < 4; j++) {
        __nv_bfloat16 h, l; split1(a[j], h, l);
        H.u[j] = __bfloat16_as_ushort(h);
        L.u[j] = __bfloat16_as_ushort(l);
    }
    ((uint2*)hi)[i] = H.q;
    ((uint2*)lo)[i] = L.q;
}

__global__ __launch_bounds__(256) void wtrans_convert4(
    const float* __restrict__ W0, const float* __restrict__ W1,
    const float* __restrict__ W2, const float* __restrict__ W3)
{
    __shared__ float t[32][33];
    int tx = threadIdx.x, ty = threadIdx.y;
    int bx = blockIdx.x, by = blockIdx.y, bz = blockIdx.z;
    const float* W = (bz == 0) ? W0 : (bz == 1) ? W1 : (bz == 2) ? W2 : W3;
    __nv_bfloat16* hi = g_wthi + (size_t)bz * 1048576;
    __nv_bfloat16* lo = g_wtlo + (size_t)bz * 1048576;
#pragma unroll
    for (int i = 0; i < 4; i++)
        t[ty + i * 8][tx] = W[(size_t)(by * 32 + ty + i * 8) * 1024 + bx * 32 + tx];
    __syncthreads();
#pragma unroll
    for (int i = 0; i < 4; i++) {
        float v = t[tx][ty + i * 8];
        __nv_bfloat16 h, l; split1(v, h, l);
        size_t o = (size_t)(bx * 32 + ty + i * 8) * 1024 + by * 32 + tx;
        hi[o] = h;
        lo[o] = l;
    }
}

// ===================== GEMM core (3-stage, 1 barrier/iter) =================
#define GSTAGE 32768
#define GSMEM (3 * GSTAGE)

__device__ __forceinline__ void gemm_mainloop(
    uint32_t sb, int tid, int wm, int wn,
    const __nv_bfloat16* Ah, const __nv_bfloat16* Al,
    const __nv_bfloat16* Bh, const __nv_bfloat16* Bl,
    float acc[4][4][4])
{
    int lane = tid & 31;
    const __nv_bfloat16* gsrc[4] = { Ah, Al, Bh, Bl };
    int l_row0 = tid >> 2,         l_c0 = tid & 3;
    int l_row1 = (tid + 256) >> 2, l_c1 = (tid + 256) & 3;

    auto load_stage = [&](int kt, int s) {
        uint32_t sbase = sb + s * GSTAGE;
#pragma unroll
        for (int t = 0; t < 4; t++) {
            const char* g0 = (const char*)(gsrc[t] + (size_t)l_row0 * 1024 + kt * 32) + l_c0 * 16;
            const char* g1 = (const char*)(gsrc[t] + (size_t)l_row1 * 1024 + kt * 32) + l_c1 * 16;
            uint32_t s0 = sbase + t * 8192 + l_row0 * 64 + ((l_c0 ^ (l_row0 & 3)) * 16);
            uint32_t s1 = sbase + t * 8192 + l_row1 * 64 + ((l_c1 ^ (l_row1 & 3)) * 16);
            CP_ASYNC16(s0, g0);
            CP_ASYNC16(s1, g1);
        }
        CP_COMMIT();
    };

    int arow = (lane & 7) | (((lane >> 3) & 1) << 3);
    int asel = lane >> 4;
    int brow = (lane & 7) | ((lane >> 4) << 3);
    int bsel = (lane >> 3) & 1;

    load_stage(0, 0);
    load_stage(1, 1);

#pragma unroll 1
    for (int t = 0; t < 32; t++) {
        if (t >= 31) { CP_WAIT0(); } else { CP_WAIT1(); }
        __syncthreads();
        if (t + 2 < 32) load_stage(t + 2, (t + 2) % 3);

        uint32_t base = sb + (t % 3) * GSTAGE;
        uint32_t Ahb = base, Alb = base + 8192, Bhb = base + 16384, Blb = base + 24576;

#pragma unroll
        for (int ks = 0; ks < 2; ks++) {
            int akc = ks * 2 + asel;
            int bkc = ks * 2 + bsel;
            uint32_t ah[4][4], al[4][4], bhf[2][4], blf[2][4];
#pragma unroll
            for (int mt = 0; mt < 4; mt++) {
                int row = wm * 64 + mt * 16 + arow;
                uint32_t off = row * 64 + ((akc ^ (row & 3)) * 16);
                LDSM4(ah[mt][0], ah[mt][1], ah[mt][2], ah[mt][3], Ahb + off);
            }
#pragma unroll
            for (int nt = 0; nt < 2; nt++) {
                int row = wn * 32 + nt * 16 + brow;
                uint32_t off = row * 64 + ((bkc ^ (row & 3)) * 16);
                LDSM4(bhf[nt][0], bhf[nt][1], bhf[nt][2], bhf[nt][3], Bhb + off);
            }
#pragma unroll
            for (int mt = 0; mt < 4; mt++)
#pragma unroll
                for (int nt = 0; nt < 2; nt++) {
                    MMA16816(acc[mt][nt * 2 + 0], ah[mt], bhf[nt][0], bhf[nt][1]);
                    MMA16816(acc[mt][nt * 2 + 1], ah[mt], bhf[nt][2], bhf[nt][3]);
                }
#pragma unroll
            for (int nt = 0; nt < 2; nt++) {
                int row = wn * 32 + nt * 16 + brow;
                uint32_t off = row * 64 + ((bkc ^ (row & 3)) * 16);
                LDSM4(blf[nt][0], blf[nt][1], blf[nt][2], blf[nt][3], Blb + off);
            }
#pragma unroll
            for (int mt = 0; mt < 4; mt++)
#pragma unroll
                for (int nt = 0; nt < 2; nt++) {
                    MMA16816(acc[mt][nt * 2 + 0], ah[mt], blf[nt][0], blf[nt][1]);
                    MMA16816(acc[mt][nt * 2 + 1], ah[mt], blf[nt][2], blf[nt][3]);
                }
#pragma unroll
            for (int mt = 0; mt < 4; mt++) {
                int row = wm * 64 + mt * 16 + arow;
                uint32_t off = row * 64 + ((akc ^ (row & 3)) * 16);
                LDSM4(al[mt][0], al[mt][1], al[mt][2], al[mt][3], Alb + off);
            }
#pragma unroll
            for (int mt = 0; mt < 4; mt++)
#pragma unroll
                for (int nt = 0; nt < 2; nt++) {
                    MMA16816(acc[mt][nt * 2 + 0], al[mt], bhf[nt][0], bhf[nt][1]);
                    MMA16816(acc[mt][nt * 2 + 1], al[mt], bhf[nt][2], bhf[nt][3]);
                }
        }
    }
}

// Fused QKV projection: grid (24, 32). bx 0-7 -> Q, 8-15 -> K, 16-23 -> V.
__global__ __launch_bounds__(256, 2) void gemm_qkv(
    const float* __restrict__ bq, const float* __restrict__ bk,
    const float* __restrict__ bv)
{
    extern __shared__ char sm[];
    uint32_t sb = smem_u32(sm);
    int tid = threadIdx.x, lane = tid & 31, wid = tid >> 5;
    int wm = wid >> 2, wn = wid & 3;
    int widx = blockIdx.x >> 3;
    int n0 = (blockIdx.x & 7) * 128;
    int m0 = blockIdx.y * 128;

    const float* bias = (widx == 0) ? bq : (widx == 1) ? bk : bv;
    const __nv_bfloat16* Bh = g_wthi + (size_t)widx * 1048576 + (size_t)n0 * 1024;
    const __nv_bfloat16* Bl = g_wtlo + (size_t)widx * 1048576 + (size_t)n0 * 1024;

    float acc[4][4][4];
#pragma unroll
    for (int a = 0; a < 4; a++)
#pragma unroll
        for (int b = 0; b < 4; b++)
#pragma unroll
            for (int c = 0; c < 4; c++) acc[a][b][c] = 0.0f;

    gemm_mainloop(sb, tid, wm, wn,
                  g_xhi + (size_t)m0 * 1024, g_xlo + (size_t)m0 * 1024, Bh, Bl, acc);

    int r = lane >> 2, c2 = (lane & 3) * 2;
    __nv_bfloat16* dhi = (widx == 0) ? g_qhi : (widx == 1) ? g_khi : g_vthi;
    __nv_bfloat16* dlo = (widx == 0) ? g_qlo : (widx == 1) ? g_klo : g_vtlo;
#pragma unroll
    for (int mt = 0; mt < 4; mt++) {
        int mrow = m0 + wm * 64 + mt * 16 + r;
        int bidx = mrow >> 10, ntok = mrow & 1023;
#pragma unroll
        for (int nt8 = 0; nt8 < 4; nt8++) {
            int col = n0 + wn * 32 + nt8 * 8 + c2;
            float b0 = bias[col], b1 = bias[col + 1];
            float v00 = acc[mt][nt8][0] + b0, v01 = acc[mt][nt8][1] + b1;
            float v10 = acc[mt][nt8][2] + b0, v11 = acc[mt][nt8][3] + b1;
            int h = col >> 6, dh = col & 63;
            if (widx < 2) {
                size_t base = ((size_t)(bidx * HEADS + h) * SEQ + ntok) * DH + dh;
                __nv_bfloat16 h0, l0, h1, l1;
                split1(v00, h0, l0); split1(v01, h1, l1);
                *(__nv_bfloat162*)(dhi + base) = {h0, h1};
                *(__nv_bfloat162*)(dlo + base) = {l0, l1};
                split1(v10, h0, l0); split1(v11, h1, l1);
                *(__nv_bfloat162*)(dhi + base + 8 * DH) = {h0, h1};
                *(__nv_bfloat162*)(dlo + base + 8 * DH) = {l0, l1};
            } else {
                size_t vb = ((size_t)(bidx * HEADS + h) * DH + dh) * SEQ + ntok;
                __nv_bfloat16 hh, ll;
                split1(v00, hh, ll); dhi[vb] = hh; dlo[vb] = ll;
                split1(v01, hh, ll); dhi[vb + SEQ] = hh; dlo[vb + SEQ] = ll;
                split1(v10, hh, ll); dhi[vb + 8] = hh; dlo[vb + 8] = ll;
                split1(v11, hh, ll); dhi[vb + SEQ + 8] = hh; dlo[vb + SEQ + 8] = ll;
            }
        }
    }
}

// Output projection: ctx_split @ Wo^T + bo -> fp32 out
__global__ __launch_bounds__(256, 2) void gemm_out(
    const float* __restrict__ bias, float* __restrict__ dstf)
{
    extern __shared__ char sm[];
    uint32_t sb = smem_u32(sm);
    int tid = threadIdx.x, lane = tid & 31, wid = tid >> 5;
    int wm = wid >> 2, wn = wid & 3;
    int n0 = blockIdx.x * 128, m0 = blockIdx.y * 128;

    float acc[4][4][4];
#pragma unroll
    for (int a = 0; a < 4; a++)
#pragma unroll
        for (int b = 0; b < 4; b++)
#pragma unroll
            for (int c = 0; c < 4; c++) acc[a][b][c] = 0.0f;

    gemm_mainloop(sb, tid, wm, wn,
                  g_chi + (size_t)m0 * 1024, g_clo + (size_t)m0 * 1024,
                  g_wthi + 3u * 1048576 + (size_t)n0 * 1024,
                  g_wtlo + 3u * 1048576 + (size_t)n0 * 1024, acc);

    int r = lane >> 2, c2 = (lane & 3) * 2;
#pragma unroll
    for (int mt = 0; mt < 4; mt++) {
        int mrow = m0 + wm * 64 + mt * 16 + r;
#pragma unroll
        for (int nt8 = 0; nt8 < 4; nt8++) {
            int col = n0 + wn * 32 + nt8 * 8 + c2;
            float b0 = bias[col], b1 = bias[col + 1];
            float* p = dstf + (size_t)mrow * CH + col;
            *(float2*)p = {acc[mt][nt8][0] + b0, acc[mt][nt8][1] + b1};
            *(float2*)(p + 8 * CH) = {acc[mt][nt8][2] + b0, acc[mt][nt8][3] + b1};
        }
    }
}

// ===================== fused HMMA scores + entmax + P@V ====================
#define EOFF_QH 0
#define EOFF_QL 2048
#define EOFF_K  4096
#define EOFF_RED (4096 + 3 * 32768)
#define ESMEM (EOFF_RED + 2 * 384 * 4)

__global__ __launch_bounds__(256, 2) void attn_entmax_mma(float* __restrict__ attn)
{
    extern __shared__ char sm[];
    uint32_t sb = smem_u32(sm);
    float* RED = (float*)(sm + EOFF_RED);   // [2][384]

    int tid = threadIdx.x, lane = tid & 31, wid = tid >> 5;
    int bh = blockIdx.y;
    int R0 = blockIdx.x * 16;

    {   // Q: 16 rows x 8 u x {hi,lo} = 256 chunks, 1/thread
        int hl = tid >> 7;
        int row = (tid >> 3) & 15;
        int u = tid & 7;
        const __nv_bfloat16* src = (hl ? g_qlo : g_qhi) + ((size_t)bh * SEQ + R0 + row) * DH + u * 8;
        uint32_t d = sb + EOFF_QH + hl * 2048 + row * 128 + ((u ^ (row & 7)) * 16);
        CP_ASYNC16(d, src);
    }
    auto loadK = [&](int c, int s) {
        uint32_t base = sb + EOFF_K + s * 32768;
#pragma unroll
        for (int i = 0; i < 8; i++) {
            int idx = tid + i * 256;
            int hl = idx >> 10;
            int row = (idx >> 3) & 127;
            int u = idx & 7;
            const __nv_bfloat16* src = (hl ? g_klo : g_khi) + ((size_t)bh * SEQ + c * 128 + row) * DH + u * 8;
            uint32_t d = base + hl * 16384 + row * 128 + ((u ^ (row & 7)) * 16);
            CP_ASYNC16(d, src);
        }
        CP_COMMIT();
    };
    auto loadV = [&](int c, int s) {
        uint32_t base = sb + EOFF_K + s * 32768;
#pragma unroll
        for (int i = 0; i < 8; i++) {
            int idx = tid + i * 256;
            int hl = idx >> 10;
            int plane = (idx >> 9) & 1;
            int row = (idx >> 3) & 63;
            int u = idx & 7;
            const __nv_bfloat16* src = (hl ? g_vtlo : g_vthi)
                + (size_t)bh * DH * SEQ + (size_t)row * SEQ + c * 128 + plane * 64 + u * 8;
            uint32_t d = base + hl * 16384 + plane * 8192 + row * 128 + ((u ^ (row & 7)) * 16);
            CP_ASYNC16(d, src);
        }
        CP_COMMIT();
    };
    loadK(0, 0);
    loadK(1, 1);

    float acc[16][4];
#pragma unroll
    for (int t = 0; t < 16; t++)
#pragma unroll
        for (int e = 0; e < 4; e++) acc[t][e] = 0.0f;

    int arow_ = (lane & 7) | (((lane >> 3) & 1) << 3);
    int asel = lane >> 4;
    int brow_ = (lane & 7) | ((lane >> 4) << 3);
    int bsel = (lane >> 3) & 1;
    int krow_ = wid * 16 + brow_;
    uint32_t QHb = sb + EOFF_QH, QLb = sb + EOFF_QL;

    // Q fragments hoisted: identical across all 8 K-chunks.
    uint32_t qh[4][4], ql[4][4];

#pragma unroll
    for (int c = 0; c < 8; c++) {
        if (c >= 7) { CP_WAIT0(); } else { CP_WAIT1(); }
        __syncthreads();
        if (c == 0) {
#pragma unroll
            for (int kc = 0; kc < 4; kc++) {
                uint32_t au = (uint32_t)(kc * 2 + asel);
                uint32_t aoff = arow_ * 128 + ((au ^ (arow_ & 7)) * 16);
                LDSM4(qh[kc][0], qh[kc][1], qh[kc][2], qh[kc][3], QHb + aoff);
                LDSM4(ql[kc][0], ql[kc][1], ql[kc][2], ql[kc][3], QLb + aoff);
            }
        }
        if (c + 2 < 8) loadK(c + 2, (c + 2) % 3);
        uint32_t KHb = sb + EOFF_K + (c % 3) * 32768;
        uint32_t KLb = KHb + 16384;
#pragma unroll
        for (int kc = 0; kc < 4; kc++) {
            uint32_t bu = (uint32_t)(kc * 2 + bsel);
            uint32_t boff = krow_ * 128 + ((bu ^ (krow_ & 7)) * 16);
            uint32_t bh4[4], bl4[4];
            LDSM4(bh4[0], bh4[1], bh4[2], bh4[3], KHb + boff);
            LDSM4(bl4[0], bl4[1], bl4[2], bl4[3], KLb + boff);
            MMA16816(acc[2 * c + 0], qh[kc], bh4[0], bh4[1]);
            MMA16816(acc[2 * c + 1], qh[kc], bh4[2], bh4[3]);
            MMA16816(acc[2 * c + 0], qh[kc], bl4[0], bl4[1]);
            MMA16816(acc[2 * c + 1], qh[kc], bl4[2], bl4[3]);
            MMA16816(acc[2 * c + 0], ql[kc], bh4[0], bh4[1]);
            MMA16816(acc[2 * c + 1], ql[kc], bh4[2], bh4[3]);
            MMA16816(acc[2 * c + 0], ql[kc], bl4[0], bl4[1]);
            MMA16816(acc[2 * c + 1], ql[kc], bl4[2], bl4[3]);
        }
    }

    // Prefetch V chunks 0,1 into stages 2,0 (stage 1 holds in-flight K7 until
    // the next block barrier; stages 2 and 0 were freed by the c=7 barrier).
    loadV(0, 2);
    loadV(1, 0);

    // --- entmax (rows 0..15) ---
    int r0 = lane >> 2;
    int r1 = r0 + 8;
    bool qlead = (lane & 3) == 0;
    int par = 0;

#pragma unroll
    for (int t = 0; t < 16; t++)
#pragma unroll
        for (int e = 0; e < 4; e++) acc[t][e] *= SCALE;

    // Phase A: row max
    float tloA, tloB;
    {
        float mA = -1e30f, mB = -1e30f;
#pragma unroll
        for (int t = 0; t < 16; t++) {
            mA = fmaxf(mA, fmaxf(acc[t][0], acc[t][1]));
            mB = fmaxf(mB, fmaxf(acc[t][2], acc[t][3]));
        }
        mA = fmaxf(mA, __shfl_xor_sync(0xffffffffu, mA, 1));
        mA = fmaxf(mA, __shfl_xor_sync(0xffffffffu, mA, 2));
        mB = fmaxf(mB, __shfl_xor_sync(0xffffffffu, mB, 1));
        mB = fmaxf(mB, __shfl_xor_sync(0xffffffffu, mB, 2));
        float* RP = RED + par * 384;
        if (qlead) { RP[r0 * 8 + wid] = mA; RP[r1 * 8 + wid] = mB; }
        __syncthreads();
        tloA = max8(RP, r0) - 1.0f;
        tloB = max8(RP, r1) - 1.0f;
        par ^= 1;
    }

    float dm = 0.484375f;
    float tmA = tloA + dm, tmB = tloB + dm;

    // Phase C: bisection (f_lo >= 0 analytically => test is f_m >= 0)
#pragma unroll 1
    for (int it = 0; it < BISECT_ITERS; it++) {
        float c0 = 0.f, c1 = 0.f, c2 = 0.f, c3 = 0.f;
#pragma unroll
        for (int t = 0; t < 16; t++) {
            float u;
            u = fmaxf(acc[t][0] - tmA, 0.f); c0 = fmaf(u, u, c0);
            u = fmaxf(acc[t][1] - tmA, 0.f); c1 = fmaf(u, u, c1);
            u = fmaxf(acc[t][2] - tmB, 0.f); c2 = fmaf(u, u, c2);
            u = fmaxf(acc[t][3] - tmB, 0.f); c3 = fmaf(u, u, c3);
        }
        float vA = c0 + c1, vB = c2 + c3;
        vA += __shfl_xor_sync(0xffffffffu, vA, 1);
        vA += __shfl_xor_sync(0xffffffffu, vA, 2);
        vB += __shfl_xor_sync(0xffffffffu, vB, 1);
        vB += __shfl_xor_sync(0xffffffffu, vB, 2);
        float* RP = RED + par * 384;
        if (qlead) { RP[r0 * 8 + wid] = vA; RP[r1 * 8 + wid] = vB; }
        __syncthreads();
        float fmA = sum8(RP, r0) - 1.0f;
        float fmB = sum8(RP, r1) - 1.0f;
        if (fmA >= 0.f) tloA = tmA;
        if (fmB >= 0.f) tloB = tmB;
        if (it < BISECT_ITERS - 1) {
            dm *= 0.5f;
            tmA = tloA + dm;
            tmB = tloB + dm;
        }
        par ^= 1;
    }

    // Phase D: analytic support-fixpoint solves
#pragma unroll 1
    for (int ps = 0; ps < SOLVE_ITERS; ps++) {
        float nA = 0.f, s1A = 0.f, s2A = 0.f;
        float nB = 0.f, s1B = 0.f, s2B = 0.f;
#pragma unroll
        for (int t = 0; t < 16; t++) {
#pragma unroll
            for (int e = 0; e < 2; e++) {
                float a = acc[t][e];
                if (a > tmA) { nA += 1.f; s1A += a; s2A = fmaf(a, a, s2A); }
                float b = acc[t][e + 2];
                if (b > tmB) { nB += 1.f; s1B += b; s2B = fmaf(b, b, s2B); }
            }
        }
#pragma unroll
        for (int o = 1; o <= 2; o <<= 1) {
            nA += __shfl_xor_sync(0xffffffffu, nA, o);
            s1A += __shfl_xor_sync(0xffffffffu, s1A, o);
            s2A += __shfl_xor_sync(0xffffffffu, s2A, o);
            nB += __shfl_xor_sync(0xffffffffu, nB, o);
            s1B += __shfl_xor_sync(0xffffffffu, s1B, o);
            s2B += __shfl_xor_sync(0xffffffffu, s2B, o);
        }
        float* RP = RED + par * 384;
        if (qlead) {
            RP[r0 * 8 + wid] = nA;        RP[r1 * 8 + wid] = nB;
            RP[128 + r0 * 8 + wid] = s1A; RP[128 + r1 * 8 + wid] = s1B;
            RP[256 + r0 * 8 + wid] = s2A; RP[256 + r1 * 8 + wid] = s2B;
        }
        __syncthreads();
        {
            float n = sum8(RP, r0), s1 = sum8(RP + 128, r0), s2 = sum8(RP + 256, r0);
            float D = fmaxf(fmaf(s1, s1, -n * (s2 - 1.0f)), 0.f);
            tmA = (s1 - sqrtf(D)) / n;
            n = sum8(RP, r1); s1 = sum8(RP + 128, r1); s2 = sum8(RP + 256, r1);
            D = fmaxf(fmaf(s1, s1, -n * (s2 - 1.0f)), 0.f);
            tmB = (s1 - sqrtf(D)) / n;
        }
        par ^= 1;
    }

    // Phase E: final p + normalize
    float ivA, ivB;
    {
        float c0 = 0.f, c1 = 0.f, c2 = 0.f, c3 = 0.f;
#pragma unroll
        for (int t = 0; t < 16; t++) {
            float u;
            u = fmaxf(acc[t][0] - tmA, 0.f); acc[t][0] = u * u; c0 += acc[t][0];
            u = fmaxf(acc[t][1] - tmA, 0.f); acc[t][1] = u * u; c1 += acc[t][1];
            u = fmaxf(acc[t][2] - tmB, 0.f); acc[t][2] = u * u; c2 += acc[t][2];
            u = fmaxf(acc[t][3] - tmB, 0.f); acc[t][3] = u * u; c3 += acc[t][3];
        }
        float vA = c0 + c1, vB = c2 + c3;
        vA += __shfl_xor_sync(0xffffffffu, vA, 1);
        vA += __shfl_xor_sync(0xffffffffu, vA, 2);
        vB += __shfl_xor_sync(0xffffffffu, vB, 1);
        vB += __shfl_xor_sync(0xffffffffu, vB, 2);
        float* RP = RED + par * 384;
        if (qlead) { RP[r0 * 8 + wid] = vA; RP[r1 * 8 + wid] = vB; }
        __syncthreads();
        ivA = 1.0f / sum8(RP, r0);
        ivB = 1.0f / sum8(RP, r1);
    }

    // normalize in-register, write attn fp32 (streaming), pack p fragments
    uint32_t pH[16][2], pL[16][2];
    {
        size_t rb0 = ((size_t)bh * SEQ + R0 + r0) * SEQ + wid * 16 + (lane & 3) * 2;
        size_t rb1 = ((size_t)bh * SEQ + R0 + r1) * SEQ + wid * 16 + (lane & 3) * 2;
#pragma unroll
        for (int t = 0; t < 16; t++) {
            int off = (t >> 1) * 128 + (t & 1) * 8;
            float p0 = acc[t][0] * ivA, p1 = acc[t][1] * ivA;
            float p2 = acc[t][2] * ivB, p3 = acc[t][3] * ivB;
            __stcs((float2*)(attn + rb0 + off), {p0, p1});
            __stcs((float2*)(attn + rb1 + off), {p2, p3});
            __nv_bfloat16 h0, l0, h1, l1;
            split1(p0, h0, l0); split1(p1, h1, l1);
            pH[t][0] = pack2(h0, h1);
            pL[t][0] = pack2(l0, l1);
            split1(p2, h0, l0); split1(p3, h1, l1);
            pH[t][1] = pack2(h0, h1);
            pL[t][1] = pack2(l0, l1);
        }
    }

    // --- fused P@V (3-term), 3-stage ring: chunk v in stage (v+2)%3 ---
    float cacc[8][4];
#pragma unroll
    for (int n8 = 0; n8 < 8; n8++)
#pragma unroll
        for (int e = 0; e < 4; e++) cacc[n8][e] = 0.0f;

    int vplane = wid >> 2;
    uint32_t vku = (uint32_t)((wid & 3) * 2 + bsel);

#pragma unroll
    for (int v = 0; v < 8; v++) {
        if (v >= 7) { CP_WAIT0(); } else { CP_WAIT1(); }
        __syncthreads();
        if (v + 2 < 8) loadV(v + 2, (v + 1) % 3);
        uint32_t VHb = sb + EOFF_K + ((v + 2) % 3) * 32768;
        uint32_t VLb = VHb + 16384;
        uint32_t pa_h[4] = { pH[2 * v][0], pH[2 * v][1], pH[2 * v + 1][0], pH[2 * v + 1][1] };
        uint32_t pa_l[4] = { pL[2 * v][0], pL[2 * v][1], pL[2 * v + 1][0], pL[2 * v + 1][1] };
#pragma unroll
        for (int nt = 0; nt < 4; nt++) {
            int row = nt * 16 + brow_;
            uint32_t off = vplane * 8192 + row * 128 + ((vku ^ (row & 7)) * 16);
            uint32_t vh[4], vl[4];
            LDSM4(vh[0], vh[1], vh[2], vh[3], VHb + off);
            LDSM4(vl[0], vl[1], vl[2], vl[3], VLb + off);
            MMA16816(cacc[nt * 2 + 0], pa_h, vh[0], vh[1]);
            MMA16816(cacc[nt * 2 + 1], pa_h, vh[2], vh[3]);
            MMA16816(cacc[nt * 2 + 0], pa_h, vl[0], vl[1]);
            MMA16816(cacc[nt * 2 + 1], pa_h, vl[2], vl[3]);
            MMA16816(cacc[nt * 2 + 0], pa_l, vh[0], vh[1]);
            MMA16816(cacc[nt * 2 + 1], pa_l, vh[2], vh[3]);
        }
    }
    __syncthreads();   // protect PART region (overlaps V stages)

    // cross-warp reduction: 8 partials of [16][64] -> ctx split
    float* PART = (float*)(sm + EOFF_K);
#pragma unroll
    for (int n8 = 0; n8 < 8; n8++) {
        int dh = (n8 >> 1) * 16 + (n8 & 1) * 8 + (lane & 3) * 2;
        *(float2*)&PART[wid * 1024 + r0 * 64 + dh] = {cacc[n8][0], cacc[n8][1]};
        *(float2*)&PART[wid * 1024 + r1 * 64 + dh] = {cacc[n8][2], cacc[n8][3]};
    }
    __syncthreads();
    {
        int r = tid >> 4, d4 = (tid & 15) * 4;
        float4 s = {0.f, 0.f, 0.f, 0.f};
#pragma unroll
        for (int w = 0; w < 8; w++) {
            float4 t4 = *(float4*)&PART[w * 1024 + r * 64 + d4];
            s.x += t4.x; s.y += t4.y; s.z += t4.z; s.w += t4.w;
        }
        int bidx = bh >> 4, h = bh & 15;
        size_t o = (size_t)(bidx * SEQ + R0 + r) * CH + h * DH + d4;
        __nv_bfloat16 h0, l0, h1, l1, h2, l2, h3, l3;
        split1(s.x, h0, l0); split1(s.y, h1, l1);
        split1(s.z, h2, l2); split1(s.w, h3, l3);
        *(__nv_bfloat162*)(g_chi + o)     = {h0, h1};
        *(__nv_bfloat162*)(g_chi + o + 2) = {h2, h3};
        *(__nv_bfloat162*)(g_clo + o)     = {l0, l1};
        *(__nv_bfloat162*)(g_clo + o + 2) = {l2, l3};
    }
}

// ---------------------------------------------------------------------------
extern "C" void kernel_launch(void* const* d_in, const int* in_sizes, int n_in,
                              void* d_out, int out_size)
{
    const float* x  = (const float*)d_in[0];
    const float* Wq = (const float*)d_in[1];
    const float* bq = (const float*)d_in[2];
    const float* Wk = (const float*)d_in[3];
    const float* bk = (const float*)d_in[4];
    const float* Wv = (const float*)d_in[5];
    const float* bv = (const float*)d_in[6];
    const float* Wo = (const float*)d_in[7];
    const float* bo = (const float*)d_in[8];

    float* out_ptr  = (float*)d_out;
    float* attn_ptr = out_ptr + OUT_ELEMS;

    __nv_bfloat16 *p_xhi, *p_xlo;
    cudaGetSymbolAddress((void**)&p_xhi, g_xhi);
    cudaGetSymbolAddress((void**)&p_xlo, g_xlo);

    cudaFuncSetAttribute(gemm_qkv, cudaFuncAttributeMaxDynamicSharedMemorySize, GSMEM);
    cudaFuncSetAttribute(gemm_out, cudaFuncAttributeMaxDynamicSharedMemorySize, GSMEM);
    cudaFuncSetAttribute(attn_entmax_mma, cudaFuncAttributeMaxDynamicSharedMemorySize, ESMEM);

    split_convert<<<OUT_ELEMS / 4 / 256, 256>>>(x, p_xhi, p_xlo, OUT_ELEMS / 4);
    dim3 wt4(32, 32, 4), wb(32, 8);
    wtrans_convert4<<<wt4, wb>>>(Wq, Wk, Wv, Wo);

    dim3 gq(24, 32);
    gemm_qkv<<<gq, 256, GSMEM>>>(bq, bk, bv);

    dim3 ge(64, BH);
    attn_entmax_mma<<<ge, 256, ESMEM>>>(attn_ptr);

    dim3 gg(8, 32);
    gemm_out<<<gg, 256, GSMEM>>>(bo, out_ptr);
}